// round 8
// baseline (speedup 1.0000x reference)
#include <cuda_runtime.h>
#include <cuda_bf16.h>
#include <cstdint>

#define NN 50000
#define NE 800000
#define NR 8

// ---------------- scratch (device globals; no allocs allowed) ----------------
__device__ __align__(16) float g_xw[(size_t)NN * NR * 256];   // per-rel transforms
__device__ __align__(16) float g_sd[NN * 64];                 // attention dots
__device__ __align__(16) float g_alpha[NE * 4];               // per-edge exp
__device__ __align__(16) float g_asum[NN * 4];
__device__ __align__(16) float g_accum[(size_t)NN * 256];
__device__ __align__(16) float g_h[(size_t)NN * 256];
__device__ __align__(16) float g_ws[256 * 64];
__device__ __align__(16) __nv_bfloat16 g_xh[(size_t)NN * 256];  // A operand hi
__device__ __align__(16) __nv_bfloat16 g_xl[(size_t)NN * 256];  // A operand lo
__device__ __align__(16) __nv_bfloat16 g_wh[NR * 256 * 256];    // B operand hi
__device__ __align__(16) __nv_bfloat16 g_wl[NR * 256 * 256];    // B operand lo

__device__ __forceinline__ float4 ld4(const float* p) { return *reinterpret_cast<const float4*>(p); }
__device__ __forceinline__ void st4(float* p, float4 v) { *reinterpret_cast<float4*>(p) = v; }

__device__ __forceinline__ uint32_t smem_u32(const void* p) {
    uint32_t a;
    asm("{ .reg .u64 t; cvta.to.shared.u64 t, %1; cvt.u32.u64 %0, t; }" : "=r"(a) : "l"(p));
    return a;
}

// fp32 pair -> bf16 hi pair + bf16 lo (residual) pair, packed as u32
__device__ __forceinline__ void split2(float x, float y, unsigned& hi, unsigned& lo) {
    __nv_bfloat16 hx = __float2bfloat16(x), hy = __float2bfloat16(y);
    float rx = x - __bfloat162float(hx), ry = y - __bfloat162float(hy);
    __nv_bfloat162 h; h.x = hx; h.y = hy;
    __nv_bfloat162 l = __floats2bfloat162_rn(rx, ry);
    hi = *reinterpret_cast<unsigned*>(&h);
    lo = *reinterpret_cast<unsigned*>(&l);
}

__device__ __forceinline__ void ldsm_x4(uint32_t addr, uint32_t& r0, uint32_t& r1, uint32_t& r2, uint32_t& r3) {
    asm volatile("ldmatrix.sync.aligned.m8n8.x4.shared.b16 {%0,%1,%2,%3}, [%4];"
                 : "=r"(r0), "=r"(r1), "=r"(r2), "=r"(r3) : "r"(addr));
}
__device__ __forceinline__ void ldsm_x4t(uint32_t addr, uint32_t& r0, uint32_t& r1, uint32_t& r2, uint32_t& r3) {
    asm volatile("ldmatrix.sync.aligned.m8n8.x4.trans.shared.b16 {%0,%1,%2,%3}, [%4];"
                 : "=r"(r0), "=r"(r1), "=r"(r2), "=r"(r3) : "r"(addr));
}
__device__ __forceinline__ void mma_bf16(float* d, const uint32_t* a, uint32_t b0, uint32_t b1) {
    asm volatile("mma.sync.aligned.m16n8k16.row.col.f32.bf16.bf16.f32 "
                 "{%0,%1,%2,%3}, {%4,%5,%6,%7}, {%8,%9}, {%0,%1,%2,%3};"
                 : "+f"(d[0]), "+f"(d[1]), "+f"(d[2]), "+f"(d[3])
                 : "r"(a[0]), "r"(a[1]), "r"(a[2]), "r"(a[3]), "r"(b0), "r"(b1));
}
__device__ __forceinline__ void cpa16(uint32_t d, const void* s, int zfill) {
    asm volatile("cp.async.cg.shared.global [%0], [%1], 16, %2;" :: "r"(d), "l"(s), "r"(zfill));
}

// ---------------- elementwise fp32 -> bf16 hi/lo converters ----------------
__global__ void conv_x_kernel(const float* __restrict__ X, int total4) {
    int i = blockIdx.x * blockDim.x + threadIdx.x;
    if (i >= total4) return;
    float4 v = ld4(X + (size_t)i * 4);
    unsigned h0, l0, h1, l1;
    split2(v.x, v.y, h0, l0);
    split2(v.z, v.w, h1, l1);
    *reinterpret_cast<uint2*>(g_xh + (size_t)i * 4) = make_uint2(h0, h1);
    *reinterpret_cast<uint2*>(g_xl + (size_t)i * 4) = make_uint2(l0, l1);
}
__global__ void conv_w_kernel(const float* __restrict__ W, int total4) {
    int i = blockIdx.x * blockDim.x + threadIdx.x;
    if (i >= total4) return;
    float4 v = ld4(W + (size_t)i * 4);
    unsigned h0, l0, h1, l1;
    split2(v.x, v.y, h0, l0);
    split2(v.z, v.w, h1, l1);
    *reinterpret_cast<uint2*>(g_wh + (size_t)i * 4) = make_uint2(h0, h1);
    *reinterpret_cast<uint2*>(g_wl + (size_t)i * 4) = make_uint2(l0, l1);
}

// ======== HMMA split-bf16 GEMM, 2-stage cp.async pipeline ========
// g_xw[row, z*NCOLS + col] = X[row,:]·W[z][:,col]; A = g_xh/g_xl, B = g_wh/g_wl
template<int NCOLS, int KTOT>
__global__ void __launch_bounds__(256) mma_gemm(int ldY) {
    constexpr int BN = (NCOLS < 128) ? NCOLS : 128;
    constexpr int WN = BN / 2;
    constexpr int NF2 = WN / 16;
    constexpr int AST = 40;                 // 32 + 8 pad (bf16)
    constexpr int BST = BN + 8;
    constexpr int A_ELE = 128 * AST;        // per hi or lo buffer
    constexpr int B_ELE = 32 * BST;
    constexpr int STAGE = 2 * A_ELE + 2 * B_ELE;
    constexpr int NIT = KTOT / 32;

    extern __shared__ __nv_bfloat16 smem[];

    const int tid = threadIdx.x;
    const int wid = tid >> 5, lane = tid & 31;
    const int wm = wid & 3, wn = wid >> 2;
    const int rowBase = blockIdx.x * 128;
    const int nbase = blockIdx.y * BN;
    const int z = blockIdx.z;
    const __nv_bfloat16* Wh = g_wh + (size_t)z * KTOT * NCOLS;
    const __nv_bfloat16* Wl = g_wl + (size_t)z * KTOT * NCOLS;

    float acc[2][WN / 8][4];
    #pragma unroll
    for (int i = 0; i < 2; i++)
        #pragma unroll
        for (int j = 0; j < WN / 8; j++)
            #pragma unroll
            for (int q = 0; q < 4; q++) acc[i][j][q] = 0.f;

    // ---- stage loader ----
    auto load_stage = [&](int s, int k0) {
        __nv_bfloat16* Ah = smem + (size_t)s * STAGE;
        __nv_bfloat16* Al = Ah + A_ELE;
        __nv_bfloat16* Bh = Al + A_ELE;
        __nv_bfloat16* Bl = Bh + B_ELE;
        #pragma unroll
        for (int i = 0; i < 2; i++) {
            int li = tid + i * 256;
            int row = li >> 2, c8 = (li & 3) * 8;
            int gr = rowBase + row;
            int zf = (gr < NN) ? 16 : 0;
            size_t goff = (size_t)gr * KTOT + k0 + c8;
            cpa16(smem_u32(Ah + row * AST + c8), g_xh + goff, zf);
            cpa16(smem_u32(Al + row * AST + c8), g_xl + goff, zf);
        }
        #pragma unroll
        for (int i = 0; i < BN / 64; i++) {
            int li = tid + i * 256;
            int row = li / (BN / 8), c8 = (li % (BN / 8)) * 8;
            size_t goff = (size_t)(k0 + row) * NCOLS + nbase + c8;
            cpa16(smem_u32(Bh + row * BST + c8), Wh + goff, 16);
            cpa16(smem_u32(Bl + row * BST + c8), Wl + goff, 16);
        }
        asm volatile("cp.async.commit_group;");
    };

    load_stage(0, 0);

    for (int it = 0; it < NIT; it++) {
        if (it + 1 < NIT) {
            load_stage((it + 1) & 1, (it + 1) * 32);
            asm volatile("cp.async.wait_group 1;");
        } else {
            asm volatile("cp.async.wait_group 0;");
        }
        __syncthreads();

        const __nv_bfloat16* Ah = smem + (size_t)(it & 1) * STAGE;
        const __nv_bfloat16* Al = Ah + A_ELE;
        const __nv_bfloat16* Bh = Al + A_ELE;
        const __nv_bfloat16* Bl = Bh + B_ELE;

        #pragma unroll
        for (int ks = 0; ks < 2; ks++) {
            uint32_t ah[2][4], al[2][4];
            #pragma unroll
            for (int mf = 0; mf < 2; mf++) {
                int arow = wm * 32 + mf * 16 + (lane & 15);
                int acol = ks * 16 + ((lane >> 4) << 3);
                ldsm_x4(smem_u32(Ah + arow * AST + acol), ah[mf][0], ah[mf][1], ah[mf][2], ah[mf][3]);
                ldsm_x4(smem_u32(Al + arow * AST + acol), al[mf][0], al[mf][1], al[mf][2], al[mf][3]);
            }
            #pragma unroll
            for (int nf2 = 0; nf2 < NF2; nf2++) {
                int brow = ks * 16 + (lane & 15);
                int bcol = wn * WN + nf2 * 16 + ((lane >> 4) << 3);
                uint32_t bh[4], bl[4];
                ldsm_x4t(smem_u32(Bh + brow * BST + bcol), bh[0], bh[1], bh[2], bh[3]);
                ldsm_x4t(smem_u32(Bl + brow * BST + bcol), bl[0], bl[1], bl[2], bl[3]);
                #pragma unroll
                for (int half = 0; half < 2; half++) {
                    uint32_t bH0 = bh[half * 2], bH1 = bh[half * 2 + 1];
                    uint32_t bL0 = bl[half * 2], bL1 = bl[half * 2 + 1];
                    #pragma unroll
                    for (int mf = 0; mf < 2; mf++) {
                        float* d = acc[mf][nf2 * 2 + half];
                        mma_bf16(d, ah[mf], bH0, bH1);
                        mma_bf16(d, ah[mf], bL0, bL1);
                        mma_bf16(d, al[mf], bH0, bH1);
                    }
                }
            }
        }
        __syncthreads();
    }
    // epilogue
    const int colG = z * NCOLS + nbase + wn * WN + (lane & 3) * 2;
    #pragma unroll
    for (int mf = 0; mf < 2; mf++) {
        int r0 = rowBase + wm * 32 + mf * 16 + (lane >> 2);
        #pragma unroll
        for (int nf = 0; nf < WN / 8; nf++) {
            float* d = acc[mf][nf];
            int c = colG + nf * 8;
            if (r0 < NN)
                *reinterpret_cast<float2*>(g_xw + (size_t)r0 * ldY + c) = make_float2(d[0], d[1]);
            if (r0 + 8 < NN)
                *reinterpret_cast<float2*>(g_xw + (size_t)(r0 + 8) * ldY + c) = make_float2(d[2], d[3]);
        }
    }
}

// ---------------- ws[k][col] = sum_c W[r][k][h*C+c] * a_{src|dst}[h][c] ----------------
template<int H, int C>
__global__ void prep_ws_kernel(const float* __restrict__ W, const float* __restrict__ a_src,
                               const float* __restrict__ a_dst, int K) {
    int idx = blockIdx.x * blockDim.x + threadIdx.x;
    if (idx >= K * 64) return;
    int k = idx >> 6;
    int col = idx & 63;
    constexpr int RH = NR * H;
    float acc = 0.f;
    if (col < 2 * RH) {
        int isd = col >= RH;
        int rh = isd ? col - RH : col;
        int r = rh / H, h = rh % H;
        const float* a = isd ? a_dst : a_src;
        const float* wrow = W + ((size_t)r * K + k) * (H * C) + h * C;
        #pragma unroll 8
        for (int c = 0; c < C; c++) acc += wrow[c] * a[h * C + c];
    }
    g_ws[idx] = acc;
}

// ---------------- fp32 SGEMM (attention dots only): g_sd = X @ g_ws ----------------
template<int BN, int XH>
__global__ void __launch_bounds__(256) gemm_dots(const float* __restrict__ Xp, int K) {
    constexpr int BM = 128, BK = 16;
    constexpr int TN = BN / 16;
    const float* X = XH ? (const float*)g_h : Xp;
    const float* W = (const float*)g_ws;
    float* Y = (float*)g_sd;
    __shared__ float As[BK][BM];
    __shared__ float Bs[BK][BN];
    const int tid = threadIdx.x;
    const int tx = tid & 15, ty = tid >> 4;
    const int rowBase = blockIdx.x * BM;

    float acc[8][TN];
    #pragma unroll
    for (int i = 0; i < 8; i++)
        #pragma unroll
        for (int j = 0; j < TN; j++) acc[i][j] = 0.f;

    for (int k0 = 0; k0 < K; k0 += BK) {
        #pragma unroll
        for (int i = 0; i < 2; i++) {
            int idx = tid + i * 256;
            int ar = idx >> 2;
            int ac = (idx & 3) << 2;
            int gr = rowBase + ar;
            float4 v = make_float4(0.f, 0.f, 0.f, 0.f);
            if (gr < NN) v = ld4(X + (size_t)gr * K + k0 + ac);
            As[ac + 0][ar] = v.x; As[ac + 1][ar] = v.y;
            As[ac + 2][ar] = v.z; As[ac + 3][ar] = v.w;
        }
        if (tid < BK * BN / 4) {
            int br = tid / (BN / 4);
            int bc = (tid % (BN / 4)) << 2;
            st4(&Bs[br][bc], ld4(W + (size_t)(k0 + br) * 64 + bc));
        }
        __syncthreads();
        #pragma unroll
        for (int kk = 0; kk < BK; kk++) {
            float av[8], bv[TN];
            float4 a0 = *reinterpret_cast<const float4*>(&As[kk][ty * 4]);
            float4 a1 = *reinterpret_cast<const float4*>(&As[kk][64 + ty * 4]);
            av[0] = a0.x; av[1] = a0.y; av[2] = a0.z; av[3] = a0.w;
            av[4] = a1.x; av[5] = a1.y; av[6] = a1.z; av[7] = a1.w;
            float4 b0 = *reinterpret_cast<const float4*>(&Bs[kk][tx * 4]);
            bv[0] = b0.x; bv[1] = b0.y; bv[2] = b0.z; bv[3] = b0.w;
            #pragma unroll
            for (int i = 0; i < 8; i++)
                #pragma unroll
                for (int j = 0; j < TN; j++) acc[i][j] = fmaf(av[i], bv[j], acc[i][j]);
        }
        __syncthreads();
    }
    #pragma unroll
    for (int i = 0; i < 8; i++) {
        int lr = (i < 4) ? (ty * 4 + i) : (64 + ty * 4 + (i - 4));
        int gr = rowBase + lr;
        if (gr >= NN) continue;
        st4(Y + (size_t)gr * 64 + tx * 4, make_float4(acc[i][0], acc[i][1], acc[i][2], acc[i][3]));
    }
}

// ---------------- zero asum + accum in one pass ----------------
template<int H, int M>
__global__ void zero_soft_accum() {
    int i = blockIdx.x * blockDim.x + threadIdx.x;
    constexpr int NA = NN * H / 4;
    constexpr int NB = NN * M / 4;
    float4 zz = make_float4(0.f, 0.f, 0.f, 0.f);
    if (i < NA) st4((float*)g_asum + (size_t)i * 4, zz);
    else if (i < NA + NB) st4((float*)g_accum + (size_t)(i - NA) * 4, zz);
}

// ---------------- edge: logit -> leaky -> exp -> denom (shift-invariant softmax) ----------------
template<int H>
__global__ void edge_exp_kernel(const int* __restrict__ ei,
                                const int* __restrict__ et,
                                const float* __restrict__ arel) {
    int e = blockIdx.x * blockDim.x + threadIdx.x;
    if (e >= NE) return;
    int src = ei[e], dst = ei[NE + e], r = et[e];
    if constexpr (H == 4) {
        float4 s = ld4(g_sd + src * 64 + r * 4);
        float4 d = ld4(g_sd + dst * 64 + 32 + r * 4);
        float4 a = ld4(arel + r * 4);
        float4 v;
        v.x = s.x + d.x + a.x; v.y = s.y + d.y + a.y;
        v.z = s.z + d.z + a.z; v.w = s.w + d.w + a.w;
        v.x = v.x > 0.f ? v.x : 0.2f * v.x;
        v.y = v.y > 0.f ? v.y : 0.2f * v.y;
        v.z = v.z > 0.f ? v.z : 0.2f * v.z;
        v.w = v.w > 0.f ? v.w : 0.2f * v.w;
        float4 ex = make_float4(expf(v.x), expf(v.y), expf(v.z), expf(v.w));
        st4(g_alpha + (size_t)e * 4, ex);
        atomicAdd(reinterpret_cast<float4*>(g_asum + dst * 4), ex);
    } else {
        float v = g_sd[src * 64 + r] + g_sd[dst * 64 + 8 + r] + arel[r];
        v = v > 0.f ? v : 0.2f * v;
        float ex = expf(v);
        g_alpha[e] = ex;
        atomicAdd(&g_asum[dst], ex);
    }
}

// ---------------- weighted message aggregation (warp per edge) ----------------
template<int M, int H>
__global__ void agg_kernel(const int* __restrict__ ei, const int* __restrict__ et) {
    int gw = (blockIdx.x * blockDim.x + threadIdx.x) >> 5;
    int lane = threadIdx.x & 31;
    if (gw >= NE) return;
    int src = ei[gw], dst = ei[NE + gw], r = et[gw];
    const float* xp = g_xw + ((size_t)src * NR + r) * M;
    float* op = g_accum + (size_t)dst * M;
    if constexpr (H == 4) {
        float4 ex = ld4(g_alpha + (size_t)gw * 4);
        float4 den = ld4(g_asum + dst * 4);
        float w0 = ex.x / den.x, w1 = ex.y / den.y, w2 = ex.z / den.z, w3 = ex.w / den.w;
        float sA = (lane < 16) ? w0 : w1;
        float sB = (lane < 16) ? w2 : w3;
        float4 v0 = ld4(xp + lane * 4);
        float4 v1 = ld4(xp + 128 + lane * 4);
        v0.x *= sA; v0.y *= sA; v0.z *= sA; v0.w *= sA;
        v1.x *= sB; v1.y *= sB; v1.z *= sB; v1.w *= sB;
        atomicAdd(reinterpret_cast<float4*>(op + lane * 4), v0);
        atomicAdd(reinterpret_cast<float4*>(op + 128 + lane * 4), v1);
    } else {
        float w = g_alpha[gw] / g_asum[dst];
        if (lane < 16) {
            float4 v = ld4(xp + lane * 4);
            v.x *= w; v.y *= w; v.z *= w; v.w *= w;
            atomicAdd(reinterpret_cast<float4*>(op + lane * 4), v);
        }
    }
}

// ---------------- bias + layernorm + elu + bf16 hi/lo export (warp per node) ----------------
__global__ void ln_elu_kernel(const float* __restrict__ bias, const float* __restrict__ gam,
                              const float* __restrict__ bet) {
    int n = (blockIdx.x * blockDim.x + threadIdx.x) >> 5;
    int lane = threadIdx.x & 31;
    if (n >= NN) return;
    const float* ap = g_accum + (size_t)n * 256;
    int c0 = lane * 4, c1 = 128 + lane * 4;
    float4 x0 = ld4(ap + c0), x1 = ld4(ap + c1);
    float4 b0 = ld4(bias + c0), b1 = ld4(bias + c1);
    x0.x += b0.x; x0.y += b0.y; x0.z += b0.z; x0.w += b0.w;
    x1.x += b1.x; x1.y += b1.y; x1.z += b1.z; x1.w += b1.w;
    float sum = x0.x + x0.y + x0.z + x0.w + x1.x + x1.y + x1.z + x1.w;
    float sq = x0.x * x0.x + x0.y * x0.y + x0.z * x0.z + x0.w * x0.w
             + x1.x * x1.x + x1.y * x1.y + x1.z * x1.z + x1.w * x1.w;
    #pragma unroll
    for (int o = 16; o; o >>= 1) {
        sum += __shfl_xor_sync(0xffffffffu, sum, o);
        sq  += __shfl_xor_sync(0xffffffffu, sq, o);
    }
    float mean = sum * (1.f / 256.f);
    float var = sq * (1.f / 256.f) - mean * mean;
    float rstd = rsqrtf(var + 1e-5f);
    float4 g0 = ld4(gam + c0), g1 = ld4(gam + c1);
    float4 e0 = ld4(bet + c0), e1 = ld4(bet + c1);
    float4 y0, y1;
    y0.x = (x0.x - mean) * rstd * g0.x + e0.x;
    y0.y = (x0.y - mean) * rstd * g0.y + e0.y;
    y0.z = (x0.z - mean) * rstd * g0.z + e0.z;
    y0.w = (x0.w - mean) * rstd * g0.w + e0.w;
    y1.x = (x1.x - mean) * rstd * g1.x + e1.x;
    y1.y = (x1.y - mean) * rstd * g1.y + e1.y;
    y1.z = (x1.z - mean) * rstd * g1.z + e1.z;
    y1.w = (x1.w - mean) * rstd * g1.w + e1.w;
    y0.x = y0.x > 0.f ? y0.x : expm1f(y0.x);
    y0.y = y0.y > 0.f ? y0.y : expm1f(y0.y);
    y0.z = y0.z > 0.f ? y0.z : expm1f(y0.z);
    y0.w = y0.w > 0.f ? y0.w : expm1f(y0.w);
    y1.x = y1.x > 0.f ? y1.x : expm1f(y1.x);
    y1.y = y1.y > 0.f ? y1.y : expm1f(y1.y);
    y1.z = y1.z > 0.f ? y1.z : expm1f(y1.z);
    y1.w = y1.w > 0.f ? y1.w : expm1f(y1.w);
    float* hp = g_h + (size_t)n * 256;
    st4(hp + c0, y0);
    st4(hp + c1, y1);
    unsigned h0, l0, h1, l1;
    split2(y0.x, y0.y, h0, l0);
    split2(y0.z, y0.w, h1, l1);
    *reinterpret_cast<uint2*>(g_xh + (size_t)n * 256 + c0) = make_uint2(h0, h1);
    *reinterpret_cast<uint2*>(g_xl + (size_t)n * 256 + c0) = make_uint2(l0, l1);
    split2(y1.x, y1.y, h0, l0);
    split2(y1.z, y1.w, h1, l1);
    *reinterpret_cast<uint2*>(g_xh + (size_t)n * 256 + c1) = make_uint2(h0, h1);
    *reinterpret_cast<uint2*>(g_xl + (size_t)n * 256 + c1) = make_uint2(l0, l1);
}

__global__ void final_bias_kernel(const float* __restrict__ bi, float* __restrict__ out) {
    int i = blockIdx.x * blockDim.x + threadIdx.x;
    if (i < NN * 64) out[i] = g_accum[i] + bi[i & 63];
}

// ---------------- orchestration (kernel launches + non-enqueuing attribute sets) ----------------
extern "C" void kernel_launch(void* const* d_in, const int* in_sizes, int n_in,
                              void* d_out, int out_size) {
    (void)in_sizes; (void)n_in; (void)out_size;
    const float* x  = (const float*)d_in[0];
    const int* ei   = (const int*)d_in[1];
    const int* et   = (const int*)d_in[2];
    const float* W0 = (const float*)d_in[3];
    const float* as0 = (const float*)d_in[4];
    const float* ad0 = (const float*)d_in[5];
    const float* ar0 = (const float*)d_in[6];
    const float* bi0 = (const float*)d_in[7];
    const float* W1 = (const float*)d_in[8];
    const float* as1 = (const float*)d_in[9];
    const float* ad1 = (const float*)d_in[10];
    const float* ar1 = (const float*)d_in[11];
    const float* bi1 = (const float*)d_in[12];
    const float* W2 = (const float*)d_in[13];
    const float* as2 = (const float*)d_in[14];
    const float* ad2 = (const float*)d_in[15];
    const float* ar2 = (const float*)d_in[16];
    const float* bi2 = (const float*)d_in[17];
    const float* g0 = (const float*)d_in[18];
    const float* be0 = (const float*)d_in[19];
    const float* g1 = (const float*)d_in[20];
    const float* be1 = (const float*)d_in[21];
    float* out = (float*)d_out;

    const int TB = 256;
    const int NT = (NN + 127) / 128;
    dim3 gTC2(NT, 2, 8);
    dim3 gTC1(NT, 1, 8);
    int ge = (NE + TB - 1) / TB;
    int gw = (NE * 32 + TB - 1) / TB;
    int gn = (NN * 32 + TB - 1) / TB;
    const int Z44 = (NN * 4 / 4 + NN * 256 / 4 + TB - 1) / TB;
    const int Z14 = (NN * 1 / 4 + NN * 64 / 4 + TB - 1) / TB;

    // dynamic smem per template: 2 stages of (A hi/lo + B hi/lo)
    const int SM128 = 2 * (2 * 128 * 40 + 2 * 32 * 136) * 2;   // 75776 B
    const int SM64  = 2 * (2 * 128 * 40 + 2 * 32 * 72) * 2;    // 59392 B
    cudaFuncSetAttribute((const void*)mma_gemm<256, 128>, cudaFuncAttributeMaxDynamicSharedMemorySize, SM128);
    cudaFuncSetAttribute((const void*)mma_gemm<256, 256>, cudaFuncAttributeMaxDynamicSharedMemorySize, SM128);
    cudaFuncSetAttribute((const void*)mma_gemm<64, 256>,  cudaFuncAttributeMaxDynamicSharedMemorySize, SM64);

    // ======== layer 0: in=128 -> [8 rel] x 256, H=4 ========
    conv_w_kernel<<<(NR * 128 * 256 / 4 + TB - 1) / TB, TB>>>(W0, NR * 128 * 256 / 4);
    conv_x_kernel<<<(NN * 128 / 4 + TB - 1) / TB, TB>>>(x, NN * 128 / 4);
    prep_ws_kernel<4, 64><<<(128 * 64 + TB - 1) / TB, TB>>>(W0, as0, ad0, 128);
    gemm_dots<64, 0><<<NT, TB>>>(x, 128);
    mma_gemm<256, 128><<<gTC2, TB, SM128>>>(2048);
    zero_soft_accum<4, 256><<<Z44, TB>>>();
    edge_exp_kernel<4><<<ge, TB>>>(ei, et, ar0);
    agg_kernel<256, 4><<<gw, TB>>>(ei, et);
    ln_elu_kernel<<<gn, TB>>>(bi0, g0, be0);

    // ======== layer 1: in=256 -> [8 rel] x 256, H=4 ========
    conv_w_kernel<<<(NR * 256 * 256 / 4 + TB - 1) / TB, TB>>>(W1, NR * 256 * 256 / 4);
    prep_ws_kernel<4, 64><<<(256 * 64 + TB - 1) / TB, TB>>>(W1, as1, ad1, 256);
    gemm_dots<64, 1><<<NT, TB>>>(nullptr, 256);
    mma_gemm<256, 256><<<gTC2, TB, SM128>>>(2048);
    zero_soft_accum<4, 256><<<Z44, TB>>>();
    edge_exp_kernel<4><<<ge, TB>>>(ei, et, ar1);
    agg_kernel<256, 4><<<gw, TB>>>(ei, et);
    ln_elu_kernel<<<gn, TB>>>(bi1, g1, be1);

    // ======== layer 2: in=256 -> [8 rel] x 64, H=1, no concat ========
    conv_w_kernel<<<(NR * 256 * 64 / 4 + TB - 1) / TB, TB>>>(W2, NR * 256 * 64 / 4);
    prep_ws_kernel<1, 64><<<(256 * 64 + TB - 1) / TB, TB>>>(W2, as2, ad2, 256);
    gemm_dots<64, 1><<<NT, TB>>>(nullptr, 256);
    mma_gemm<64, 256><<<gTC1, TB, SM64>>>(512);
    zero_soft_accum<1, 64><<<Z14, TB>>>();
    edge_exp_kernel<1><<<ge, TB>>>(ei, et, ar2);
    agg_kernel<64, 1><<<gw, TB>>>(ei, et);
    final_bias_kernel<<<(NN * 64 + TB - 1) / TB, TB>>>(bi2, out);
}

// round 9
// speedup vs baseline: 1.3610x; 1.3610x over previous
#include <cuda_runtime.h>
#include <cuda_bf16.h>
#include <cstdint>

#define NN 50000
#define NE 800000
#define NR 8

// ---------------- scratch (device globals; no allocs allowed) ----------------
__device__ __align__(16) float g_xw[(size_t)NN * NR * 256];   // per-rel transforms
__device__ __align__(16) float g_sd[NN * 64];                 // attention dots
__device__ __align__(16) float g_alpha[NE * 4];               // per-edge exp
__device__ __align__(16) float g_asum[NN * 4];
__device__ __align__(16) float g_accum[(size_t)NN * 256];
__device__ __align__(16) float g_h[(size_t)NN * 256];
__device__ __align__(16) float g_ws[256 * 64];
__device__ __align__(16) __nv_bfloat16 g_xh[(size_t)NN * 256];  // A operand hi
__device__ __align__(16) __nv_bfloat16 g_xl[(size_t)NN * 256];  // A operand lo
__device__ __align__(16) __nv_bfloat16 g_wh[NR * 256 * 256];    // B operand hi
__device__ __align__(16) __nv_bfloat16 g_wl[NR * 256 * 256];    // B operand lo

__device__ __forceinline__ float4 ld4(const float* p) { return *reinterpret_cast<const float4*>(p); }
__device__ __forceinline__ void st4(float* p, float4 v) { *reinterpret_cast<float4*>(p) = v; }

__device__ __forceinline__ uint32_t smem_u32(const void* p) {
    uint32_t a;
    asm("{ .reg .u64 t; cvta.to.shared.u64 t, %1; cvt.u32.u64 %0, t; }" : "=r"(a) : "l"(p));
    return a;
}

// fp32 pair -> bf16 hi pair + bf16 lo (residual) pair, packed as u32
__device__ __forceinline__ void split2(float x, float y, unsigned& hi, unsigned& lo) {
    __nv_bfloat16 hx = __float2bfloat16(x), hy = __float2bfloat16(y);
    float rx = x - __bfloat162float(hx), ry = y - __bfloat162float(hy);
    __nv_bfloat162 h; h.x = hx; h.y = hy;
    __nv_bfloat162 l = __floats2bfloat162_rn(rx, ry);
    hi = *reinterpret_cast<unsigned*>(&h);
    lo = *reinterpret_cast<unsigned*>(&l);
}

__device__ __forceinline__ void ldsm_x4(uint32_t addr, uint32_t& r0, uint32_t& r1, uint32_t& r2, uint32_t& r3) {
    asm volatile("ldmatrix.sync.aligned.m8n8.x4.shared.b16 {%0,%1,%2,%3}, [%4];"
                 : "=r"(r0), "=r"(r1), "=r"(r2), "=r"(r3) : "r"(addr));
}
__device__ __forceinline__ void ldsm_x4t(uint32_t addr, uint32_t& r0, uint32_t& r1, uint32_t& r2, uint32_t& r3) {
    asm volatile("ldmatrix.sync.aligned.m8n8.x4.trans.shared.b16 {%0,%1,%2,%3}, [%4];"
                 : "=r"(r0), "=r"(r1), "=r"(r2), "=r"(r3) : "r"(addr));
}
__device__ __forceinline__ void mma_bf16(float* d, const uint32_t* a, uint32_t b0, uint32_t b1) {
    asm volatile("mma.sync.aligned.m16n8k16.row.col.f32.bf16.bf16.f32 "
                 "{%0,%1,%2,%3}, {%4,%5,%6,%7}, {%8,%9}, {%0,%1,%2,%3};"
                 : "+f"(d[0]), "+f"(d[1]), "+f"(d[2]), "+f"(d[3])
                 : "r"(a[0]), "r"(a[1]), "r"(a[2]), "r"(a[3]), "r"(b0), "r"(b1));
}
__device__ __forceinline__ void cpa16(uint32_t d, const void* s, int zfill) {
    asm volatile("cp.async.cg.shared.global [%0], [%1], 16, %2;" :: "r"(d), "l"(s), "r"(zfill));
}

// ---------------- elementwise fp32 -> bf16 hi/lo converters ----------------
__global__ void conv_x_kernel(const float* __restrict__ X, int total4) {
    int i = blockIdx.x * blockDim.x + threadIdx.x;
    if (i >= total4) return;
    float4 v = ld4(X + (size_t)i * 4);
    unsigned h0, l0, h1, l1;
    split2(v.x, v.y, h0, l0);
    split2(v.z, v.w, h1, l1);
    *reinterpret_cast<uint2*>(g_xh + (size_t)i * 4) = make_uint2(h0, h1);
    *reinterpret_cast<uint2*>(g_xl + (size_t)i * 4) = make_uint2(l0, l1);
}
__global__ void conv_w_kernel(const float* __restrict__ W, int total4) {
    int i = blockIdx.x * blockDim.x + threadIdx.x;
    if (i >= total4) return;
    float4 v = ld4(W + (size_t)i * 4);
    unsigned h0, l0, h1, l1;
    split2(v.x, v.y, h0, l0);
    split2(v.z, v.w, h1, l1);
    *reinterpret_cast<uint2*>(g_wh + (size_t)i * 4) = make_uint2(h0, h1);
    *reinterpret_cast<uint2*>(g_wl + (size_t)i * 4) = make_uint2(l0, l1);
}

// ======== HMMA split-bf16 GEMM, 2-stage cp.async pipeline, BK=16, static SMEM ========
// g_xw[row, z*NCOLS + col] = X[row,:]·W[z][:,col]; A = g_xh/g_xl, B = g_wh/g_wl
template<int NCOLS, int KTOT>
__global__ void __launch_bounds__(256) mma_gemm(int ldY) {
    constexpr int BN = (NCOLS < 128) ? NCOLS : 128;
    constexpr int WN = BN / 2;
    constexpr int NF2 = WN / 16;
    constexpr int BK = 16;
    constexpr int AST = BK + 8;             // 24 bf16 (48B row stride, 16B aligned, conflict-free)
    constexpr int BST = BN + 8;
    constexpr int NIT = KTOT / BK;

    __shared__ __align__(16) __nv_bfloat16 Ah_s[2][128][AST];
    __shared__ __align__(16) __nv_bfloat16 Al_s[2][128][AST];
    __shared__ __align__(16) __nv_bfloat16 Bh_s[2][BK][BST];
    __shared__ __align__(16) __nv_bfloat16 Bl_s[2][BK][BST];

    const int tid = threadIdx.x;
    const int wid = tid >> 5, lane = tid & 31;
    const int wm = wid & 3, wn = wid >> 2;
    const int rowBase = blockIdx.x * 128;
    const int nbase = blockIdx.y * BN;
    const int z = blockIdx.z;
    const __nv_bfloat16* Wh = g_wh + (size_t)z * KTOT * NCOLS;
    const __nv_bfloat16* Wl = g_wl + (size_t)z * KTOT * NCOLS;

    float acc[2][WN / 8][4];
    #pragma unroll
    for (int i = 0; i < 2; i++)
        #pragma unroll
        for (int j = 0; j < WN / 8; j++)
            #pragma unroll
            for (int q = 0; q < 4; q++) acc[i][j][q] = 0.f;

    // ---- stage loader: A 128x16 (256 chunks of 8), B 16xBN ----
    auto load_stage = [&](int s, int k0) {
        {
            int row = tid >> 1, c8 = (tid & 1) * 8;
            int gr = rowBase + row;
            int zf = (gr < NN) ? 16 : 0;
            size_t goff = (size_t)gr * KTOT + k0 + c8;
            cpa16(smem_u32(&Ah_s[s][row][c8]), g_xh + goff, zf);
            cpa16(smem_u32(&Al_s[s][row][c8]), g_xl + goff, zf);
        }
        constexpr int BCH = BK * BN / 8;     // 256 (BN=128) or 128 (BN=64)
        if (BCH >= 256 || tid < BCH) {
            int row = tid / (BN / 8), c8 = (tid % (BN / 8)) * 8;
            size_t goff = (size_t)(k0 + row) * NCOLS + nbase + c8;
            cpa16(smem_u32(&Bh_s[s][row][c8]), Wh + goff, 16);
            cpa16(smem_u32(&Bl_s[s][row][c8]), Wl + goff, 16);
        }
        asm volatile("cp.async.commit_group;");
    };

    load_stage(0, 0);

    for (int it = 0; it < NIT; it++) {
        if (it + 1 < NIT) {
            load_stage((it + 1) & 1, (it + 1) * BK);
            asm volatile("cp.async.wait_group 1;");
        } else {
            asm volatile("cp.async.wait_group 0;");
        }
        __syncthreads();

        const int s = it & 1;
        uint32_t ah[2][4], al[2][4];
        #pragma unroll
        for (int mf = 0; mf < 2; mf++) {
            int arow = wm * 32 + mf * 16 + (lane & 15);
            int acol = (lane >> 4) << 3;
            ldsm_x4(smem_u32(&Ah_s[s][arow][acol]), ah[mf][0], ah[mf][1], ah[mf][2], ah[mf][3]);
            ldsm_x4(smem_u32(&Al_s[s][arow][acol]), al[mf][0], al[mf][1], al[mf][2], al[mf][3]);
        }
        #pragma unroll
        for (int nf2 = 0; nf2 < NF2; nf2++) {
            int brow = lane & 15;
            int bcol = wn * WN + nf2 * 16 + ((lane >> 4) << 3);
            uint32_t bh[4], bl[4];
            ldsm_x4t(smem_u32(&Bh_s[s][brow][bcol]), bh[0], bh[1], bh[2], bh[3]);
            ldsm_x4t(smem_u32(&Bl_s[s][brow][bcol]), bl[0], bl[1], bl[2], bl[3]);
            #pragma unroll
            for (int half = 0; half < 2; half++) {
                uint32_t bH0 = bh[half * 2], bH1 = bh[half * 2 + 1];
                uint32_t bL0 = bl[half * 2], bL1 = bl[half * 2 + 1];
                #pragma unroll
                for (int mf = 0; mf < 2; mf++) {
                    float* d = acc[mf][nf2 * 2 + half];
                    mma_bf16(d, ah[mf], bH0, bH1);
                    mma_bf16(d, ah[mf], bL0, bL1);
                    mma_bf16(d, al[mf], bH0, bH1);
                }
            }
        }
        __syncthreads();
    }
    // epilogue
    const int colG = z * NCOLS + nbase + wn * WN + (lane & 3) * 2;
    #pragma unroll
    for (int mf = 0; mf < 2; mf++) {
        int r0 = rowBase + wm * 32 + mf * 16 + (lane >> 2);
        #pragma unroll
        for (int nf = 0; nf < WN / 8; nf++) {
            float* d = acc[mf][nf];
            int c = colG + nf * 8;
            if (r0 < NN)
                *reinterpret_cast<float2*>(g_xw + (size_t)r0 * ldY + c) = make_float2(d[0], d[1]);
            if (r0 + 8 < NN)
                *reinterpret_cast<float2*>(g_xw + (size_t)(r0 + 8) * ldY + c) = make_float2(d[2], d[3]);
        }
    }
}

// ---------------- ws[k][col] = sum_c W[r][k][h*C+c] * a_{src|dst}[h][c] ----------------
template<int H, int C>
__global__ void prep_ws_kernel(const float* __restrict__ W, const float* __restrict__ a_src,
                               const float* __restrict__ a_dst, int K) {
    int idx = blockIdx.x * blockDim.x + threadIdx.x;
    if (idx >= K * 64) return;
    int k = idx >> 6;
    int col = idx & 63;
    constexpr int RH = NR * H;
    float acc = 0.f;
    if (col < 2 * RH) {
        int isd = col >= RH;
        int rh = isd ? col - RH : col;
        int r = rh / H, h = rh % H;
        const float* a = isd ? a_dst : a_src;
        const float* wrow = W + ((size_t)r * K + k) * (H * C) + h * C;
        #pragma unroll 8
        for (int c = 0; c < C; c++) acc += wrow[c] * a[h * C + c];
    }
    g_ws[idx] = acc;
}

// ---------------- fp32 SGEMM (attention dots only): g_sd = X @ g_ws ----------------
template<int BN, int XH>
__global__ void __launch_bounds__(256) gemm_dots(const float* __restrict__ Xp, int K) {
    constexpr int BM = 128, BK = 16;
    constexpr int TN = BN / 16;
    const float* X = XH ? (const float*)g_h : Xp;
    const float* W = (const float*)g_ws;
    float* Y = (float*)g_sd;
    __shared__ float As[BK][BM];
    __shared__ float Bs[BK][BN];
    const int tid = threadIdx.x;
    const int tx = tid & 15, ty = tid >> 4;
    const int rowBase = blockIdx.x * BM;

    float acc[8][TN];
    #pragma unroll
    for (int i = 0; i < 8; i++)
        #pragma unroll
        for (int j = 0; j < TN; j++) acc[i][j] = 0.f;

    for (int k0 = 0; k0 < K; k0 += BK) {
        #pragma unroll
        for (int i = 0; i < 2; i++) {
            int idx = tid + i * 256;
            int ar = idx >> 2;
            int ac = (idx & 3) << 2;
            int gr = rowBase + ar;
            float4 v = make_float4(0.f, 0.f, 0.f, 0.f);
            if (gr < NN) v = ld4(X + (size_t)gr * K + k0 + ac);
            As[ac + 0][ar] = v.x; As[ac + 1][ar] = v.y;
            As[ac + 2][ar] = v.z; As[ac + 3][ar] = v.w;
        }
        if (tid < BK * BN / 4) {
            int br = tid / (BN / 4);
            int bc = (tid % (BN / 4)) << 2;
            st4(&Bs[br][bc], ld4(W + (size_t)(k0 + br) * 64 + bc));
        }
        __syncthreads();
        #pragma unroll
        for (int kk = 0; kk < BK; kk++) {
            float av[8], bv[TN];
            float4 a0 = *reinterpret_cast<const float4*>(&As[kk][ty * 4]);
            float4 a1 = *reinterpret_cast<const float4*>(&As[kk][64 + ty * 4]);
            av[0] = a0.x; av[1] = a0.y; av[2] = a0.z; av[3] = a0.w;
            av[4] = a1.x; av[5] = a1.y; av[6] = a1.z; av[7] = a1.w;
            float4 b0 = *reinterpret_cast<const float4*>(&Bs[kk][tx * 4]);
            bv[0] = b0.x; bv[1] = b0.y; bv[2] = b0.z; bv[3] = b0.w;
            #pragma unroll
            for (int i = 0; i < 8; i++)
                #pragma unroll
                for (int j = 0; j < TN; j++) acc[i][j] = fmaf(av[i], bv[j], acc[i][j]);
        }
        __syncthreads();
    }
    #pragma unroll
    for (int i = 0; i < 8; i++) {
        int lr = (i < 4) ? (ty * 4 + i) : (64 + ty * 4 + (i - 4));
        int gr = rowBase + lr;
        if (gr >= NN) continue;
        st4(Y + (size_t)gr * 64 + tx * 4, make_float4(acc[i][0], acc[i][1], acc[i][2], acc[i][3]));
    }
}

// ---------------- zero asum + accum in one pass ----------------
template<int H, int M>
__global__ void zero_soft_accum() {
    int i = blockIdx.x * blockDim.x + threadIdx.x;
    constexpr int NA = NN * H / 4;
    constexpr int NB = NN * M / 4;
    float4 zz = make_float4(0.f, 0.f, 0.f, 0.f);
    if (i < NA) st4((float*)g_asum + (size_t)i * 4, zz);
    else if (i < NA + NB) st4((float*)g_accum + (size_t)(i - NA) * 4, zz);
}

// ---------------- edge: logit -> leaky -> exp -> denom (shift-invariant softmax) ----------------
template<int H>
__global__ void edge_exp_kernel(const int* __restrict__ ei,
                                const int* __restrict__ et,
                                const float* __restrict__ arel) {
    int e = blockIdx.x * blockDim.x + threadIdx.x;
    if (e >= NE) return;
    int src = ei[e], dst = ei[NE + e], r = et[e];
    if constexpr (H == 4) {
        float4 s = ld4(g_sd + src * 64 + r * 4);
        float4 d = ld4(g_sd + dst * 64 + 32 + r * 4);
        float4 a = ld4(arel + r * 4);
        float4 v;
        v.x = s.x + d.x + a.x; v.y = s.y + d.y + a.y;
        v.z = s.z + d.z + a.z; v.w = s.w + d.w + a.w;
        v.x = v.x > 0.f ? v.x : 0.2f * v.x;
        v.y = v.y > 0.f ? v.y : 0.2f * v.y;
        v.z = v.z > 0.f ? v.z : 0.2f * v.z;
        v.w = v.w > 0.f ? v.w : 0.2f * v.w;
        float4 ex = make_float4(expf(v.x), expf(v.y), expf(v.z), expf(v.w));
        st4(g_alpha + (size_t)e * 4, ex);
        atomicAdd(reinterpret_cast<float4*>(g_asum + dst * 4), ex);
    } else {
        float v = g_sd[src * 64 + r] + g_sd[dst * 64 + 8 + r] + arel[r];
        v = v > 0.f ? v : 0.2f * v;
        float ex = expf(v);
        g_alpha[e] = ex;
        atomicAdd(&g_asum[dst], ex);
    }
}

// ---------------- weighted message aggregation (warp per edge) ----------------
template<int M, int H>
__global__ void agg_kernel(const int* __restrict__ ei, const int* __restrict__ et) {
    int gw = (blockIdx.x * blockDim.x + threadIdx.x) >> 5;
    int lane = threadIdx.x & 31;
    if (gw >= NE) return;
    int src = ei[gw], dst = ei[NE + gw], r = et[gw];
    const float* xp = g_xw + ((size_t)src * NR + r) * M;
    float* op = g_accum + (size_t)dst * M;
    if constexpr (H == 4) {
        float4 ex = ld4(g_alpha + (size_t)gw * 4);
        float4 den = ld4(g_asum + dst * 4);
        float w0 = ex.x / den.x, w1 = ex.y / den.y, w2 = ex.z / den.z, w3 = ex.w / den.w;
        float sA = (lane < 16) ? w0 : w1;
        float sB = (lane < 16) ? w2 : w3;
        float4 v0 = ld4(xp + lane * 4);
        float4 v1 = ld4(xp + 128 + lane * 4);
        v0.x *= sA; v0.y *= sA; v0.z *= sA; v0.w *= sA;
        v1.x *= sB; v1.y *= sB; v1.z *= sB; v1.w *= sB;
        atomicAdd(reinterpret_cast<float4*>(op + lane * 4), v0);
        atomicAdd(reinterpret_cast<float4*>(op + 128 + lane * 4), v1);
    } else {
        float w = g_alpha[gw] / g_asum[dst];
        if (lane < 16) {
            float4 v = ld4(xp + lane * 4);
            v.x *= w; v.y *= w; v.z *= w; v.w *= w;
            atomicAdd(reinterpret_cast<float4*>(op + lane * 4), v);
        }
    }
}

// ---------------- bias + layernorm + elu + bf16 hi/lo export (warp per node) ----------------
__global__ void ln_elu_kernel(const float* __restrict__ bias, const float* __restrict__ gam,
                              const float* __restrict__ bet) {
    int n = (blockIdx.x * blockDim.x + threadIdx.x) >> 5;
    int lane = threadIdx.x & 31;
    if (n >= NN) return;
    const float* ap = g_accum + (size_t)n * 256;
    int c0 = lane * 4, c1 = 128 + lane * 4;
    float4 x0 = ld4(ap + c0), x1 = ld4(ap + c1);
    float4 b0 = ld4(bias + c0), b1 = ld4(bias + c1);
    x0.x += b0.x; x0.y += b0.y; x0.z += b0.z; x0.w += b0.w;
    x1.x += b1.x; x1.y += b1.y; x1.z += b1.z; x1.w += b1.w;
    float sum = x0.x + x0.y + x0.z + x0.w + x1.x + x1.y + x1.z + x1.w;
    float sq = x0.x * x0.x + x0.y * x0.y + x0.z * x0.z + x0.w * x0.w
             + x1.x * x1.x + x1.y * x1.y + x1.z * x1.z + x1.w * x1.w;
    #pragma unroll
    for (int o = 16; o; o >>= 1) {
        sum += __shfl_xor_sync(0xffffffffu, sum, o);
        sq  += __shfl_xor_sync(0xffffffffu, sq, o);
    }
    float mean = sum * (1.f / 256.f);
    float var = sq * (1.f / 256.f) - mean * mean;
    float rstd = rsqrtf(var + 1e-5f);
    float4 g0 = ld4(gam + c0), g1 = ld4(gam + c1);
    float4 e0 = ld4(bet + c0), e1 = ld4(bet + c1);
    float4 y0, y1;
    y0.x = (x0.x - mean) * rstd * g0.x + e0.x;
    y0.y = (x0.y - mean) * rstd * g0.y + e0.y;
    y0.z = (x0.z - mean) * rstd * g0.z + e0.z;
    y0.w = (x0.w - mean) * rstd * g0.w + e0.w;
    y1.x = (x1.x - mean) * rstd * g1.x + e1.x;
    y1.y = (x1.y - mean) * rstd * g1.y + e1.y;
    y1.z = (x1.z - mean) * rstd * g1.z + e1.z;
    y1.w = (x1.w - mean) * rstd * g1.w + e1.w;
    y0.x = y0.x > 0.f ? y0.x : expm1f(y0.x);
    y0.y = y0.y > 0.f ? y0.y : expm1f(y0.y);
    y0.z = y0.z > 0.f ? y0.z : expm1f(y0.z);
    y0.w = y0.w > 0.f ? y0.w : expm1f(y0.w);
    y1.x = y1.x > 0.f ? y1.x : expm1f(y1.x);
    y1.y = y1.y > 0.f ? y1.y : expm1f(y1.y);
    y1.z = y1.z > 0.f ? y1.z : expm1f(y1.z);
    y1.w = y1.w > 0.f ? y1.w : expm1f(y1.w);
    float* hp = g_h + (size_t)n * 256;
    st4(hp + c0, y0);
    st4(hp + c1, y1);
    unsigned h0, l0, h1, l1;
    split2(y0.x, y0.y, h0, l0);
    split2(y0.z, y0.w, h1, l1);
    *reinterpret_cast<uint2*>(g_xh + (size_t)n * 256 + c0) = make_uint2(h0, h1);
    *reinterpret_cast<uint2*>(g_xl + (size_t)n * 256 + c0) = make_uint2(l0, l1);
    split2(y1.x, y1.y, h0, l0);
    split2(y1.z, y1.w, h1, l1);
    *reinterpret_cast<uint2*>(g_xh + (size_t)n * 256 + c1) = make_uint2(h0, h1);
    *reinterpret_cast<uint2*>(g_xl + (size_t)n * 256 + c1) = make_uint2(l0, l1);
}

__global__ void final_bias_kernel(const float* __restrict__ bi, float* __restrict__ out) {
    int i = blockIdx.x * blockDim.x + threadIdx.x;
    if (i < NN * 64) out[i] = g_accum[i] + bi[i & 63];
}

// ---------------- orchestration (pure kernel launches) ----------------
extern "C" void kernel_launch(void* const* d_in, const int* in_sizes, int n_in,
                              void* d_out, int out_size) {
    (void)in_sizes; (void)n_in; (void)out_size;
    const float* x  = (const float*)d_in[0];
    const int* ei   = (const int*)d_in[1];
    const int* et   = (const int*)d_in[2];
    const float* W0 = (const float*)d_in[3];
    const float* as0 = (const float*)d_in[4];
    const float* ad0 = (const float*)d_in[5];
    const float* ar0 = (const float*)d_in[6];
    const float* bi0 = (const float*)d_in[7];
    const float* W1 = (const float*)d_in[8];
    const float* as1 = (const float*)d_in[9];
    const float* ad1 = (const float*)d_in[10];
    const float* ar1 = (const float*)d_in[11];
    const float* bi1 = (const float*)d_in[12];
    const float* W2 = (const float*)d_in[13];
    const float* as2 = (const float*)d_in[14];
    const float* ad2 = (const float*)d_in[15];
    const float* ar2 = (const float*)d_in[16];
    const float* bi2 = (const float*)d_in[17];
    const float* g0 = (const float*)d_in[18];
    const float* be0 = (const float*)d_in[19];
    const float* g1 = (const float*)d_in[20];
    const float* be1 = (const float*)d_in[21];
    float* out = (float*)d_out;

    const int TB = 256;
    const int NT = (NN + 127) / 128;
    dim3 gTC2(NT, 2, 8);
    dim3 gTC1(NT, 1, 8);
    int ge = (NE + TB - 1) / TB;
    int gw = (NE * 32 + TB - 1) / TB;
    int gn = (NN * 32 + TB - 1) / TB;
    const int Z44 = (NN * 4 / 4 + NN * 256 / 4 + TB - 1) / TB;
    const int Z14 = (NN * 1 / 4 + NN * 64 / 4 + TB - 1) / TB;

    // ======== layer 0: in=128 -> [8 rel] x 256, H=4 ========
    conv_w_kernel<<<(NR * 128 * 256 / 4 + TB - 1) / TB, TB>>>(W0, NR * 128 * 256 / 4);
    conv_x_kernel<<<(NN * 128 / 4 + TB - 1) / TB, TB>>>(x, NN * 128 / 4);
    prep_ws_kernel<4, 64><<<(128 * 64 + TB - 1) / TB, TB>>>(W0, as0, ad0, 128);
    gemm_dots<64, 0><<<NT, TB>>>(x, 128);
    mma_gemm<256, 128><<<gTC2, TB>>>(2048);
    zero_soft_accum<4, 256><<<Z44, TB>>>();
    edge_exp_kernel<4><<<ge, TB>>>(ei, et, ar0);
    agg_kernel<256, 4><<<gw, TB>>>(ei, et);
    ln_elu_kernel<<<gn, TB>>>(bi0, g0, be0);

    // ======== layer 1: in=256 -> [8 rel] x 256, H=4 ========
    conv_w_kernel<<<(NR * 256 * 256 / 4 + TB - 1) / TB, TB>>>(W1, NR * 256 * 256 / 4);
    prep_ws_kernel<4, 64><<<(256 * 64 + TB - 1) / TB, TB>>>(W1, as1, ad1, 256);
    gemm_dots<64, 1><<<NT, TB>>>(nullptr, 256);
    mma_gemm<256, 256><<<gTC2, TB>>>(2048);
    zero_soft_accum<4, 256><<<Z44, TB>>>();
    edge_exp_kernel<4><<<ge, TB>>>(ei, et, ar1);
    agg_kernel<256, 4><<<gw, TB>>>(ei, et);
    ln_elu_kernel<<<gn, TB>>>(bi1, g1, be1);

    // ======== layer 2: in=256 -> [8 rel] x 64, H=1, no concat ========
    conv_w_kernel<<<(NR * 256 * 64 / 4 + TB - 1) / TB, TB>>>(W2, NR * 256 * 64 / 4);
    prep_ws_kernel<1, 64><<<(256 * 64 + TB - 1) / TB, TB>>>(W2, as2, ad2, 256);
    gemm_dots<64, 1><<<NT, TB>>>(nullptr, 256);
    mma_gemm<64, 256><<<gTC1, TB>>>(512);
    zero_soft_accum<1, 64><<<Z14, TB>>>();
    edge_exp_kernel<1><<<ge, TB>>>(ei, et, ar2);
    agg_kernel<64, 1><<<gw, TB>>>(ei, et);
    final_bias_kernel<<<(NN * 64 + TB - 1) / TB, TB>>>(bi2, out);
}

// round 10
// speedup vs baseline: 1.4806x; 1.0879x over previous
#include <cuda_runtime.h>
#include <cuda_bf16.h>
#include <cstdint>

#define NN 50000
#define NE 800000
#define NR 8

// ---------------- scratch (device globals; no allocs allowed) ----------------
__device__ __align__(16) float g_xw[(size_t)NN * NR * 256];   // per-rel transforms
__device__ __align__(16) float g_sd[NN * 64];                 // attention dots
__device__ __align__(16) float g_alpha[NE * 4];               // per-edge exp
__device__ __align__(16) float g_asum[NN * 4];
__device__ __align__(16) float g_h[(size_t)NN * 256];
__device__ __align__(16) float g_ws[256 * 64];
__device__ __align__(16) __nv_bfloat16 g_xh[(size_t)NN * 256];  // A operand hi
__device__ __align__(16) __nv_bfloat16 g_xl[(size_t)NN * 256];  // A operand lo
__device__ __align__(16) __nv_bfloat16 g_wh[NR * 256 * 256];    // B operand hi
__device__ __align__(16) __nv_bfloat16 g_wl[NR * 256 * 256];    // B operand lo
// CSR by destination (built once per launch)
__device__ int g_deg[NN];
__device__ int g_off[NN + 1];
__device__ int g_pos[NN];
__device__ int g_bsum[256];
__device__ int g_esr[NE];     // (src<<3)|rel, sorted by dst
__device__ int g_eid[NE];     // original edge id, sorted by dst

__device__ __forceinline__ float4 ld4(const float* p) { return *reinterpret_cast<const float4*>(p); }
__device__ __forceinline__ void st4(float* p, float4 v) { *reinterpret_cast<float4*>(p) = v; }

__device__ __forceinline__ uint32_t smem_u32(const void* p) {
    uint32_t a;
    asm("{ .reg .u64 t; cvta.to.shared.u64 t, %1; cvt.u32.u64 %0, t; }" : "=r"(a) : "l"(p));
    return a;
}

// fp32 pair -> bf16 hi pair + bf16 lo (residual) pair, packed as u32
__device__ __forceinline__ void split2(float x, float y, unsigned& hi, unsigned& lo) {
    __nv_bfloat16 hx = __float2bfloat16(x), hy = __float2bfloat16(y);
    float rx = x - __bfloat162float(hx), ry = y - __bfloat162float(hy);
    __nv_bfloat162 h; h.x = hx; h.y = hy;
    __nv_bfloat162 l = __floats2bfloat162_rn(rx, ry);
    hi = *reinterpret_cast<unsigned*>(&h);
    lo = *reinterpret_cast<unsigned*>(&l);
}

__device__ __forceinline__ void ldsm_x4(uint32_t addr, uint32_t& r0, uint32_t& r1, uint32_t& r2, uint32_t& r3) {
    asm volatile("ldmatrix.sync.aligned.m8n8.x4.shared.b16 {%0,%1,%2,%3}, [%4];"
                 : "=r"(r0), "=r"(r1), "=r"(r2), "=r"(r3) : "r"(addr));
}
__device__ __forceinline__ void ldsm_x4t(uint32_t addr, uint32_t& r0, uint32_t& r1, uint32_t& r2, uint32_t& r3) {
    asm volatile("ldmatrix.sync.aligned.m8n8.x4.trans.shared.b16 {%0,%1,%2,%3}, [%4];"
                 : "=r"(r0), "=r"(r1), "=r"(r2), "=r"(r3) : "r"(addr));
}
__device__ __forceinline__ void mma_bf16(float* d, const uint32_t* a, uint32_t b0, uint32_t b1) {
    asm volatile("mma.sync.aligned.m16n8k16.row.col.f32.bf16.bf16.f32 "
                 "{%0,%1,%2,%3}, {%4,%5,%6,%7}, {%8,%9}, {%0,%1,%2,%3};"
                 : "+f"(d[0]), "+f"(d[1]), "+f"(d[2]), "+f"(d[3])
                 : "r"(a[0]), "r"(a[1]), "r"(a[2]), "r"(a[3]), "r"(b0), "r"(b1));
}

// ---------------- elementwise fp32 -> bf16 hi/lo converters ----------------
__global__ void conv_x_kernel(const float* __restrict__ X, int total4) {
    int i = blockIdx.x * blockDim.x + threadIdx.x;
    if (i >= total4) return;
    float4 v = ld4(X + (size_t)i * 4);
    unsigned h0, l0, h1, l1;
    split2(v.x, v.y, h0, l0);
    split2(v.z, v.w, h1, l1);
    *reinterpret_cast<uint2*>(g_xh + (size_t)i * 4) = make_uint2(h0, h1);
    *reinterpret_cast<uint2*>(g_xl + (size_t)i * 4) = make_uint2(l0, l1);
}
__global__ void conv_w_kernel(const float* __restrict__ W, int total4) {
    int i = blockIdx.x * blockDim.x + threadIdx.x;
    if (i >= total4) return;
    float4 v = ld4(W + (size_t)i * 4);
    unsigned h0, l0, h1, l1;
    split2(v.x, v.y, h0, l0);
    split2(v.z, v.w, h1, l1);
    *reinterpret_cast<uint2*>(g_wh + (size_t)i * 4) = make_uint2(h0, h1);
    *reinterpret_cast<uint2*>(g_wl + (size_t)i * 4) = make_uint2(l0, l1);
}

// ======== HMMA split-bf16 GEMM (round-7 exact: single-buffer BK=32, static SMEM) ========
template<int NCOLS, int KTOT>
__global__ void __launch_bounds__(256) mma_gemm(int ldY) {
    constexpr int BN = (NCOLS < 128) ? NCOLS : 128;
    constexpr int WN = BN / 2;
    constexpr int NF2 = WN / 16;
    constexpr int AST = 40;
    constexpr int BST = BN + 8;

    __shared__ __align__(16) __nv_bfloat16 Ah[128][AST];
    __shared__ __align__(16) __nv_bfloat16 Al[128][AST];
    __shared__ __align__(16) __nv_bfloat16 Bh[32][BST];
    __shared__ __align__(16) __nv_bfloat16 Bl[32][BST];

    const int tid = threadIdx.x;
    const int wid = tid >> 5, lane = tid & 31;
    const int wm = wid & 3, wn = wid >> 2;
    const int rowBase = blockIdx.x * 128;
    const int nbase = blockIdx.y * BN;
    const int z = blockIdx.z;
    const __nv_bfloat16* Wh = g_wh + (size_t)z * KTOT * NCOLS;
    const __nv_bfloat16* Wl = g_wl + (size_t)z * KTOT * NCOLS;

    float acc[2][WN / 8][4];
    #pragma unroll
    for (int i = 0; i < 2; i++)
        #pragma unroll
        for (int j = 0; j < WN / 8; j++)
            #pragma unroll
            for (int q = 0; q < 4; q++) acc[i][j][q] = 0.f;

    for (int k0 = 0; k0 < KTOT; k0 += 32) {
        #pragma unroll
        for (int i = 0; i < 2; i++) {
            int li = tid + i * 256;
            int row = li >> 2, c8 = (li & 3) * 8;
            int gr = rowBase + row;
            uint4 vh = make_uint4(0, 0, 0, 0), vl = make_uint4(0, 0, 0, 0);
            if (gr < NN) {
                size_t goff = (size_t)gr * KTOT + k0 + c8;
                vh = *reinterpret_cast<const uint4*>(g_xh + goff);
                vl = *reinterpret_cast<const uint4*>(g_xl + goff);
            }
            *reinterpret_cast<uint4*>(&Ah[row][c8]) = vh;
            *reinterpret_cast<uint4*>(&Al[row][c8]) = vl;
        }
        #pragma unroll
        for (int i = 0; i < BN / 64; i++) {
            int li = tid + i * 256;
            int row = li / (BN / 8), c8 = (li % (BN / 8)) * 8;
            size_t goff = (size_t)(k0 + row) * NCOLS + nbase + c8;
            *reinterpret_cast<uint4*>(&Bh[row][c8]) = *reinterpret_cast<const uint4*>(Wh + goff);
            *reinterpret_cast<uint4*>(&Bl[row][c8]) = *reinterpret_cast<const uint4*>(Wl + goff);
        }
        __syncthreads();
        #pragma unroll
        for (int ks = 0; ks < 2; ks++) {
            uint32_t ah[2][4], al[2][4];
            #pragma unroll
            for (int mf = 0; mf < 2; mf++) {
                int arow = wm * 32 + mf * 16 + (lane & 15);
                int acol = ks * 16 + ((lane >> 4) << 3);
                ldsm_x4(smem_u32(&Ah[arow][acol]), ah[mf][0], ah[mf][1], ah[mf][2], ah[mf][3]);
                ldsm_x4(smem_u32(&Al[arow][acol]), al[mf][0], al[mf][1], al[mf][2], al[mf][3]);
            }
            #pragma unroll
            for (int nf2 = 0; nf2 < NF2; nf2++) {
                int brow = ks * 16 + (lane & 15);
                int bcol = wn * WN + nf2 * 16 + ((lane >> 4) << 3);
                uint32_t bh[4], bl[4];
                ldsm_x4t(smem_u32(&Bh[brow][bcol]), bh[0], bh[1], bh[2], bh[3]);
                ldsm_x4t(smem_u32(&Bl[brow][bcol]), bl[0], bl[1], bl[2], bl[3]);
                #pragma unroll
                for (int half = 0; half < 2; half++) {
                    uint32_t bH0 = bh[half * 2], bH1 = bh[half * 2 + 1];
                    uint32_t bL0 = bl[half * 2], bL1 = bl[half * 2 + 1];
                    #pragma unroll
                    for (int mf = 0; mf < 2; mf++) {
                        float* d = acc[mf][nf2 * 2 + half];
                        mma_bf16(d, ah[mf], bH0, bH1);
                        mma_bf16(d, ah[mf], bL0, bL1);
                        mma_bf16(d, al[mf], bH0, bH1);
                    }
                }
            }
        }
        __syncthreads();
    }
    const int colG = z * NCOLS + nbase + wn * WN + (lane & 3) * 2;
    #pragma unroll
    for (int mf = 0; mf < 2; mf++) {
        int r0 = rowBase + wm * 32 + mf * 16 + (lane >> 2);
        #pragma unroll
        for (int nf = 0; nf < WN / 8; nf++) {
            float* d = acc[mf][nf];
            int c = colG + nf * 8;
            if (r0 < NN)
                *reinterpret_cast<float2*>(g_xw + (size_t)r0 * ldY + c) = make_float2(d[0], d[1]);
            if (r0 + 8 < NN)
                *reinterpret_cast<float2*>(g_xw + (size_t)(r0 + 8) * ldY + c) = make_float2(d[2], d[3]);
        }
    }
}

// ---------------- CSR build (once per launch) ----------------
__global__ void zero_deg_kernel() {
    int i = blockIdx.x * blockDim.x + threadIdx.x;
    if (i < NN) g_deg[i] = 0;
}
__global__ void hist_kernel(const int* __restrict__ ei) {
    int e = blockIdx.x * blockDim.x + threadIdx.x;
    if (e < NE) atomicAdd(&g_deg[ei[NE + e]], 1);
}
__device__ __forceinline__ int blk_excl_scan(int v, int tid, int* wsum) {
    int lane = tid & 31, w = tid >> 5;
    int x = v;
    #pragma unroll
    for (int o = 1; o < 32; o <<= 1) { int t = __shfl_up_sync(~0u, x, o); if (lane >= o) x += t; }
    if (lane == 31) wsum[w] = x;
    __syncthreads();
    if (w == 0) {
        int s = (lane < 8) ? wsum[lane] : 0;
        #pragma unroll
        for (int o = 1; o < 8; o <<= 1) { int t = __shfl_up_sync(~0u, s, o); if (lane >= o) s += t; }
        if (lane < 8) wsum[lane] = s;
    }
    __syncthreads();
    int incl = x + (w > 0 ? wsum[w - 1] : 0);
    return incl - v;
}
__global__ void scan1_kernel() {
    __shared__ int wsum[8];
    int i = blockIdx.x * 256 + threadIdx.x;
    int v = (i < NN) ? g_deg[i] : 0;
    int excl = blk_excl_scan(v, threadIdx.x, wsum);
    if (i < NN) g_off[i] = excl;
    if (threadIdx.x == 255) g_bsum[blockIdx.x] = excl + v;
}
__global__ void scan2_kernel(int nb) {
    __shared__ int wsum[8];
    int t = threadIdx.x;
    int v = (t < nb) ? g_bsum[t] : 0;
    int excl = blk_excl_scan(v, t, wsum);
    if (t < nb) g_bsum[t] = excl;
}
__global__ void scan3_kernel() {
    int i = blockIdx.x * 256 + threadIdx.x;
    if (i < NN) {
        int f = g_off[i] + g_bsum[blockIdx.x];
        g_off[i] = f;
        g_pos[i] = f;
    }
    if (i == 0) g_off[NN] = NE;
}
__global__ void scatter_kernel(const int* __restrict__ ei, const int* __restrict__ et) {
    int e = blockIdx.x * blockDim.x + threadIdx.x;
    if (e >= NE) return;
    int dst = ei[NE + e];
    int p = atomicAdd(&g_pos[dst], 1);
    g_esr[p] = (ei[e] << 3) | et[e];
    g_eid[p] = e;
}

// ---------------- zero asum ----------------
template<int H>
__global__ void zero_asum_kernel() {
    int i = blockIdx.x * blockDim.x + threadIdx.x;
    if (i < NN * H) g_asum[i] = 0.f;
}

// ---------------- edge: logit -> leaky -> exp -> denom (shift-invariant softmax) ----------------
template<int H>
__global__ void edge_exp_kernel(const int* __restrict__ ei,
                                const int* __restrict__ et,
                                const float* __restrict__ arel) {
    int e = blockIdx.x * blockDim.x + threadIdx.x;
    if (e >= NE) return;
    int src = ei[e], dst = ei[NE + e], r = et[e];
    if constexpr (H == 4) {
        float4 s = ld4(g_sd + src * 64 + r * 4);
        float4 d = ld4(g_sd + dst * 64 + 32 + r * 4);
        float4 a = ld4(arel + r * 4);
        float4 v;
        v.x = s.x + d.x + a.x; v.y = s.y + d.y + a.y;
        v.z = s.z + d.z + a.z; v.w = s.w + d.w + a.w;
        v.x = v.x > 0.f ? v.x : 0.2f * v.x;
        v.y = v.y > 0.f ? v.y : 0.2f * v.y;
        v.z = v.z > 0.f ? v.z : 0.2f * v.z;
        v.w = v.w > 0.f ? v.w : 0.2f * v.w;
        float4 ex = make_float4(expf(v.x), expf(v.y), expf(v.z), expf(v.w));
        st4(g_alpha + (size_t)e * 4, ex);
        atomicAdd(reinterpret_cast<float4*>(g_asum + dst * 4), ex);
    } else {
        float v = g_sd[src * 64 + r] + g_sd[dst * 64 + 8 + r] + arel[r];
        v = v > 0.f ? v : 0.2f * v;
        float ex = expf(v);
        g_alpha[e] = ex;
        atomicAdd(&g_asum[dst], ex);
    }
}

// ---------------- CSR aggregation + bias + LN + ELU + bf16 export (warp per dst) ----------------
__global__ void agg_ln_csr(const float* __restrict__ bias, const float* __restrict__ gam,
                           const float* __restrict__ bet) {
    int n = (blockIdx.x * blockDim.x + threadIdx.x) >> 5;
    int lane = threadIdx.x & 31;
    if (n >= NN) return;
    int start = g_off[n], end = g_off[n + 1];
    float4 den = ld4(g_asum + n * 4);
    int c0 = lane * 4, c1 = 128 + lane * 4;
    float4 a0 = make_float4(0.f, 0.f, 0.f, 0.f);
    float4 a1 = make_float4(0.f, 0.f, 0.f, 0.f);
    for (int p = start; p < end; p++) {
        int sr = g_esr[p];
        int e = g_eid[p];
        float4 ex = ld4(g_alpha + (size_t)e * 4);
        float w0 = ex.x / den.x, w1 = ex.y / den.y, w2 = ex.z / den.z, w3 = ex.w / den.w;
        float sA = (lane < 16) ? w0 : w1;
        float sB = (lane < 16) ? w2 : w3;
        const float* xp = g_xw + ((size_t)(sr >> 3) * NR + (sr & 7)) * 256;
        float4 v0 = ld4(xp + c0), v1 = ld4(xp + c1);
        a0.x += v0.x * sA; a0.y += v0.y * sA; a0.z += v0.z * sA; a0.w += v0.w * sA;
        a1.x += v1.x * sB; a1.y += v1.y * sB; a1.z += v1.z * sB; a1.w += v1.w * sB;
    }
    float4 b0 = ld4(bias + c0), b1 = ld4(bias + c1);
    a0.x += b0.x; a0.y += b0.y; a0.z += b0.z; a0.w += b0.w;
    a1.x += b1.x; a1.y += b1.y; a1.z += b1.z; a1.w += b1.w;
    float sum = a0.x + a0.y + a0.z + a0.w + a1.x + a1.y + a1.z + a1.w;
    float sq = a0.x * a0.x + a0.y * a0.y + a0.z * a0.z + a0.w * a0.w
             + a1.x * a1.x + a1.y * a1.y + a1.z * a1.z + a1.w * a1.w;
    #pragma unroll
    for (int o = 16; o; o >>= 1) {
        sum += __shfl_xor_sync(0xffffffffu, sum, o);
        sq  += __shfl_xor_sync(0xffffffffu, sq, o);
    }
    float mean = sum * (1.f / 256.f);
    float var = sq * (1.f / 256.f) - mean * mean;
    float rstd = rsqrtf(var + 1e-5f);
    float4 g0 = ld4(gam + c0), g1 = ld4(gam + c1);
    float4 e0 = ld4(bet + c0), e1 = ld4(bet + c1);
    float4 y0, y1;
    y0.x = (a0.x - mean) * rstd * g0.x + e0.x;
    y0.y = (a0.y - mean) * rstd * g0.y + e0.y;
    y0.z = (a0.z - mean) * rstd * g0.z + e0.z;
    y0.w = (a0.w - mean) * rstd * g0.w + e0.w;
    y1.x = (a1.x - mean) * rstd * g1.x + e1.x;
    y1.y = (a1.y - mean) * rstd * g1.y + e1.y;
    y1.z = (a1.z - mean) * rstd * g1.z + e1.z;
    y1.w = (a1.w - mean) * rstd * g1.w + e1.w;
    y0.x = y0.x > 0.f ? y0.x : expm1f(y0.x);
    y0.y = y0.y > 0.f ? y0.y : expm1f(y0.y);
    y0.z = y0.z > 0.f ? y0.z : expm1f(y0.z);
    y0.w = y0.w > 0.f ? y0.w : expm1f(y0.w);
    y1.x = y1.x > 0.f ? y1.x : expm1f(y1.x);
    y1.y = y1.y > 0.f ? y1.y : expm1f(y1.y);
    y1.z = y1.z > 0.f ? y1.z : expm1f(y1.z);
    y1.w = y1.w > 0.f ? y1.w : expm1f(y1.w);
    float* hp = g_h + (size_t)n * 256;
    st4(hp + c0, y0);
    st4(hp + c1, y1);
    unsigned h0, l0, h1, l1;
    split2(y0.x, y0.y, h0, l0);
    split2(y0.z, y0.w, h1, l1);
    *reinterpret_cast<uint2*>(g_xh + (size_t)n * 256 + c0) = make_uint2(h0, h1);
    *reinterpret_cast<uint2*>(g_xl + (size_t)n * 256 + c0) = make_uint2(l0, l1);
    split2(y1.x, y1.y, h0, l0);
    split2(y1.z, y1.w, h1, l1);
    *reinterpret_cast<uint2*>(g_xh + (size_t)n * 256 + c1) = make_uint2(h0, h1);
    *reinterpret_cast<uint2*>(g_xl + (size_t)n * 256 + c1) = make_uint2(l0, l1);
}

// ---------------- CSR aggregation for layer 2 (half-warp per dst, M=64, H=1) + bias -> out ----------------
__global__ void agg_out_csr(const float* __restrict__ bi, float* __restrict__ out) {
    int hw = (blockIdx.x * blockDim.x + threadIdx.x) >> 4;   // half-warp per node
    int l16 = threadIdx.x & 15;
    if (hw >= NN) return;
    int n = hw;
    int start = g_off[n], end = g_off[n + 1];
    float den = g_asum[n];
    int c = l16 * 4;
    float4 acc = make_float4(0.f, 0.f, 0.f, 0.f);
    for (int p = start; p < end; p++) {
        int sr = g_esr[p];
        int e = g_eid[p];
        float w = g_alpha[e] / den;
        const float* xp = g_xw + ((size_t)(sr >> 3) * NR + (sr & 7)) * 64;
        float4 v = ld4(xp + c);
        acc.x += v.x * w; acc.y += v.y * w; acc.z += v.z * w; acc.w += v.w * w;
    }
    float4 b = ld4(bi + c);
    acc.x += b.x; acc.y += b.y; acc.z += b.z; acc.w += b.w;
    st4(out + (size_t)n * 64 + c, acc);
}

// ---------------- ws[k][col] = sum_c W[r][k][h*C+c] * a_{src|dst}[h][c] ----------------
template<int H, int C>
__global__ void prep_ws_kernel(const float* __restrict__ W, const float* __restrict__ a_src,
                               const float* __restrict__ a_dst, int K) {
    int idx = blockIdx.x * blockDim.x + threadIdx.x;
    if (idx >= K * 64) return;
    int k = idx >> 6;
    int col = idx & 63;
    constexpr int RH = NR * H;
    float acc = 0.f;
    if (col < 2 * RH) {
        int isd = col >= RH;
        int rh = isd ? col - RH : col;
        int r = rh / H, h = rh % H;
        const float* a = isd ? a_dst : a_src;
        const float* wrow = W + ((size_t)r * K + k) * (H * C) + h * C;
        #pragma unroll 8
        for (int c = 0; c < C; c++) acc += wrow[c] * a[h * C + c];
    }
    g_ws[idx] = acc;
}

// ---------------- fp32 SGEMM (attention dots only): g_sd = X @ g_ws ----------------
template<int BN, int XH>
__global__ void __launch_bounds__(256) gemm_dots(const float* __restrict__ Xp, int K) {
    constexpr int BM = 128, BK = 16;
    constexpr int TN = BN / 16;
    const float* X = XH ? (const float*)g_h : Xp;
    const float* W = (const float*)g_ws;
    float* Y = (float*)g_sd;
    __shared__ float As[BK][BM];
    __shared__ float Bs[BK][BN];
    const int tid = threadIdx.x;
    const int tx = tid & 15, ty = tid >> 4;
    const int rowBase = blockIdx.x * BM;

    float acc[8][TN];
    #pragma unroll
    for (int i = 0; i < 8; i++)
        #pragma unroll
        for (int j = 0; j < TN; j++) acc[i][j] = 0.f;

    for (int k0 = 0; k0 < K; k0 += BK) {
        #pragma unroll
        for (int i = 0; i < 2; i++) {
            int idx = tid + i * 256;
            int ar = idx >> 2;
            int ac = (idx & 3) << 2;
            int gr = rowBase + ar;
            float4 v = make_float4(0.f, 0.f, 0.f, 0.f);
            if (gr < NN) v = ld4(X + (size_t)gr * K + k0 + ac);
            As[ac + 0][ar] = v.x; As[ac + 1][ar] = v.y;
            As[ac + 2][ar] = v.z; As[ac + 3][ar] = v.w;
        }
        if (tid < BK * BN / 4) {
            int br = tid / (BN / 4);
            int bc = (tid % (BN / 4)) << 2;
            st4(&Bs[br][bc], ld4(W + (size_t)(k0 + br) * 64 + bc));
        }
        __syncthreads();
        #pragma unroll
        for (int kk = 0; kk < BK; kk++) {
            float av[8], bv[TN];
            float4 a0 = *reinterpret_cast<const float4*>(&As[kk][ty * 4]);
            float4 a1 = *reinterpret_cast<const float4*>(&As[kk][64 + ty * 4]);
            av[0] = a0.x; av[1] = a0.y; av[2] = a0.z; av[3] = a0.w;
            av[4] = a1.x; av[5] = a1.y; av[6] = a1.z; av[7] = a1.w;
            float4 b0 = *reinterpret_cast<const float4*>(&Bs[kk][tx * 4]);
            bv[0] = b0.x; bv[1] = b0.y; bv[2] = b0.z; bv[3] = b0.w;
            #pragma unroll
            for (int i = 0; i < 8; i++)
                #pragma unroll
                for (int j = 0; j < TN; j++) acc[i][j] = fmaf(av[i], bv[j], acc[i][j]);
        }
        __syncthreads();
    }
    #pragma unroll
    for (int i = 0; i < 8; i++) {
        int lr = (i < 4) ? (ty * 4 + i) : (64 + ty * 4 + (i - 4));
        int gr = rowBase + lr;
        if (gr >= NN) continue;
        st4(Y + (size_t)gr * 64 + tx * 4, make_float4(acc[i][0], acc[i][1], acc[i][2], acc[i][3]));
    }
}

// ---------------- orchestration (pure kernel launches) ----------------
extern "C" void kernel_launch(void* const* d_in, const int* in_sizes, int n_in,
                              void* d_out, int out_size) {
    (void)in_sizes; (void)n_in; (void)out_size;
    const float* x  = (const float*)d_in[0];
    const int* ei   = (const int*)d_in[1];
    const int* et   = (const int*)d_in[2];
    const float* W0 = (const float*)d_in[3];
    const float* as0 = (const float*)d_in[4];
    const float* ad0 = (const float*)d_in[5];
    const float* ar0 = (const float*)d_in[6];
    const float* bi0 = (const float*)d_in[7];
    const float* W1 = (const float*)d_in[8];
    const float* as1 = (const float*)d_in[9];
    const float* ad1 = (const float*)d_in[10];
    const float* ar1 = (const float*)d_in[11];
    const float* bi1 = (const float*)d_in[12];
    const float* W2 = (const float*)d_in[13];
    const float* as2 = (const float*)d_in[14];
    const float* ad2 = (const float*)d_in[15];
    const float* ar2 = (const float*)d_in[16];
    const float* bi2 = (const float*)d_in[17];
    const float* g0 = (const float*)d_in[18];
    const float* be0 = (const float*)d_in[19];
    const float* g1 = (const float*)d_in[20];
    const float* be1 = (const float*)d_in[21];
    float* out = (float*)d_out;

    const int TB = 256;
    const int NT = (NN + 127) / 128;
    const int NB = (NN + 255) / 256;            // 196 scan blocks
    dim3 gTC2(NT, 2, 8);
    dim3 gTC1(NT, 1, 8);
    int ge = (NE + TB - 1) / TB;
    int gwn = (NN * 32 + TB - 1) / TB;          // warp per node
    int ghn = (NN * 16 + TB - 1) / TB;          // half-warp per node

    // ---- build dst-CSR once ----
    zero_deg_kernel<<<NB, TB>>>();
    hist_kernel<<<ge, TB>>>(ei);
    scan1_kernel<<<NB, TB>>>();
    scan2_kernel<<<1, TB>>>(NB);
    scan3_kernel<<<NB, TB>>>();
    scatter_kernel<<<ge, TB>>>(ei, et);

    // ======== layer 0: in=128 -> [8 rel] x 256, H=4 ========
    conv_w_kernel<<<(NR * 128 * 256 / 4 + TB - 1) / TB, TB>>>(W0, NR * 128 * 256 / 4);
    conv_x_kernel<<<(NN * 128 / 4 + TB - 1) / TB, TB>>>(x, NN * 128 / 4);
    prep_ws_kernel<4, 64><<<(128 * 64 + TB - 1) / TB, TB>>>(W0, as0, ad0, 128);
    gemm_dots<64, 0><<<NT, TB>>>(x, 128);
    mma_gemm<256, 128><<<gTC2, TB>>>(2048);
    zero_asum_kernel<4><<<(NN * 4 + TB - 1) / TB, TB>>>();
    edge_exp_kernel<4><<<ge, TB>>>(ei, et, ar0);
    agg_ln_csr<<<gwn, TB>>>(bi0, g0, be0);

    // ======== layer 1: in=256 -> [8 rel] x 256, H=4 ========
    conv_w_kernel<<<(NR * 256 * 256 / 4 + TB - 1) / TB, TB>>>(W1, NR * 256 * 256 / 4);
    prep_ws_kernel<4, 64><<<(256 * 64 + TB - 1) / TB, TB>>>(W1, as1, ad1, 256);
    gemm_dots<64, 1><<<NT, TB>>>(nullptr, 256);
    mma_gemm<256, 256><<<gTC2, TB>>>(2048);
    zero_asum_kernel<4><<<(NN * 4 + TB - 1) / TB, TB>>>();
    edge_exp_kernel<4><<<ge, TB>>>(ei, et, ar1);
    agg_ln_csr<<<gwn, TB>>>(bi1, g1, be1);

    // ======== layer 2: in=256 -> [8 rel] x 64, H=1, no concat ========
    conv_w_kernel<<<(NR * 256 * 64 / 4 + TB - 1) / TB, TB>>>(W2, NR * 256 * 64 / 4);
    prep_ws_kernel<1, 64><<<(256 * 64 + TB - 1) / TB, TB>>>(W2, as2, ad2, 256);
    gemm_dots<64, 1><<<NT, TB>>>(nullptr, 256);
    mma_gemm<64, 256><<<gTC1, TB>>>(512);
    zero_asum_kernel<1><<<(NN + TB - 1) / TB, TB>>>();
    edge_exp_kernel<1><<<ge, TB>>>(ei, et, ar2);
    agg_out_csr<<<ghn, TB>>>(bi2, out);
}

// round 12
// speedup vs baseline: 1.8660x; 1.2603x over previous
#include <cuda_runtime.h>
#include <cuda_bf16.h>
#include <cstdint>

#define NN 50000
#define NE 800000
#define NR 8

// ---------------- scratch (device globals; no allocs allowed) ----------------
__device__ __align__(16) float g_xw[(size_t)NN * NR * 256];   // per-rel transforms
__device__ __align__(16) float g_sd[NN * 64];                 // attention dots
__device__ __align__(16) float g_h[(size_t)NN * 256];
__device__ __align__(16) float g_ws[256 * 64];
__device__ __align__(16) __nv_bfloat16 g_xh[(size_t)NN * 256];  // A operand hi
__device__ __align__(16) __nv_bfloat16 g_xl[(size_t)NN * 256];  // A operand lo
__device__ __align__(16) __nv_bfloat16 g_wh[256 * 2048];        // B hi, [K][8*M] transposed-concat
__device__ __align__(16) __nv_bfloat16 g_wl[256 * 2048];        // B lo
// CSR by destination (built once per launch)
__device__ int g_deg[NN];
__device__ int g_off[NN + 1];
__device__ int g_pos[NN];
__device__ int g_bsum[256];
__device__ int g_esr[NE];     // (src<<3)|rel, grouped by dst

__device__ __forceinline__ float4 ld4(const float* p) { return *reinterpret_cast<const float4*>(p); }
__device__ __forceinline__ void st4(float* p, float4 v) { *reinterpret_cast<float4*>(p) = v; }

__device__ __forceinline__ uint32_t smem_u32(const void* p) {
    uint32_t a;
    asm("{ .reg .u64 t; cvta.to.shared.u64 t, %1; cvt.u32.u64 %0, t; }" : "=r"(a) : "l"(p));
    return a;
}

// fp32 pair -> bf16 hi pair + bf16 lo (residual) pair, packed as u32
__device__ __forceinline__ void split2(float x, float y, unsigned& hi, unsigned& lo) {
    __nv_bfloat16 hx = __float2bfloat16(x), hy = __float2bfloat16(y);
    float rx = x - __bfloat162float(hx), ry = y - __bfloat162float(hy);
    __nv_bfloat162 h; h.x = hx; h.y = hy;
    __nv_bfloat162 l = __floats2bfloat162_rn(rx, ry);
    hi = *reinterpret_cast<unsigned*>(&h);
    lo = *reinterpret_cast<unsigned*>(&l);
}

__device__ __forceinline__ void ldsm_x4(uint32_t addr, uint32_t& r0, uint32_t& r1, uint32_t& r2, uint32_t& r3) {
    asm volatile("ldmatrix.sync.aligned.m8n8.x4.shared.b16 {%0,%1,%2,%3}, [%4];"
                 : "=r"(r0), "=r"(r1), "=r"(r2), "=r"(r3) : "r"(addr));
}
__device__ __forceinline__ void ldsm_x4t(uint32_t addr, uint32_t& r0, uint32_t& r1, uint32_t& r2, uint32_t& r3) {
    asm volatile("ldmatrix.sync.aligned.m8n8.x4.trans.shared.b16 {%0,%1,%2,%3}, [%4];"
                 : "=r"(r0), "=r"(r1), "=r"(r2), "=r"(r3) : "r"(addr));
}
__device__ __forceinline__ void mma_bf16(float* d, const uint32_t* a, uint32_t b0, uint32_t b1) {
    asm volatile("mma.sync.aligned.m16n8k16.row.col.f32.bf16.bf16.f32 "
                 "{%0,%1,%2,%3}, {%4,%5,%6,%7}, {%8,%9}, {%0,%1,%2,%3};"
                 : "+f"(d[0]), "+f"(d[1]), "+f"(d[2]), "+f"(d[3])
                 : "r"(a[0]), "r"(a[1]), "r"(a[2]), "r"(a[3]), "r"(b0), "r"(b1));
}

// ---------------- fp32 -> bf16 hi/lo converters ----------------
__global__ void conv_x_kernel(const float* __restrict__ X, int total4) {
    int i = blockIdx.x * blockDim.x + threadIdx.x;
    if (i >= total4) return;
    float4 v = ld4(X + (size_t)i * 4);
    unsigned h0, l0, h1, l1;
    split2(v.x, v.y, h0, l0);
    split2(v.z, v.w, h1, l1);
    *reinterpret_cast<uint2*>(g_xh + (size_t)i * 4) = make_uint2(h0, h1);
    *reinterpret_cast<uint2*>(g_xl + (size_t)i * 4) = make_uint2(l0, l1);
}
// W [R][K][M] -> transposed-concat [K][R*M] bf16 hi/lo
template<int K, int M>
__global__ void conv_w_t(const float* __restrict__ W) {
    int i = blockIdx.x * blockDim.x + threadIdx.x;
    constexpr int ROW4 = 8 * M / 4;
    if (i >= K * ROW4) return;
    int k = i / ROW4;
    int rest = i % ROW4;
    int z = rest / (M / 4);
    int m4 = rest % (M / 4);
    float4 v = ld4(W + ((size_t)z * K + k) * M + m4 * 4);
    unsigned h0, l0, h1, l1;
    split2(v.x, v.y, h0, l0);
    split2(v.z, v.w, h1, l1);
    *reinterpret_cast<uint2*>(g_wh + (size_t)i * 4) = make_uint2(h0, h1);
    *reinterpret_cast<uint2*>(g_wl + (size_t)i * 4) = make_uint2(l0, l1);
}

// ======== HMMA split-bf16 GEMM: g_xw[row][col] = X[row,:]·Wt[:,col], NTOT = 8*MP ========
template<int MP, int KTOT>
__global__ void __launch_bounds__(256) mma_gemm() {
    constexpr int NTOT = 8 * MP;
    constexpr int BN = 128, WN = 64, NF2 = 4;
    constexpr int AST = 40;
    constexpr int BST = BN + 8;

    __shared__ __align__(16) __nv_bfloat16 Ah[128][AST];
    __shared__ __align__(16) __nv_bfloat16 Al[128][AST];
    __shared__ __align__(16) __nv_bfloat16 Bh[32][BST];
    __shared__ __align__(16) __nv_bfloat16 Bl[32][BST];

    const int tid = threadIdx.x;
    const int wid = tid >> 5, lane = tid & 31;
    const int wm = wid & 3, wn = wid >> 2;
    const int rowBase = blockIdx.x * 128;
    const int nbase = blockIdx.y * BN;

    float acc[2][8][4];
    #pragma unroll
    for (int i = 0; i < 2; i++)
        #pragma unroll
        for (int j = 0; j < 8; j++)
            #pragma unroll
            for (int q = 0; q < 4; q++) acc[i][j][q] = 0.f;

    for (int k0 = 0; k0 < KTOT; k0 += 32) {
        #pragma unroll
        for (int i = 0; i < 2; i++) {
            int li = tid + i * 256;
            int row = li >> 2, c8 = (li & 3) * 8;
            int gr = rowBase + row;
            uint4 vh = make_uint4(0, 0, 0, 0), vl = make_uint4(0, 0, 0, 0);
            if (gr < NN) {
                size_t goff = (size_t)gr * KTOT + k0 + c8;
                vh = *reinterpret_cast<const uint4*>(g_xh + goff);
                vl = *reinterpret_cast<const uint4*>(g_xl + goff);
            }
            *reinterpret_cast<uint4*>(&Ah[row][c8]) = vh;
            *reinterpret_cast<uint4*>(&Al[row][c8]) = vl;
        }
        #pragma unroll
        for (int i = 0; i < 2; i++) {
            int li = tid + i * 256;
            int row = li >> 4, c8 = (li & 15) * 8;
            size_t goff = (size_t)(k0 + row) * NTOT + nbase + c8;
            *reinterpret_cast<uint4*>(&Bh[row][c8]) = *reinterpret_cast<const uint4*>(g_wh + goff);
            *reinterpret_cast<uint4*>(&Bl[row][c8]) = *reinterpret_cast<const uint4*>(g_wl + goff);
        }
        __syncthreads();
        #pragma unroll
        for (int ks = 0; ks < 2; ks++) {
            uint32_t ah[2][4], al[2][4];
            #pragma unroll
            for (int mf = 0; mf < 2; mf++) {
                int arow = wm * 32 + mf * 16 + (lane & 15);
                int acol = ks * 16 + ((lane >> 4) << 3);
                ldsm_x4(smem_u32(&Ah[arow][acol]), ah[mf][0], ah[mf][1], ah[mf][2], ah[mf][3]);
                ldsm_x4(smem_u32(&Al[arow][acol]), al[mf][0], al[mf][1], al[mf][2], al[mf][3]);
            }
            #pragma unroll
            for (int nf2 = 0; nf2 < NF2; nf2++) {
                int brow = ks * 16 + (lane & 15);
                int bcol = wn * WN + nf2 * 16 + ((lane >> 4) << 3);
                uint32_t bh[4], bl[4];
                ldsm_x4t(smem_u32(&Bh[brow][bcol]), bh[0], bh[1], bh[2], bh[3]);
                ldsm_x4t(smem_u32(&Bl[brow][bcol]), bl[0], bl[1], bl[2], bl[3]);
                #pragma unroll
                for (int half = 0; half < 2; half++) {
                    uint32_t bH0 = bh[half * 2], bH1 = bh[half * 2 + 1];
                    uint32_t bL0 = bl[half * 2], bL1 = bl[half * 2 + 1];
                    #pragma unroll
                    for (int mf = 0; mf < 2; mf++) {
                        float* d = acc[mf][nf2 * 2 + half];
                        mma_bf16(d, ah[mf], bH0, bH1);
                        mma_bf16(d, ah[mf], bL0, bL1);
                        mma_bf16(d, al[mf], bH0, bH1);
                    }
                }
            }
        }
        __syncthreads();
    }
    const int colG = nbase + wn * WN + (lane & 3) * 2;
    #pragma unroll
    for (int mf = 0; mf < 2; mf++) {
        int r0 = rowBase + wm * 32 + mf * 16 + (lane >> 2);
        #pragma unroll
        for (int nf = 0; nf < 8; nf++) {
            float* d = acc[mf][nf];
            int c = colG + nf * 8;
            if (r0 < NN)
                *reinterpret_cast<float2*>(g_xw + (size_t)r0 * NTOT + c) = make_float2(d[0], d[1]);
            if (r0 + 8 < NN)
                *reinterpret_cast<float2*>(g_xw + (size_t)(r0 + 8) * NTOT + c) = make_float2(d[2], d[3]);
        }
    }
}

// ---------------- CSR build (once per launch) ----------------
__global__ void zero_deg_kernel() {
    int i = blockIdx.x * blockDim.x + threadIdx.x;
    if (i < NN) g_deg[i] = 0;
}
__global__ void hist_kernel(const int* __restrict__ ei) {
    int e = blockIdx.x * blockDim.x + threadIdx.x;
    if (e < NE) atomicAdd(&g_deg[ei[NE + e]], 1);
}
__device__ __forceinline__ int blk_excl_scan(int v, int tid, int* wsum) {
    int lane = tid & 31, w = tid >> 5;
    int x = v;
    #pragma unroll
    for (int o = 1; o < 32; o <<= 1) { int t = __shfl_up_sync(~0u, x, o); if (lane >= o) x += t; }
    if (lane == 31) wsum[w] = x;
    __syncthreads();
    if (w == 0) {
        int s = (lane < 8) ? wsum[lane] : 0;
        #pragma unroll
        for (int o = 1; o < 8; o <<= 1) { int t = __shfl_up_sync(~0u, s, o); if (lane >= o) s += t; }
        if (lane < 8) wsum[lane] = s;
    }
    __syncthreads();
    int incl = x + (w > 0 ? wsum[w - 1] : 0);
    return incl - v;
}
__global__ void scan1_kernel() {
    __shared__ int wsum[8];
    int i = blockIdx.x * 256 + threadIdx.x;
    int v = (i < NN) ? g_deg[i] : 0;
    int excl = blk_excl_scan(v, threadIdx.x, wsum);
    if (i < NN) g_off[i] = excl;
    if (threadIdx.x == 255) g_bsum[blockIdx.x] = excl + v;
}
__global__ void scan2_kernel(int nb) {
    __shared__ int wsum[8];
    int t = threadIdx.x;
    int v = (t < nb) ? g_bsum[t] : 0;
    int excl = blk_excl_scan(v, t, wsum);
    if (t < nb) g_bsum[t] = excl;
}
__global__ void scan3_kernel() {
    int i = blockIdx.x * 256 + threadIdx.x;
    if (i < NN) {
        int f = g_off[i] + g_bsum[blockIdx.x];
        g_off[i] = f;
        g_pos[i] = f;
    }
    if (i == 0) g_off[NN] = NE;
}
__global__ void scatter_kernel(const int* __restrict__ ei, const int* __restrict__ et) {
    int e = blockIdx.x * blockDim.x + threadIdx.x;
    if (e >= NE) return;
    int dst = ei[NE + e];
    int p = atomicAdd(&g_pos[dst], 1);
    g_esr[p] = (ei[e] << 3) | et[e];
}

// ---------------- fused softmax+aggregation+bias+LN+ELU+bf16 export (warp per dst; H=4, M=256) ----------------
__global__ void agg_ln_csr(const float* __restrict__ arel, const float* __restrict__ bias,
                           const float* __restrict__ gam, const float* __restrict__ bet) {
    int n = (blockIdx.x * blockDim.x + threadIdx.x) >> 5;
    int lane = threadIdx.x & 31;
    if (n >= NN) return;
    int start = g_off[n], end = g_off[n + 1];
    int c0 = lane * 4, c1 = 128 + lane * 4;
    float4 a0 = make_float4(0.f, 0.f, 0.f, 0.f);
    float4 a1 = make_float4(0.f, 0.f, 0.f, 0.f);
    float4 den = make_float4(0.f, 0.f, 0.f, 0.f);
    for (int base = start; base < end; base += 32) {
        int p = base + lane;
        float4 ex = make_float4(0.f, 0.f, 0.f, 0.f);
        int sr = 0;
        if (p < end) {
            sr = g_esr[p];
            int src = sr >> 3, r = sr & 7;
            float4 s = ld4(g_sd + src * 64 + r * 4);
            float4 d = ld4(g_sd + n * 64 + 32 + r * 4);
            float4 a = ld4(arel + r * 4);
            float4 v;
            v.x = s.x + d.x + a.x; v.y = s.y + d.y + a.y;
            v.z = s.z + d.z + a.z; v.w = s.w + d.w + a.w;
            v.x = v.x > 0.f ? v.x : 0.2f * v.x;
            v.y = v.y > 0.f ? v.y : 0.2f * v.y;
            v.z = v.z > 0.f ? v.z : 0.2f * v.z;
            v.w = v.w > 0.f ? v.w : 0.2f * v.w;
            ex = make_float4(expf(v.x), expf(v.y), expf(v.z), expf(v.w));
        }
        den.x += ex.x; den.y += ex.y; den.z += ex.z; den.w += ex.w;
        int cnt = min(32, end - base);
        for (int j = 0; j < cnt; j++) {
            int srj = __shfl_sync(~0u, sr, j);
            float e0 = __shfl_sync(~0u, ex.x, j);
            float e1 = __shfl_sync(~0u, ex.y, j);
            float e2 = __shfl_sync(~0u, ex.z, j);
            float e3 = __shfl_sync(~0u, ex.w, j);
            float sA = (lane < 16) ? e0 : e1;
            float sB = (lane < 16) ? e2 : e3;
            const float* xp = g_xw + (size_t)(srj >> 3) * 2048 + (srj & 7) * 256;
            float4 v0 = ld4(xp + c0), v1 = ld4(xp + c1);
            a0.x += v0.x * sA; a0.y += v0.y * sA; a0.z += v0.z * sA; a0.w += v0.w * sA;
            a1.x += v1.x * sB; a1.y += v1.y * sB; a1.z += v1.z * sB; a1.w += v1.w * sB;
        }
    }
    #pragma unroll
    for (int o = 16; o; o >>= 1) {
        den.x += __shfl_xor_sync(~0u, den.x, o);
        den.y += __shfl_xor_sync(~0u, den.y, o);
        den.z += __shfl_xor_sync(~0u, den.z, o);
        den.w += __shfl_xor_sync(~0u, den.w, o);
    }
    float dA = (lane < 16) ? den.x : den.y;
    float dB = (lane < 16) ? den.z : den.w;
    float iA = dA > 0.f ? 1.f / dA : 0.f;
    float iB = dB > 0.f ? 1.f / dB : 0.f;
    a0.x *= iA; a0.y *= iA; a0.z *= iA; a0.w *= iA;
    a1.x *= iB; a1.y *= iB; a1.z *= iB; a1.w *= iB;
    float4 b0 = ld4(bias + c0), b1 = ld4(bias + c1);
    a0.x += b0.x; a0.y += b0.y; a0.z += b0.z; a0.w += b0.w;
    a1.x += b1.x; a1.y += b1.y; a1.z += b1.z; a1.w += b1.w;
    float sum = a0.x + a0.y + a0.z + a0.w + a1.x + a1.y + a1.z + a1.w;
    float sq = a0.x * a0.x + a0.y * a0.y + a0.z * a0.z + a0.w * a0.w
             + a1.x * a1.x + a1.y * a1.y + a1.z * a1.z + a1.w * a1.w;
    #pragma unroll
    for (int o = 16; o; o >>= 1) {
        sum += __shfl_xor_sync(0xffffffffu, sum, o);
        sq  += __shfl_xor_sync(0xffffffffu, sq, o);
    }
    float mean = sum * (1.f / 256.f);
    float var = sq * (1.f / 256.f) - mean * mean;
    float rstd = rsqrtf(var + 1e-5f);
    float4 g0 = ld4(gam + c0), g1 = ld4(gam + c1);
    float4 e0v = ld4(bet + c0), e1v = ld4(bet + c1);
    float4 y0, y1;
    y0.x = (a0.x - mean) * rstd * g0.x + e0v.x;
    y0.y = (a0.y - mean) * rstd * g0.y + e0v.y;
    y0.z = (a0.z - mean) * rstd * g0.z + e0v.z;
    y0.w = (a0.w - mean) * rstd * g0.w + e0v.w;
    y1.x = (a1.x - mean) * rstd * g1.x + e1v.x;
    y1.y = (a1.y - mean) * rstd * g1.y + e1v.y;
    y1.z = (a1.z - mean) * rstd * g1.z + e1v.z;
    y1.w = (a1.w - mean) * rstd * g1.w + e1v.w;
    y0.x = y0.x > 0.f ? y0.x : expm1f(y0.x);
    y0.y = y0.y > 0.f ? y0.y : expm1f(y0.y);
    y0.z = y0.z > 0.f ? y0.z : expm1f(y0.z);
    y0.w = y0.w > 0.f ? y0.w : expm1f(y0.w);
    y1.x = y1.x > 0.f ? y1.x : expm1f(y1.x);
    y1.y = y1.y > 0.f ? y1.y : expm1f(y1.y);
    y1.z = y1.z > 0.f ? y1.z : expm1f(y1.z);
    y1.w = y1.w > 0.f ? y1.w : expm1f(y1.w);
    float* hp = g_h + (size_t)n * 256;
    st4(hp + c0, y0);
    st4(hp + c1, y1);
    unsigned h0, l0, h1, l1;
    split2(y0.x, y0.y, h0, l0);
    split2(y0.z, y0.w, h1, l1);
    *reinterpret_cast<uint2*>(g_xh + (size_t)n * 256 + c0) = make_uint2(h0, h1);
    *reinterpret_cast<uint2*>(g_xl + (size_t)n * 256 + c0) = make_uint2(l0, l1);
    split2(y1.x, y1.y, h0, l0);
    split2(y1.z, y1.w, h1, l1);
    *reinterpret_cast<uint2*>(g_xh + (size_t)n * 256 + c1) = make_uint2(h0, h1);
    *reinterpret_cast<uint2*>(g_xl + (size_t)n * 256 + c1) = make_uint2(l0, l1);
}

// ---------------- fused softmax+aggregation layer 2 (warp per dst; H=1, M=64) + bias -> out ----------------
// NOTE: broadcast loop is warp-uniform; accumulation predicated by (j&1)==half.
__global__ void agg_out_csr(const float* __restrict__ arel, const float* __restrict__ bi,
                            float* __restrict__ out) {
    int n = (blockIdx.x * blockDim.x + threadIdx.x) >> 5;
    int lane = threadIdx.x & 31;
    if (n >= NN) return;
    int start = g_off[n], end = g_off[n + 1];
    int half = lane >> 4;
    int c = (lane & 15) * 4;
    float4 acc = make_float4(0.f, 0.f, 0.f, 0.f);
    float den = 0.f;
    for (int base = start; base < end; base += 32) {
        int p = base + lane;
        float ex = 0.f;
        int sr = 0;
        if (p < end) {
            sr = g_esr[p];
            int src = sr >> 3, r = sr & 7;
            float v = g_sd[src * 64 + r] + g_sd[n * 64 + 8 + r] + arel[r];
            v = v > 0.f ? v : 0.2f * v;
            ex = expf(v);
        }
        den += ex;
        int cnt = min(32, end - base);
        for (int j = 0; j < cnt; j++) {
            int srj = __shfl_sync(~0u, sr, j);
            float exj = __shfl_sync(~0u, ex, j);
            if ((j & 1) == half) {
                const float* xp = g_xw + (size_t)(srj >> 3) * 512 + (srj & 7) * 64;
                float4 v = ld4(xp + c);
                acc.x += v.x * exj; acc.y += v.y * exj; acc.z += v.z * exj; acc.w += v.w * exj;
            }
        }
    }
    #pragma unroll
    for (int o = 16; o; o >>= 1) den += __shfl_xor_sync(~0u, den, o);
    acc.x += __shfl_xor_sync(~0u, acc.x, 16);
    acc.y += __shfl_xor_sync(~0u, acc.y, 16);
    acc.z += __shfl_xor_sync(~0u, acc.z, 16);
    acc.w += __shfl_xor_sync(~0u, acc.w, 16);
    if (half == 0) {
        float inv = den > 0.f ? 1.f / den : 0.f;
        float4 b = ld4(bi + c);
        acc.x = acc.x * inv + b.x;
        acc.y = acc.y * inv + b.y;
        acc.z = acc.z * inv + b.z;
        acc.w = acc.w * inv + b.w;
        st4(out + (size_t)n * 64 + c, acc);
    }
}

// ---------------- ws[k][col] = sum_c W[r][k][h*C+c] * a_{src|dst}[h][c] ----------------
template<int H, int C>
__global__ void prep_ws_kernel(const float* __restrict__ W, const float* __restrict__ a_src,
                               const float* __restrict__ a_dst, int K) {
    int idx = blockIdx.x * blockDim.x + threadIdx.x;
    if (idx >= K * 64) return;
    int k = idx >> 6;
    int col = idx & 63;
    constexpr int RH = NR * H;
    float acc = 0.f;
    if (col < 2 * RH) {
        int isd = col >= RH;
        int rh = isd ? col - RH : col;
        int r = rh / H, h = rh % H;
        const float* a = isd ? a_dst : a_src;
        const float* wrow = W + ((size_t)r * K + k) * (H * C) + h * C;
        #pragma unroll 8
        for (int c = 0; c < C; c++) acc += wrow[c] * a[h * C + c];
    }
    g_ws[idx] = acc;
}

// ---------------- fp32 SGEMM (attention dots only): g_sd = X @ g_ws ----------------
template<int BN, int XH>
__global__ void __launch_bounds__(256) gemm_dots(const float* __restrict__ Xp, int K) {
    constexpr int BM = 128, BK = 16;
    constexpr int TN = BN / 16;
    const float* X = XH ? (const float*)g_h : Xp;
    const float* W = (const float*)g_ws;
    float* Y = (float*)g_sd;
    __shared__ float As[BK][BM];
    __shared__ float Bs[BK][BN];
    const int tid = threadIdx.x;
    const int tx = tid & 15, ty = tid >> 4;
    const int rowBase = blockIdx.x * BM;

    float acc[8][TN];
    #pragma unroll
    for (int i = 0; i < 8; i++)
        #pragma unroll
        for (int j = 0; j < TN; j++) acc[i][j] = 0.f;

    for (int k0 = 0; k0 < K; k0 += BK) {
        #pragma unroll
        for (int i = 0; i < 2; i++) {
            int idx = tid + i * 256;
            int ar = idx >> 2;
            int ac = (idx & 3) << 2;
            int gr = rowBase + ar;
            float4 v = make_float4(0.f, 0.f, 0.f, 0.f);
            if (gr < NN) v = ld4(X + (size_t)gr * K + k0 + ac);
            As[ac + 0][ar] = v.x; As[ac + 1][ar] = v.y;
            As[ac + 2][ar] = v.z; As[ac + 3][ar] = v.w;
        }
        if (tid < BK * BN / 4) {
            int br = tid / (BN / 4);
            int bc = (tid % (BN / 4)) << 2;
            st4(&Bs[br][bc], ld4(W + (size_t)(k0 + br) * 64 + bc));
        }
        __syncthreads();
        #pragma unroll
        for (int kk = 0; kk < BK; kk++) {
            float av[8], bv[TN];
            float4 a0 = *reinterpret_cast<const float4*>(&As[kk][ty * 4]);
            float4 a1 = *reinterpret_cast<const float4*>(&As[kk][64 + ty * 4]);
            av[0] = a0.x; av[1] = a0.y; av[2] = a0.z; av[3] = a0.w;
            av[4] = a1.x; av[5] = a1.y; av[6] = a1.z; av[7] = a1.w;
            float4 b0 = *reinterpret_cast<const float4*>(&Bs[kk][tx * 4]);
            bv[0] = b0.x; bv[1] = b0.y; bv[2] = b0.z; bv[3] = b0.w;
            #pragma unroll
            for (int i = 0; i < 8; i++)
                #pragma unroll
                for (int j = 0; j < TN; j++) acc[i][j] = fmaf(av[i], bv[j], acc[i][j]);
        }
        __syncthreads();
    }
    #pragma unroll
    for (int i = 0; i < 8; i++) {
        int lr = (i < 4) ? (ty * 4 + i) : (64 + ty * 4 + (i - 4));
        int gr = rowBase + lr;
        if (gr >= NN) continue;
        st4(Y + (size_t)gr * 64 + tx * 4, make_float4(acc[i][0], acc[i][1], acc[i][2], acc[i][3]));
    }
}

// ---------------- orchestration (pure kernel launches) ----------------
extern "C" void kernel_launch(void* const* d_in, const int* in_sizes, int n_in,
                              void* d_out, int out_size) {
    (void)in_sizes; (void)n_in; (void)out_size;
    const float* x  = (const float*)d_in[0];
    const int* ei   = (const int*)d_in[1];
    const int* et   = (const int*)d_in[2];
    const float* W0 = (const float*)d_in[3];
    const float* as0 = (const float*)d_in[4];
    const float* ad0 = (const float*)d_in[5];
    const float* ar0 = (const float*)d_in[6];
    const float* bi0 = (const float*)d_in[7];
    const float* W1 = (const float*)d_in[8];
    const float* as1 = (const float*)d_in[9];
    const float* ad1 = (const float*)d_in[10];
    const float* ar1 = (const float*)d_in[11];
    const float* bi1 = (const float*)d_in[12];
    const float* W2 = (const float*)d_in[13];
    const float* as2 = (const float*)d_in[14];
    const float* ad2 = (const float*)d_in[15];
    const float* ar2 = (const float*)d_in[16];
    const float* bi2 = (const float*)d_in[17];
    const float* g0 = (const float*)d_in[18];
    const float* be0 = (const float*)d_in[19];
    const float* g1 = (const float*)d_in[20];
    const float* be1 = (const float*)d_in[21];
    float* out = (float*)d_out;

    const int TB = 256;
    const int NT = (NN + 127) / 128;
    const int NB = (NN + 255) / 256;
    dim3 gTC2(NT, 16, 1);      // NTOT=2048
    dim3 gTC1(NT, 4, 1);       // NTOT=512
    int ge = (NE + TB - 1) / TB;
    int gwn = (NN * 32 + TB - 1) / TB;

    // ---- build dst-CSR once ----
    zero_deg_kernel<<<NB, TB>>>();
    hist_kernel<<<ge, TB>>>(ei);
    scan1_kernel<<<NB, TB>>>();
    scan2_kernel<<<1, TB>>>(NB);
    scan3_kernel<<<NB, TB>>>();
    scatter_kernel<<<ge, TB>>>(ei, et);

    // ======== layer 0: in=128 -> [8 rel] x 256, H=4 ========
    conv_w_t<128, 256><<<(128 * 2048 / 4 + TB - 1) / TB, TB>>>(W0);
    conv_x_kernel<<<(NN * 128 / 4 + TB - 1) / TB, TB>>>(x, NN * 128 / 4);
    prep_ws_kernel<4, 64><<<(128 * 64 + TB - 1) / TB, TB>>>(W0, as0, ad0, 128);
    gemm_dots<64, 0><<<NT, TB>>>(x, 128);
    mma_gemm<256, 128><<<gTC2, TB>>>();
    agg_ln_csr<<<gwn, TB>>>(ar0, bi0, g0, be0);

    // ======== layer 1: in=256 -> [8 rel] x 256, H=4 ========
    conv_w_t<256, 256><<<(256 * 2048 / 4 + TB - 1) / TB, TB>>>(W1);
    prep_ws_kernel<4, 64><<<(256 * 64 + TB - 1) / TB, TB>>>(W1, as1, ad1, 256);
    gemm_dots<64, 1><<<NT, TB>>>(nullptr, 256);
    mma_gemm<256, 256><<<gTC2, TB>>>();
    agg_ln_csr<<<gwn, TB>>>(ar1, bi1, g1, be1);

    // ======== layer 2: in=256 -> [8 rel] x 64, H=1, no concat ========
    conv_w_t<256, 64><<<(256 * 512 / 4 + TB - 1) / TB, TB>>>(W2);
    prep_ws_kernel<1, 64><<<(256 * 64 + TB - 1) / TB, TB>>>(W2, as2, ad2, 256);
    gemm_dots<64, 1><<<NT, TB>>>(nullptr, 256);
    mma_gemm<64, 256><<<gTC1, TB>>>();
    agg_out_csr<<<gwn, TB>>>(ar2, bi2, out);
}

// round 13
// speedup vs baseline: 1.9670x; 1.0542x over previous
#include <cuda_runtime.h>
#include <cuda_bf16.h>
#include <cuda_fp16.h>
#include <cstdint>

#define NN 50000
#define NE 800000
#define NR 8

// ---------------- scratch (device globals; no allocs allowed) ----------------
__device__ __align__(16) __half g_xw[(size_t)NN * 2048];      // per-rel transforms (fp16)
__device__ __align__(16) float g_sd[NN * 64];                 // attention dots
__device__ __align__(16) float g_h[(size_t)NN * 256];
__device__ __align__(16) float g_ws[256 * 64];
__device__ __align__(16) __nv_bfloat16 g_xh[(size_t)NN * 256];  // A operand hi
__device__ __align__(16) __nv_bfloat16 g_xl[(size_t)NN * 256];  // A operand lo
__device__ __align__(16) __nv_bfloat16 g_wh[256 * 2048];        // B hi, [K][8*M] transposed-concat
__device__ __align__(16) __nv_bfloat16 g_wl[256 * 2048];        // B lo
// CSR by destination (built once per launch)
__device__ int g_deg[NN];
__device__ int g_off[NN + 1];
__device__ int g_pos[NN];
__device__ int g_bsum[256];
__device__ int g_esr[NE];     // (src<<3)|rel, grouped by dst

__device__ __forceinline__ float4 ld4(const float* p) { return *reinterpret_cast<const float4*>(p); }
__device__ __forceinline__ void st4(float* p, float4 v) { *reinterpret_cast<float4*>(p) = v; }

__device__ __forceinline__ uint32_t smem_u32(const void* p) {
    uint32_t a;
    asm("{ .reg .u64 t; cvta.to.shared.u64 t, %1; cvt.u32.u64 %0, t; }" : "=r"(a) : "l"(p));
    return a;
}

// load 4 halves -> float4
__device__ __forceinline__ float4 ldh4(const __half* p) {
    uint2 u = *reinterpret_cast<const uint2*>(p);
    __half2 h0 = *reinterpret_cast<__half2*>(&u.x);
    __half2 h1 = *reinterpret_cast<__half2*>(&u.y);
    float2 f0 = __half22float2(h0);
    float2 f1 = __half22float2(h1);
    return make_float4(f0.x, f0.y, f1.x, f1.y);
}

// fp32 pair -> bf16 hi pair + bf16 lo (residual) pair, packed as u32
__device__ __forceinline__ void split2(float x, float y, unsigned& hi, unsigned& lo) {
    __nv_bfloat16 hx = __float2bfloat16(x), hy = __float2bfloat16(y);
    float rx = x - __bfloat162float(hx), ry = y - __bfloat162float(hy);
    __nv_bfloat162 h; h.x = hx; h.y = hy;
    __nv_bfloat162 l = __floats2bfloat162_rn(rx, ry);
    hi = *reinterpret_cast<unsigned*>(&h);
    lo = *reinterpret_cast<unsigned*>(&l);
}

__device__ __forceinline__ void ldsm_x4(uint32_t addr, uint32_t& r0, uint32_t& r1, uint32_t& r2, uint32_t& r3) {
    asm volatile("ldmatrix.sync.aligned.m8n8.x4.shared.b16 {%0,%1,%2,%3}, [%4];"
                 : "=r"(r0), "=r"(r1), "=r"(r2), "=r"(r3) : "r"(addr));
}
__device__ __forceinline__ void ldsm_x4t(uint32_t addr, uint32_t& r0, uint32_t& r1, uint32_t& r2, uint32_t& r3) {
    asm volatile("ldmatrix.sync.aligned.m8n8.x4.trans.shared.b16 {%0,%1,%2,%3}, [%4];"
                 : "=r"(r0), "=r"(r1), "=r"(r2), "=r"(r3) : "r"(addr));
}
__device__ __forceinline__ void mma_bf16(float* d, const uint32_t* a, uint32_t b0, uint32_t b1) {
    asm volatile("mma.sync.aligned.m16n8k16.row.col.f32.bf16.bf16.f32 "
                 "{%0,%1,%2,%3}, {%4,%5,%6,%7}, {%8,%9}, {%0,%1,%2,%3};"
                 : "+f"(d[0]), "+f"(d[1]), "+f"(d[2]), "+f"(d[3])
                 : "r"(a[0]), "r"(a[1]), "r"(a[2]), "r"(a[3]), "r"(b0), "r"(b1));
}

// ---------------- fp32 -> bf16 hi/lo converters ----------------
__global__ void conv_x_kernel(const float* __restrict__ X, int total4) {
    int i = blockIdx.x * blockDim.x + threadIdx.x;
    if (i >= total4) return;
    float4 v = ld4(X + (size_t)i * 4);
    unsigned h0, l0, h1, l1;
    split2(v.x, v.y, h0, l0);
    split2(v.z, v.w, h1, l1);
    *reinterpret_cast<uint2*>(g_xh + (size_t)i * 4) = make_uint2(h0, h1);
    *reinterpret_cast<uint2*>(g_xl + (size_t)i * 4) = make_uint2(l0, l1);
}
// W [R][K][M] -> transposed-concat [K][R*M] bf16 hi/lo
template<int K, int M>
__global__ void conv_w_t(const float* __restrict__ W) {
    int i = blockIdx.x * blockDim.x + threadIdx.x;
    constexpr int ROW4 = 8 * M / 4;
    if (i >= K * ROW4) return;
    int k = i / ROW4;
    int rest = i % ROW4;
    int z = rest / (M / 4);
    int m4 = rest % (M / 4);
    float4 v = ld4(W + ((size_t)z * K + k) * M + m4 * 4);
    unsigned h0, l0, h1, l1;
    split2(v.x, v.y, h0, l0);
    split2(v.z, v.w, h1, l1);
    *reinterpret_cast<uint2*>(g_wh + (size_t)i * 4) = make_uint2(h0, h1);
    *reinterpret_cast<uint2*>(g_wl + (size_t)i * 4) = make_uint2(l0, l1);
}

// ======== HMMA split-bf16 GEMM: g_xw[row][col] = X[row,:]·Wt[:,col] (fp16 out), NTOT = 8*MP ========
template<int MP, int KTOT>
__global__ void __launch_bounds__(256) mma_gemm() {
    constexpr int NTOT = 8 * MP;
    constexpr int BN = 128, WN = 64, NF2 = 4;
    constexpr int AST = 40;
    constexpr int BST = BN + 8;

    __shared__ __align__(16) __nv_bfloat16 Ah[128][AST];
    __shared__ __align__(16) __nv_bfloat16 Al[128][AST];
    __shared__ __align__(16) __nv_bfloat16 Bh[32][BST];
    __shared__ __align__(16) __nv_bfloat16 Bl[32][BST];

    const int tid = threadIdx.x;
    const int wid = tid >> 5, lane = tid & 31;
    const int wm = wid & 3, wn = wid >> 2;
    const int rowBase = blockIdx.x * 128;
    const int nbase = blockIdx.y * BN;

    float acc[2][8][4];
    #pragma unroll
    for (int i = 0; i < 2; i++)
        #pragma unroll
        for (int j = 0; j < 8; j++)
            #pragma unroll
            for (int q = 0; q < 4; q++) acc[i][j][q] = 0.f;

    for (int k0 = 0; k0 < KTOT; k0 += 32) {
        #pragma unroll
        for (int i = 0; i < 2; i++) {
            int li = tid + i * 256;
            int row = li >> 2, c8 = (li & 3) * 8;
            int gr = rowBase + row;
            uint4 vh = make_uint4(0, 0, 0, 0), vl = make_uint4(0, 0, 0, 0);
            if (gr < NN) {
                size_t goff = (size_t)gr * KTOT + k0 + c8;
                vh = *reinterpret_cast<const uint4*>(g_xh + goff);
                vl = *reinterpret_cast<const uint4*>(g_xl + goff);
            }
            *reinterpret_cast<uint4*>(&Ah[row][c8]) = vh;
            *reinterpret_cast<uint4*>(&Al[row][c8]) = vl;
        }
        #pragma unroll
        for (int i = 0; i < 2; i++) {
            int li = tid + i * 256;
            int row = li >> 4, c8 = (li & 15) * 8;
            size_t goff = (size_t)(k0 + row) * NTOT + nbase + c8;
            *reinterpret_cast<uint4*>(&Bh[row][c8]) = *reinterpret_cast<const uint4*>(g_wh + goff);
            *reinterpret_cast<uint4*>(&Bl[row][c8]) = *reinterpret_cast<const uint4*>(g_wl + goff);
        }
        __syncthreads();
        #pragma unroll
        for (int ks = 0; ks < 2; ks++) {
            uint32_t ah[2][4], al[2][4];
            #pragma unroll
            for (int mf = 0; mf < 2; mf++) {
                int arow = wm * 32 + mf * 16 + (lane & 15);
                int acol = ks * 16 + ((lane >> 4) << 3);
                ldsm_x4(smem_u32(&Ah[arow][acol]), ah[mf][0], ah[mf][1], ah[mf][2], ah[mf][3]);
                ldsm_x4(smem_u32(&Al[arow][acol]), al[mf][0], al[mf][1], al[mf][2], al[mf][3]);
            }
            #pragma unroll
            for (int nf2 = 0; nf2 < NF2; nf2++) {
                int brow = ks * 16 + (lane & 15);
                int bcol = wn * WN + nf2 * 16 + ((lane >> 4) << 3);
                uint32_t bh[4], bl[4];
                ldsm_x4t(smem_u32(&Bh[brow][bcol]), bh[0], bh[1], bh[2], bh[3]);
                ldsm_x4t(smem_u32(&Bl[brow][bcol]), bl[0], bl[1], bl[2], bl[3]);
                #pragma unroll
                for (int half = 0; half < 2; half++) {
                    uint32_t bH0 = bh[half * 2], bH1 = bh[half * 2 + 1];
                    uint32_t bL0 = bl[half * 2], bL1 = bl[half * 2 + 1];
                    #pragma unroll
                    for (int mf = 0; mf < 2; mf++) {
                        float* d = acc[mf][nf2 * 2 + half];
                        mma_bf16(d, ah[mf], bH0, bH1);
                        mma_bf16(d, ah[mf], bL0, bL1);
                        mma_bf16(d, al[mf], bH0, bH1);
                    }
                }
            }
        }
        __syncthreads();
    }
    const int colG = nbase + wn * WN + (lane & 3) * 2;
    #pragma unroll
    for (int mf = 0; mf < 2; mf++) {
        int r0 = rowBase + wm * 32 + mf * 16 + (lane >> 2);
        #pragma unroll
        for (int nf = 0; nf < 8; nf++) {
            float* d = acc[mf][nf];
            int c = colG + nf * 8;
            if (r0 < NN)
                *reinterpret_cast<__half2*>(g_xw + (size_t)r0 * NTOT + c) = __floats2half2_rn(d[0], d[1]);
            if (r0 + 8 < NN)
                *reinterpret_cast<__half2*>(g_xw + (size_t)(r0 + 8) * NTOT + c) = __floats2half2_rn(d[2], d[3]);
        }
    }
}

// ---------------- CSR build (once per launch) ----------------
__global__ void zero_deg_kernel() {
    int i = blockIdx.x * blockDim.x + threadIdx.x;
    if (i < NN) g_deg[i] = 0;
}
__global__ void hist_kernel(const int* __restrict__ ei) {
    int e = blockIdx.x * blockDim.x + threadIdx.x;
    if (e < NE) atomicAdd(&g_deg[ei[NE + e]], 1);
}
__device__ __forceinline__ int blk_excl_scan(int v, int tid, int* wsum) {
    int lane = tid & 31, w = tid >> 5;
    int x = v;
    #pragma unroll
    for (int o = 1; o < 32; o <<= 1) { int t = __shfl_up_sync(~0u, x, o); if (lane >= o) x += t; }
    if (lane == 31) wsum[w] = x;
    __syncthreads();
    if (w == 0) {
        int s = (lane < 8) ? wsum[lane] : 0;
        #pragma unroll
        for (int o = 1; o < 8; o <<= 1) { int t = __shfl_up_sync(~0u, s, o); if (lane >= o) s += t; }
        if (lane < 8) wsum[lane] = s;
    }
    __syncthreads();
    int incl = x + (w > 0 ? wsum[w - 1] : 0);
    return incl - v;
}
__global__ void scan1_kernel() {
    __shared__ int wsum[8];
    int i = blockIdx.x * 256 + threadIdx.x;
    int v = (i < NN) ? g_deg[i] : 0;
    int excl = blk_excl_scan(v, threadIdx.x, wsum);
    if (i < NN) g_off[i] = excl;
    if (threadIdx.x == 255) g_bsum[blockIdx.x] = excl + v;
}
__global__ void scan2_kernel(int nb) {
    __shared__ int wsum[8];
    int t = threadIdx.x;
    int v = (t < nb) ? g_bsum[t] : 0;
    int excl = blk_excl_scan(v, t, wsum);
    if (t < nb) g_bsum[t] = excl;
}
__global__ void scan3_kernel() {
    int i = blockIdx.x * 256 + threadIdx.x;
    if (i < NN) {
        int f = g_off[i] + g_bsum[blockIdx.x];
        g_off[i] = f;
        g_pos[i] = f;
    }
    if (i == 0) g_off[NN] = NE;
}
__global__ void scatter_kernel(const int* __restrict__ ei, const int* __restrict__ et) {
    int e = blockIdx.x * blockDim.x + threadIdx.x;
    if (e >= NE) return;
    int dst = ei[NE + e];
    int p = atomicAdd(&g_pos[dst], 1);
    g_esr[p] = (ei[e] << 3) | et[e];
}

// ---------------- fused softmax+aggregation+bias+LN+ELU+bf16 export (warp per dst; H=4, M=256) ----------------
__global__ void agg_ln_csr(const float* __restrict__ arel, const float* __restrict__ bias,
                           const float* __restrict__ gam, const float* __restrict__ bet) {
    int n = (blockIdx.x * blockDim.x + threadIdx.x) >> 5;
    int lane = threadIdx.x & 31;
    if (n >= NN) return;
    int start = g_off[n], end = g_off[n + 1];
    int c0 = lane * 4, c1 = 128 + lane * 4;
    float4 a0 = make_float4(0.f, 0.f, 0.f, 0.f);
    float4 a1 = make_float4(0.f, 0.f, 0.f, 0.f);
    float4 den = make_float4(0.f, 0.f, 0.f, 0.f);
    for (int base = start; base < end; base += 32) {
        int p = base + lane;
        float4 ex = make_float4(0.f, 0.f, 0.f, 0.f);
        int sr = 0;
        if (p < end) {
            sr = g_esr[p];
            int src = sr >> 3, r = sr & 7;
            float4 s = ld4(g_sd + src * 64 + r * 4);
            float4 d = ld4(g_sd + n * 64 + 32 + r * 4);
            float4 a = ld4(arel + r * 4);
            float4 v;
            v.x = s.x + d.x + a.x; v.y = s.y + d.y + a.y;
            v.z = s.z + d.z + a.z; v.w = s.w + d.w + a.w;
            v.x = v.x > 0.f ? v.x : 0.2f * v.x;
            v.y = v.y > 0.f ? v.y : 0.2f * v.y;
            v.z = v.z > 0.f ? v.z : 0.2f * v.z;
            v.w = v.w > 0.f ? v.w : 0.2f * v.w;
            ex = make_float4(expf(v.x), expf(v.y), expf(v.z), expf(v.w));
        }
        den.x += ex.x; den.y += ex.y; den.z += ex.z; den.w += ex.w;
        int cnt = min(32, end - base);
        for (int j = 0; j < cnt; j++) {
            int srj = __shfl_sync(~0u, sr, j);
            float e0 = __shfl_sync(~0u, ex.x, j);
            float e1 = __shfl_sync(~0u, ex.y, j);
            float e2 = __shfl_sync(~0u, ex.z, j);
            float e3 = __shfl_sync(~0u, ex.w, j);
            float sA = (lane < 16) ? e0 : e1;
            float sB = (lane < 16) ? e2 : e3;
            const __half* xp = g_xw + (size_t)(srj >> 3) * 2048 + (srj & 7) * 256;
            float4 v0 = ldh4(xp + c0), v1 = ldh4(xp + c1);
            a0.x += v0.x * sA; a0.y += v0.y * sA; a0.z += v0.z * sA; a0.w += v0.w * sA;
            a1.x += v1.x * sB; a1.y += v1.y * sB; a1.z += v1.z * sB; a1.w += v1.w * sB;
        }
    }
    #pragma unroll
    for (int o = 16; o; o >>= 1) {
        den.x += __shfl_xor_sync(~0u, den.x, o);
        den.y += __shfl_xor_sync(~0u, den.y, o);
        den.z += __shfl_xor_sync(~0u, den.z, o);
        den.w += __shfl_xor_sync(~0u, den.w, o);
    }
    float dA = (lane < 16) ? den.x : den.y;
    float dB = (lane < 16) ? den.z : den.w;
    float iA = dA > 0.f ? 1.f / dA : 0.f;
    float iB = dB > 0.f ? 1.f / dB : 0.f;
    a0.x *= iA; a0.y *= iA; a0.z *= iA; a0.w *= iA;
    a1.x *= iB; a1.y *= iB; a1.z *= iB; a1.w *= iB;
    float4 b0 = ld4(bias + c0), b1 = ld4(bias + c1);
    a0.x += b0.x; a0.y += b0.y; a0.z += b0.z; a0.w += b0.w;
    a1.x += b1.x; a1.y += b1.y; a1.z += b1.z; a1.w += b1.w;
    float sum = a0.x + a0.y + a0.z + a0.w + a1.x + a1.y + a1.z + a1.w;
    float sq = a0.x * a0.x + a0.y * a0.y + a0.z * a0.z + a0.w * a0.w
             + a1.x * a1.x + a1.y * a1.y + a1.z * a1.z + a1.w * a1.w;
    #pragma unroll
    for (int o = 16; o; o >>= 1) {
        sum += __shfl_xor_sync(0xffffffffu, sum, o);
        sq  += __shfl_xor_sync(0xffffffffu, sq, o);
    }
    float mean = sum * (1.f / 256.f);
    float var = sq * (1.f / 256.f) - mean * mean;
    float rstd = rsqrtf(var + 1e-5f);
    float4 g0 = ld4(gam + c0), g1 = ld4(gam + c1);
    float4 e0v = ld4(bet + c0), e1v = ld4(bet + c1);
    float4 y0, y1;
    y0.x = (a0.x - mean) * rstd * g0.x + e0v.x;
    y0.y = (a0.y - mean) * rstd * g0.y + e0v.y;
    y0.z = (a0.z - mean) * rstd * g0.z + e0v.z;
    y0.w = (a0.w - mean) * rstd * g0.w + e0v.w;
    y1.x = (a1.x - mean) * rstd * g1.x + e1v.x;
    y1.y = (a1.y - mean) * rstd * g1.y + e1v.y;
    y1.z = (a1.z - mean) * rstd * g1.z + e1v.z;
    y1.w = (a1.w - mean) * rstd * g1.w + e1v.w;
    y0.x = y0.x > 0.f ? y0.x : expm1f(y0.x);
    y0.y = y0.y > 0.f ? y0.y : expm1f(y0.y);
    y0.z = y0.z > 0.f ? y0.z : expm1f(y0.z);
    y0.w = y0.w > 0.f ? y0.w : expm1f(y0.w);
    y1.x = y1.x > 0.f ? y1.x : expm1f(y1.x);
    y1.y = y1.y > 0.f ? y1.y : expm1f(y1.y);
    y1.z = y1.z > 0.f ? y1.z : expm1f(y1.z);
    y1.w = y1.w > 0.f ? y1.w : expm1f(y1.w);
    float* hp = g_h + (size_t)n * 256;
    st4(hp + c0, y0);
    st4(hp + c1, y1);
    unsigned h0, l0, h1, l1;
    split2(y0.x, y0.y, h0, l0);
    split2(y0.z, y0.w, h1, l1);
    *reinterpret_cast<uint2*>(g_xh + (size_t)n * 256 + c0) = make_uint2(h0, h1);
    *reinterpret_cast<uint2*>(g_xl + (size_t)n * 256 + c0) = make_uint2(l0, l1);
    split2(y1.x, y1.y, h0, l0);
    split2(y1.z, y1.w, h1, l1);
    *reinterpret_cast<uint2*>(g_xh + (size_t)n * 256 + c1) = make_uint2(h0, h1);
    *reinterpret_cast<uint2*>(g_xl + (size_t)n * 256 + c1) = make_uint2(l0, l1);
}

// ---------------- fused softmax+aggregation layer 2 (warp per dst; H=1, M=64) + bias -> out ----------------
// Broadcast loop is warp-uniform; accumulation predicated by (j&1)==half.
__global__ void agg_out_csr(const float* __restrict__ arel, const float* __restrict__ bi,
                            float* __restrict__ out) {
    int n = (blockIdx.x * blockDim.x + threadIdx.x) >> 5;
    int lane = threadIdx.x & 31;
    if (n >= NN) return;
    int start = g_off[n], end = g_off[n + 1];
    int half = lane >> 4;
    int c = (lane & 15) * 4;
    float4 acc = make_float4(0.f, 0.f, 0.f, 0.f);
    float den = 0.f;
    for (int base = start; base < end; base += 32) {
        int p = base + lane;
        float ex = 0.f;
        int sr = 0;
        if (p < end) {
            sr = g_esr[p];
            int src = sr >> 3, r = sr & 7;
            float v = g_sd[src * 64 + r] + g_sd[n * 64 + 8 + r] + arel[r];
            v = v > 0.f ? v : 0.2f * v;
            ex = expf(v);
        }
        den += ex;
        int cnt = min(32, end - base);
        for (int j = 0; j < cnt; j++) {
            int srj = __shfl_sync(~0u, sr, j);
            float exj = __shfl_sync(~0u, ex, j);
            if ((j & 1) == half) {
                const __half* xp = g_xw + (size_t)(srj >> 3) * 512 + (srj & 7) * 64;
                float4 v = ldh4(xp + c);
                acc.x += v.x * exj; acc.y += v.y * exj; acc.z += v.z * exj; acc.w += v.w * exj;
            }
        }
    }
    #pragma unroll
    for (int o = 16; o; o >>= 1) den += __shfl_xor_sync(~0u, den, o);
    acc.x += __shfl_xor_sync(~0u, acc.x, 16);
    acc.y += __shfl_xor_sync(~0u, acc.y, 16);
    acc.z += __shfl_xor_sync(~0u, acc.z, 16);
    acc.w += __shfl_xor_sync(~0u, acc.w, 16);
    if (half == 0) {
        float inv = den > 0.f ? 1.f / den : 0.f;
        float4 b = ld4(bi + c);
        acc.x = acc.x * inv + b.x;
        acc.y = acc.y * inv + b.y;
        acc.z = acc.z * inv + b.z;
        acc.w = acc.w * inv + b.w;
        st4(out + (size_t)n * 64 + c, acc);
    }
}

// ---------------- ws[k][col] = sum_c W[r][k][h*C+c] * a_{src|dst}[h][c] ----------------
template<int H, int C>
__global__ void prep_ws_kernel(const float* __restrict__ W, const float* __restrict__ a_src,
                               const float* __restrict__ a_dst, int K) {
    int idx = blockIdx.x * blockDim.x + threadIdx.x;
    if (idx >= K * 64) return;
    int k = idx >> 6;
    int col = idx & 63;
    constexpr int RH = NR * H;
    float acc = 0.f;
    if (col < 2 * RH) {
        int isd = col >= RH;
        int rh = isd ? col - RH : col;
        int r = rh / H, h = rh % H;
        const float* a = isd ? a_dst : a_src;
        const float* wrow = W + ((size_t)r * K + k) * (H * C) + h * C;
        #pragma unroll 8
        for (int c = 0; c < C; c++) acc += wrow[c] * a[h * C + c];
    }
    g_ws[idx] = acc;
}

// ---------------- fp32 SGEMM (attention dots only): g_sd = X @ g_ws ----------------
template<int BN, int XH>
__global__ void __launch_bounds__(256) gemm_dots(const float* __restrict__ Xp, int K) {
    constexpr int BM = 128, BK = 16;
    constexpr int TN = BN / 16;
    const float* X = XH ? (const float*)g_h : Xp;
    const float* W = (const float*)g_ws;
    float* Y = (float*)g_sd;
    __shared__ float As[BK][BM];
    __shared__ float Bs[BK][BN];
    const int tid = threadIdx.x;
    const int tx = tid & 15, ty = tid >> 4;
    const int rowBase = blockIdx.x * BM;

    float acc[8][TN];
    #pragma unroll
    for (int i = 0; i < 8; i++)
        #pragma unroll
        for (int j = 0; j < TN; j++) acc[i][j] = 0.f;

    for (int k0 = 0; k0 < K; k0 += BK) {
        #pragma unroll
        for (int i = 0; i < 2; i++) {
            int idx = tid + i * 256;
            int ar = idx >> 2;
            int ac = (idx & 3) << 2;
            int gr = rowBase + ar;
            float4 v = make_float4(0.f, 0.f, 0.f, 0.f);
            if (gr < NN) v = ld4(X + (size_t)gr * K + k0 + ac);
            As[ac + 0][ar] = v.x; As[ac + 1][ar] = v.y;
            As[ac + 2][ar] = v.z; As[ac + 3][ar] = v.w;
        }
        if (tid < BK * BN / 4) {
            int br = tid / (BN / 4);
            int bc = (tid % (BN / 4)) << 2;
            st4(&Bs[br][bc], ld4(W + (size_t)(k0 + br) * 64 + bc));
        }
        __syncthreads();
        #pragma unroll
        for (int kk = 0; kk < BK; kk++) {
            float av[8], bv[TN];
            float4 a0 = *reinterpret_cast<const float4*>(&As[kk][ty * 4]);
            float4 a1 = *reinterpret_cast<const float4*>(&As[kk][64 + ty * 4]);
            av[0] = a0.x; av[1] = a0.y; av[2] = a0.z; av[3] = a0.w;
            av[4] = a1.x; av[5] = a1.y; av[6] = a1.z; av[7] = a1.w;
            float4 b0 = *reinterpret_cast<const float4*>(&Bs[kk][tx * 4]);
            bv[0] = b0.x; bv[1] = b0.y; bv[2] = b0.z; bv[3] = b0.w;
            #pragma unroll
            for (int i = 0; i < 8; i++)
                #pragma unroll
                for (int j = 0; j < TN; j++) acc[i][j] = fmaf(av[i], bv[j], acc[i][j]);
        }
        __syncthreads();
    }
    #pragma unroll
    for (int i = 0; i < 8; i++) {
        int lr = (i < 4) ? (ty * 4 + i) : (64 + ty * 4 + (i - 4));
        int gr = rowBase + lr;
        if (gr >= NN) continue;
        st4(Y + (size_t)gr * 64 + tx * 4, make_float4(acc[i][0], acc[i][1], acc[i][2], acc[i][3]));
    }
}

// ---------------- orchestration (pure kernel launches) ----------------
extern "C" void kernel_launch(void* const* d_in, const int* in_sizes, int n_in,
                              void* d_out, int out_size) {
    (void)in_sizes; (void)n_in; (void)out_size;
    const float* x  = (const float*)d_in[0];
    const int* ei   = (const int*)d_in[1];
    const int* et   = (const int*)d_in[2];
    const float* W0 = (const float*)d_in[3];
    const float* as0 = (const float*)d_in[4];
    const float* ad0 = (const float*)d_in[5];
    const float* ar0 = (const float*)d_in[6];
    const float* bi0 = (const float*)d_in[7];
    const float* W1 = (const float*)d_in[8];
    const float* as1 = (const float*)d_in[9];
    const float* ad1 = (const float*)d_in[10];
    const float* ar1 = (const float*)d_in[11];
    const float* bi1 = (const float*)d_in[12];
    const float* W2 = (const float*)d_in[13];
    const float* as2 = (const float*)d_in[14];
    const float* ad2 = (const float*)d_in[15];
    const float* ar2 = (const float*)d_in[16];
    const float* bi2 = (const float*)d_in[17];
    const float* g0 = (const float*)d_in[18];
    const float* be0 = (const float*)d_in[19];
    const float* g1 = (const float*)d_in[20];
    const float* be1 = (const float*)d_in[21];
    float* out = (float*)d_out;

    const int TB = 256;
    const int NT = (NN + 127) / 128;
    const int NB = (NN + 255) / 256;
    dim3 gTC2(NT, 16, 1);      // NTOT=2048
    dim3 gTC1(NT, 4, 1);       // NTOT=512
    int ge = (NE + TB - 1) / TB;
    int gwn = (NN * 32 + TB - 1) / TB;

    // ---- build dst-CSR once ----
    zero_deg_kernel<<<NB, TB>>>();
    hist_kernel<<<ge, TB>>>(ei);
    scan1_kernel<<<NB, TB>>>();
    scan2_kernel<<<1, TB>>>(NB);
    scan3_kernel<<<NB, TB>>>();
    scatter_kernel<<<ge, TB>>>(ei, et);

    // ======== layer 0: in=128 -> [8 rel] x 256, H=4 ========
    conv_w_t<128, 256><<<(128 * 2048 / 4 + TB - 1) / TB, TB>>>(W0);
    conv_x_kernel<<<(NN * 128 / 4 + TB - 1) / TB, TB>>>(x, NN * 128 / 4);
    prep_ws_kernel<4, 64><<<(128 * 64 + TB - 1) / TB, TB>>>(W0, as0, ad0, 128);
    gemm_dots<64, 0><<<NT, TB>>>(x, 128);
    mma_gemm<256, 128><<<gTC2, TB>>>();
    agg_ln_csr<<<gwn, TB>>>(ar0, bi0, g0, be0);

    // ======== layer 1: in=256 -> [8 rel] x 256, H=4 ========
    conv_w_t<256, 256><<<(256 * 2048 / 4 + TB - 1) / TB, TB>>>(W1);
    prep_ws_kernel<4, 64><<<(256 * 64 + TB - 1) / TB, TB>>>(W1, as1, ad1, 256);
    gemm_dots<64, 1><<<NT, TB>>>(nullptr, 256);
    mma_gemm<256, 256><<<gTC2, TB>>>();
    agg_ln_csr<<<gwn, TB>>>(ar1, bi1, g1, be1);

    // ======== layer 2: in=256 -> [8 rel] x 64, H=1, no concat ========
    conv_w_t<256, 64><<<(256 * 512 / 4 + TB - 1) / TB, TB>>>(W2);
    prep_ws_kernel<1, 64><<<(256 * 64 + TB - 1) / TB, TB>>>(W2, as2, ad2, 256);
    gemm_dots<64, 1><<<NT, TB>>>(nullptr, 256);
    mma_gemm<64, 256><<<gTC1, TB>>>();
    agg_out_csr<<<gwn, TB>>>(ar2, bi2, out);
}

// round 14
// speedup vs baseline: 2.0663x; 1.0505x over previous
#include <cuda_runtime.h>
#include <cuda_bf16.h>
#include <cuda_fp16.h>
#include <cstdint>

#define NN 50000
#define NE 800000
#define NR 8

// ---------------- scratch (device globals; no allocs allowed) ----------------
__device__ __align__(16) __half g_xw[(size_t)NN * 2048];      // per-rel transforms (fp16)
__device__ __align__(16) float g_sd[NN * 64];                 // attention dots
__device__ __align__(16) float g_h[(size_t)NN * 256];
__device__ __align__(16) __nv_bfloat16 g_xh[(size_t)NN * 256];  // A operand hi
__device__ __align__(16) __nv_bfloat16 g_xl[(size_t)NN * 256];  // A operand lo
__device__ __align__(16) __nv_bfloat16 g_wh[256 * 2176];        // B hi, [K][NTOTP] transposed-concat + ws pad
__device__ __align__(16) __nv_bfloat16 g_wl[256 * 2176];        // B lo
// CSR by destination (built once per launch)
__device__ int g_deg[NN];
__device__ int g_off[NN + 1];
__device__ int g_pos[NN];
__device__ int g_bsum[256];
__device__ int g_esr[NE];     // (src<<3)|rel, grouped by dst

__device__ __forceinline__ float4 ld4(const float* p) { return *reinterpret_cast<const float4*>(p); }
__device__ __forceinline__ void st4(float* p, float4 v) { *reinterpret_cast<float4*>(p) = v; }

__device__ __forceinline__ uint32_t smem_u32(const void* p) {
    uint32_t a;
    asm("{ .reg .u64 t; cvta.to.shared.u64 t, %1; cvt.u32.u64 %0, t; }" : "=r"(a) : "l"(p));
    return a;
}

// load 4 halves -> float4
__device__ __forceinline__ float4 ldh4(const __half* p) {
    uint2 u = *reinterpret_cast<const uint2*>(p);
    __half2 h0 = *reinterpret_cast<__half2*>(&u.x);
    __half2 h1 = *reinterpret_cast<__half2*>(&u.y);
    float2 f0 = __half22float2(h0);
    float2 f1 = __half22float2(h1);
    return make_float4(f0.x, f0.y, f1.x, f1.y);
}

// fp32 pair -> bf16 hi pair + bf16 lo (residual) pair, packed as u32
__device__ __forceinline__ void split2(float x, float y, unsigned& hi, unsigned& lo) {
    __nv_bfloat16 hx = __float2bfloat16(x), hy = __float2bfloat16(y);
    float rx = x - __bfloat162float(hx), ry = y - __bfloat162float(hy);
    __nv_bfloat162 h; h.x = hx; h.y = hy;
    __nv_bfloat162 l = __floats2bfloat162_rn(rx, ry);
    hi = *reinterpret_cast<unsigned*>(&h);
    lo = *reinterpret_cast<unsigned*>(&l);
}

__device__ __forceinline__ void ldsm_x4(uint32_t addr, uint32_t& r0, uint32_t& r1, uint32_t& r2, uint32_t& r3) {
    asm volatile("ldmatrix.sync.aligned.m8n8.x4.shared.b16 {%0,%1,%2,%3}, [%4];"
                 : "=r"(r0), "=r"(r1), "=r"(r2), "=r"(r3) : "r"(addr));
}
__device__ __forceinline__ void ldsm_x4t(uint32_t addr, uint32_t& r0, uint32_t& r1, uint32_t& r2, uint32_t& r3) {
    asm volatile("ldmatrix.sync.aligned.m8n8.x4.trans.shared.b16 {%0,%1,%2,%3}, [%4];"
                 : "=r"(r0), "=r"(r1), "=r"(r2), "=r"(r3) : "r"(addr));
}
__device__ __forceinline__ void mma_bf16(float* d, const uint32_t* a, uint32_t b0, uint32_t b1) {
    asm volatile("mma.sync.aligned.m16n8k16.row.col.f32.bf16.bf16.f32 "
                 "{%0,%1,%2,%3}, {%4,%5,%6,%7}, {%8,%9}, {%0,%1,%2,%3};"
                 : "+f"(d[0]), "+f"(d[1]), "+f"(d[2]), "+f"(d[3])
                 : "r"(a[0]), "r"(a[1]), "r"(a[2]), "r"(a[3]), "r"(b0), "r"(b1));
}

// ---------------- fp32 -> bf16 hi/lo converters ----------------
__global__ void conv_x_kernel(const float* __restrict__ X, int total4) {
    int i = blockIdx.x * blockDim.x + threadIdx.x;
    if (i >= total4) return;
    float4 v = ld4(X + (size_t)i * 4);
    unsigned h0, l0, h1, l1;
    split2(v.x, v.y, h0, l0);
    split2(v.z, v.w, h1, l1);
    *reinterpret_cast<uint2*>(g_xh + (size_t)i * 4) = make_uint2(h0, h1);
    *reinterpret_cast<uint2*>(g_xl + (size_t)i * 4) = make_uint2(l0, l1);
}
// W [R][K][M] -> transposed-concat [K][NTOTP] bf16 hi/lo (cols [0, 8*M))
template<int K, int M, int NTOTP>
__global__ void conv_w_t(const float* __restrict__ W) {
    int i = blockIdx.x * blockDim.x + threadIdx.x;
    constexpr int ROW4 = 8 * M / 4;
    if (i >= K * ROW4) return;
    int k = i / ROW4;
    int rest = i % ROW4;
    int z = rest / (M / 4);
    int m4 = rest % (M / 4);
    float4 v = ld4(W + ((size_t)z * K + k) * M + m4 * 4);
    unsigned h0, l0, h1, l1;
    split2(v.x, v.y, h0, l0);
    split2(v.z, v.w, h1, l1);
    size_t o = (size_t)k * NTOTP + z * M + m4 * 4;
    *reinterpret_cast<uint2*>(g_wh + o) = make_uint2(h0, h1);
    *reinterpret_cast<uint2*>(g_wl + o) = make_uint2(l0, l1);
}
// Fold attention-vector weights into pad cols [PADBASE, PADBASE+64) of g_wh/g_wl.
// ws[k][col] = sum_c W[r][k][h*C+c] * a_{src|dst}[h][c]; col layout: [0,RH) src, [RH,2RH) dst, rest 0.
template<int H, int C, int NTOTP, int PADBASE>
__global__ void prep_ws2(const float* __restrict__ W, const float* __restrict__ a_src,
                         const float* __restrict__ a_dst, int K) {
    int idx = blockIdx.x * blockDim.x + threadIdx.x;
    if (idx >= K * 32) return;
    int k = idx >> 5;
    int cp = idx & 31;
    constexpr int RH = NR * H;
    float acc[2];
    #pragma unroll
    for (int q = 0; q < 2; q++) {
        int col = cp * 2 + q;
        float a = 0.f;
        if (col < 2 * RH) {
            int isd = col >= RH;
            int rh = isd ? col - RH : col;
            int r = rh / H, h = rh % H;
            const float* av = isd ? a_dst : a_src;
            const float* wrow = W + ((size_t)r * K + k) * (H * C) + h * C;
            #pragma unroll 8
            for (int c = 0; c < C; c++) a += wrow[c] * av[h * C + c];
        }
        acc[q] = a;
    }
    unsigned hi, lo;
    split2(acc[0], acc[1], hi, lo);
    size_t o = (size_t)k * NTOTP + PADBASE + cp * 2;
    *reinterpret_cast<unsigned*>(g_wh + o) = hi;
    *reinterpret_cast<unsigned*>(g_wl + o) = lo;
}

// ======== HMMA split-bf16 GEMM with fused dots tile ========
// cols [0, NTOTR): fp16 -> g_xw (stride NTOTR); cols [NTOTR, NTOTR+64): fp32 -> g_sd.
template<int NTOTR, int NTOTP, int KTOT>
__global__ void __launch_bounds__(256) mma_gemm() {
    constexpr int BN = 128, WN = 64, NF2 = 4;
    constexpr int AST = 40;
    constexpr int BST = BN + 8;

    __shared__ __align__(16) __nv_bfloat16 Ah[128][AST];
    __shared__ __align__(16) __nv_bfloat16 Al[128][AST];
    __shared__ __align__(16) __nv_bfloat16 Bh[32][BST];
    __shared__ __align__(16) __nv_bfloat16 Bl[32][BST];

    const int tid = threadIdx.x;
    const int wid = tid >> 5, lane = tid & 31;
    const int wm = wid & 3, wn = wid >> 2;
    const int rowBase = blockIdx.x * 128;
    const int nbase = blockIdx.y * BN;

    float acc[2][8][4];
    #pragma unroll
    for (int i = 0; i < 2; i++)
        #pragma unroll
        for (int j = 0; j < 8; j++)
            #pragma unroll
            for (int q = 0; q < 4; q++) acc[i][j][q] = 0.f;

    for (int k0 = 0; k0 < KTOT; k0 += 32) {
        #pragma unroll
        for (int i = 0; i < 2; i++) {
            int li = tid + i * 256;
            int row = li >> 2, c8 = (li & 3) * 8;
            int gr = rowBase + row;
            uint4 vh = make_uint4(0, 0, 0, 0), vl = make_uint4(0, 0, 0, 0);
            if (gr < NN) {
                size_t goff = (size_t)gr * KTOT + k0 + c8;
                vh = *reinterpret_cast<const uint4*>(g_xh + goff);
                vl = *reinterpret_cast<const uint4*>(g_xl + goff);
            }
            *reinterpret_cast<uint4*>(&Ah[row][c8]) = vh;
            *reinterpret_cast<uint4*>(&Al[row][c8]) = vl;
        }
        #pragma unroll
        for (int i = 0; i < 2; i++) {
            int li = tid + i * 256;
            int row = li >> 4, c8 = (li & 15) * 8;
            size_t goff = (size_t)(k0 + row) * NTOTP + nbase + c8;
            *reinterpret_cast<uint4*>(&Bh[row][c8]) = *reinterpret_cast<const uint4*>(g_wh + goff);
            *reinterpret_cast<uint4*>(&Bl[row][c8]) = *reinterpret_cast<const uint4*>(g_wl + goff);
        }
        __syncthreads();
        #pragma unroll
        for (int ks = 0; ks < 2; ks++) {
            uint32_t ah[2][4], al[2][4];
            #pragma unroll
            for (int mf = 0; mf < 2; mf++) {
                int arow = wm * 32 + mf * 16 + (lane & 15);
                int acol = ks * 16 + ((lane >> 4) << 3);
                ldsm_x4(smem_u32(&Ah[arow][acol]), ah[mf][0], ah[mf][1], ah[mf][2], ah[mf][3]);
                ldsm_x4(smem_u32(&Al[arow][acol]), al[mf][0], al[mf][1], al[mf][2], al[mf][3]);
            }
            #pragma unroll
            for (int nf2 = 0; nf2 < NF2; nf2++) {
                int brow = ks * 16 + (lane & 15);
                int bcol = wn * WN + nf2 * 16 + ((lane >> 4) << 3);
                uint32_t bh[4], bl[4];
                ldsm_x4t(smem_u32(&Bh[brow][bcol]), bh[0], bh[1], bh[2], bh[3]);
                ldsm_x4t(smem_u32(&Bl[brow][bcol]), bl[0], bl[1], bl[2], bl[3]);
                #pragma unroll
                for (int half = 0; half < 2; half++) {
                    uint32_t bH0 = bh[half * 2], bH1 = bh[half * 2 + 1];
                    uint32_t bL0 = bl[half * 2], bL1 = bl[half * 2 + 1];
                    #pragma unroll
                    for (int mf = 0; mf < 2; mf++) {
                        float* d = acc[mf][nf2 * 2 + half];
                        mma_bf16(d, ah[mf], bH0, bH1);
                        mma_bf16(d, ah[mf], bL0, bL1);
                        mma_bf16(d, al[mf], bH0, bH1);
                    }
                }
            }
        }
        __syncthreads();
    }
    if (nbase < NTOTR) {
        const int colG = nbase + wn * WN + (lane & 3) * 2;
        #pragma unroll
        for (int mf = 0; mf < 2; mf++) {
            int r0 = rowBase + wm * 32 + mf * 16 + (lane >> 2);
            #pragma unroll
            for (int nf = 0; nf < 8; nf++) {
                float* d = acc[mf][nf];
                int c = colG + nf * 8;
                if (r0 < NN)
                    *reinterpret_cast<__half2*>(g_xw + (size_t)r0 * NTOTR + c) = __floats2half2_rn(d[0], d[1]);
                if (r0 + 8 < NN)
                    *reinterpret_cast<__half2*>(g_xw + (size_t)(r0 + 8) * NTOTR + c) = __floats2half2_rn(d[2], d[3]);
            }
        }
    } else if (wn == 0) {
        // dots tile: local cols 0..63 -> g_sd fp32
        const int scol = (lane & 3) * 2;
        #pragma unroll
        for (int mf = 0; mf < 2; mf++) {
            int r0 = rowBase + wm * 32 + mf * 16 + (lane >> 2);
            #pragma unroll
            for (int nf = 0; nf < 8; nf++) {
                float* d = acc[mf][nf];
                int c = scol + nf * 8;
                if (r0 < NN)
                    *reinterpret_cast<float2*>(g_sd + (size_t)r0 * 64 + c) = make_float2(d[0], d[1]);
                if (r0 + 8 < NN)
                    *reinterpret_cast<float2*>(g_sd + (size_t)(r0 + 8) * 64 + c) = make_float2(d[2], d[3]);
            }
        }
    }
}

// ---------------- CSR build (once per launch) ----------------
__global__ void zero_deg_kernel() {
    int i = blockIdx.x * blockDim.x + threadIdx.x;
    if (i < NN) g_deg[i] = 0;
}
__global__ void hist_kernel(const int* __restrict__ ei) {
    int e = blockIdx.x * blockDim.x + threadIdx.x;
    if (e < NE) atomicAdd(&g_deg[ei[NE + e]], 1);
}
__device__ __forceinline__ int blk_excl_scan(int v, int tid, int* wsum) {
    int lane = tid & 31, w = tid >> 5;
    int x = v;
    #pragma unroll
    for (int o = 1; o < 32; o <<= 1) { int t = __shfl_up_sync(~0u, x, o); if (lane >= o) x += t; }
    if (lane == 31) wsum[w] = x;
    __syncthreads();
    if (w == 0) {
        int s = (lane < 8) ? wsum[lane] : 0;
        #pragma unroll
        for (int o = 1; o < 8; o <<= 1) { int t = __shfl_up_sync(~0u, s, o); if (lane >= o) s += t; }
        if (lane < 8) wsum[lane] = s;
    }
    __syncthreads();
    int incl = x + (w > 0 ? wsum[w - 1] : 0);
    return incl - v;
}
__global__ void scan1_kernel() {
    __shared__ int wsum[8];
    int i = blockIdx.x * 256 + threadIdx.x;
    int v = (i < NN) ? g_deg[i] : 0;
    int excl = blk_excl_scan(v, threadIdx.x, wsum);
    if (i < NN) g_off[i] = excl;
    if (threadIdx.x == 255) g_bsum[blockIdx.x] = excl + v;
}
__global__ void scan2_kernel(int nb) {
    __shared__ int wsum[8];
    int t = threadIdx.x;
    int v = (t < nb) ? g_bsum[t] : 0;
    int excl = blk_excl_scan(v, t, wsum);
    if (t < nb) g_bsum[t] = excl;
}
__global__ void scan3_kernel() {
    int i = blockIdx.x * 256 + threadIdx.x;
    if (i < NN) {
        int f = g_off[i] + g_bsum[blockIdx.x];
        g_off[i] = f;
        g_pos[i] = f;
    }
    if (i == 0) g_off[NN] = NE;
}
__global__ void scatter_kernel(const int* __restrict__ ei, const int* __restrict__ et) {
    int e = blockIdx.x * blockDim.x + threadIdx.x;
    if (e >= NE) return;
    int dst = ei[NE + e];
    int p = atomicAdd(&g_pos[dst], 1);
    g_esr[p] = (ei[e] << 3) | et[e];
}

// ---------------- fused softmax+aggregation+bias+LN+ELU+bf16 export (warp per dst; H=4, M=256) ----------------
__global__ void agg_ln_csr(const float* __restrict__ arel, const float* __restrict__ bias,
                           const float* __restrict__ gam, const float* __restrict__ bet) {
    int n = (blockIdx.x * blockDim.x + threadIdx.x) >> 5;
    int lane = threadIdx.x & 31;
    if (n >= NN) return;
    int start = g_off[n], end = g_off[n + 1];
    int c0 = lane * 4, c1 = 128 + lane * 4;
    float4 a0 = make_float4(0.f, 0.f, 0.f, 0.f);
    float4 a1 = make_float4(0.f, 0.f, 0.f, 0.f);
    float4 den = make_float4(0.f, 0.f, 0.f, 0.f);
    for (int base = start; base < end; base += 32) {
        int p = base + lane;
        float4 ex = make_float4(0.f, 0.f, 0.f, 0.f);
        int sr = 0;
        if (p < end) {
            sr = g_esr[p];
            int src = sr >> 3, r = sr & 7;
            float4 s = ld4(g_sd + src * 64 + r * 4);
            float4 d = ld4(g_sd + n * 64 + 32 + r * 4);
            float4 a = ld4(arel + r * 4);
            float4 v;
            v.x = s.x + d.x + a.x; v.y = s.y + d.y + a.y;
            v.z = s.z + d.z + a.z; v.w = s.w + d.w + a.w;
            v.x = v.x > 0.f ? v.x : 0.2f * v.x;
            v.y = v.y > 0.f ? v.y : 0.2f * v.y;
            v.z = v.z > 0.f ? v.z : 0.2f * v.z;
            v.w = v.w > 0.f ? v.w : 0.2f * v.w;
            ex = make_float4(expf(v.x), expf(v.y), expf(v.z), expf(v.w));
        }
        den.x += ex.x; den.y += ex.y; den.z += ex.z; den.w += ex.w;
        int cnt = min(32, end - base);
        for (int j = 0; j < cnt; j++) {
            int srj = __shfl_sync(~0u, sr, j);
            float e0 = __shfl_sync(~0u, ex.x, j);
            float e1 = __shfl_sync(~0u, ex.y, j);
            float e2 = __shfl_sync(~0u, ex.z, j);
            float e3 = __shfl_sync(~0u, ex.w, j);
            float sA = (lane < 16) ? e0 : e1;
            float sB = (lane < 16) ? e2 : e3;
            const __half* xp = g_xw + (size_t)(srj >> 3) * 2048 + (srj & 7) * 256;
            float4 v0 = ldh4(xp + c0), v1 = ldh4(xp + c1);
            a0.x += v0.x * sA; a0.y += v0.y * sA; a0.z += v0.z * sA; a0.w += v0.w * sA;
            a1.x += v1.x * sB; a1.y += v1.y * sB; a1.z += v1.z * sB; a1.w += v1.w * sB;
        }
    }
    #pragma unroll
    for (int o = 16; o; o >>= 1) {
        den.x += __shfl_xor_sync(~0u, den.x, o);
        den.y += __shfl_xor_sync(~0u, den.y, o);
        den.z += __shfl_xor_sync(~0u, den.z, o);
        den.w += __shfl_xor_sync(~0u, den.w, o);
    }
    float dA = (lane < 16) ? den.x : den.y;
    float dB = (lane < 16) ? den.z : den.w;
    float iA = dA > 0.f ? 1.f / dA : 0.f;
    float iB = dB > 0.f ? 1.f / dB : 0.f;
    a0.x *= iA; a0.y *= iA; a0.z *= iA; a0.w *= iA;
    a1.x *= iB; a1.y *= iB; a1.z *= iB; a1.w *= iB;
    float4 b0 = ld4(bias + c0), b1 = ld4(bias + c1);
    a0.x += b0.x; a0.y += b0.y; a0.z += b0.z; a0.w += b0.w;
    a1.x += b1.x; a1.y += b1.y; a1.z += b1.z; a1.w += b1.w;
    float sum = a0.x + a0.y + a0.z + a0.w + a1.x + a1.y + a1.z + a1.w;
    float sq = a0.x * a0.x + a0.y * a0.y + a0.z * a0.z + a0.w * a0.w
             + a1.x * a1.x + a1.y * a1.y + a1.z * a1.z + a1.w * a1.w;
    #pragma unroll
    for (int o = 16; o; o >>= 1) {
        sum += __shfl_xor_sync(0xffffffffu, sum, o);
        sq  += __shfl_xor_sync(0xffffffffu, sq, o);
    }
    float mean = sum * (1.f / 256.f);
    float var = sq * (1.f / 256.f) - mean * mean;
    float rstd = rsqrtf(var + 1e-5f);
    float4 g0 = ld4(gam + c0), g1 = ld4(gam + c1);
    float4 e0v = ld4(bet + c0), e1v = ld4(bet + c1);
    float4 y0, y1;
    y0.x = (a0.x - mean) * rstd * g0.x + e0v.x;
    y0.y = (a0.y - mean) * rstd * g0.y + e0v.y;
    y0.z = (a0.z - mean) * rstd * g0.z + e0v.z;
    y0.w = (a0.w - mean) * rstd * g0.w + e0v.w;
    y1.x = (a1.x - mean) * rstd * g1.x + e1v.x;
    y1.y = (a1.y - mean) * rstd * g1.y + e1v.y;
    y1.z = (a1.z - mean) * rstd * g1.z + e1v.z;
    y1.w = (a1.w - mean) * rstd * g1.w + e1v.w;
    y0.x = y0.x > 0.f ? y0.x : expm1f(y0.x);
    y0.y = y0.y > 0.f ? y0.y : expm1f(y0.y);
    y0.z = y0.z > 0.f ? y0.z : expm1f(y0.z);
    y0.w = y0.w > 0.f ? y0.w : expm1f(y0.w);
    y1.x = y1.x > 0.f ? y1.x : expm1f(y1.x);
    y1.y = y1.y > 0.f ? y1.y : expm1f(y1.y);
    y1.z = y1.z > 0.f ? y1.z : expm1f(y1.z);
    y1.w = y1.w > 0.f ? y1.w : expm1f(y1.w);
    float* hp = g_h + (size_t)n * 256;
    st4(hp + c0, y0);
    st4(hp + c1, y1);
    unsigned h0, l0, h1, l1;
    split2(y0.x, y0.y, h0, l0);
    split2(y0.z, y0.w, h1, l1);
    *reinterpret_cast<uint2*>(g_xh + (size_t)n * 256 + c0) = make_uint2(h0, h1);
    *reinterpret_cast<uint2*>(g_xl + (size_t)n * 256 + c0) = make_uint2(l0, l1);
    split2(y1.x, y1.y, h0, l0);
    split2(y1.z, y1.w, h1, l1);
    *reinterpret_cast<uint2*>(g_xh + (size_t)n * 256 + c1) = make_uint2(h0, h1);
    *reinterpret_cast<uint2*>(g_xl + (size_t)n * 256 + c1) = make_uint2(l0, l1);
}

// ---------------- fused softmax+aggregation layer 2 (warp per dst; H=1, M=64) + bias -> out ----------------
// Broadcast loop is warp-uniform; accumulation predicated by (j&1)==half.
__global__ void agg_out_csr(const float* __restrict__ arel, const float* __restrict__ bi,
                            float* __restrict__ out) {
    int n = (blockIdx.x * blockDim.x + threadIdx.x) >> 5;
    int lane = threadIdx.x & 31;
    if (n >= NN) return;
    int start = g_off[n], end = g_off[n + 1];
    int half = lane >> 4;
    int c = (lane & 15) * 4;
    float4 acc = make_float4(0.f, 0.f, 0.f, 0.f);
    float den = 0.f;
    for (int base = start; base < end; base += 32) {
        int p = base + lane;
        float ex = 0.f;
        int sr = 0;
        if (p < end) {
            sr = g_esr[p];
            int src = sr >> 3, r = sr & 7;
            float v = g_sd[src * 64 + r] + g_sd[n * 64 + 8 + r] + arel[r];
            v = v > 0.f ? v : 0.2f * v;
            ex = expf(v);
        }
        den += ex;
        int cnt = min(32, end - base);
        for (int j = 0; j < cnt; j++) {
            int srj = __shfl_sync(~0u, sr, j);
            float exj = __shfl_sync(~0u, ex, j);
            if ((j & 1) == half) {
                const __half* xp = g_xw + (size_t)(srj >> 3) * 512 + (srj & 7) * 64;
                float4 v = ldh4(xp + c);
                acc.x += v.x * exj; acc.y += v.y * exj; acc.z += v.z * exj; acc.w += v.w * exj;
            }
        }
    }
    #pragma unroll
    for (int o = 16; o; o >>= 1) den += __shfl_xor_sync(~0u, den, o);
    acc.x += __shfl_xor_sync(~0u, acc.x, 16);
    acc.y += __shfl_xor_sync(~0u, acc.y, 16);
    acc.z += __shfl_xor_sync(~0u, acc.z, 16);
    acc.w += __shfl_xor_sync(~0u, acc.w, 16);
    if (half == 0) {
        float inv = den > 0.f ? 1.f / den : 0.f;
        float4 b = ld4(bi + c);
        acc.x = acc.x * inv + b.x;
        acc.y = acc.y * inv + b.y;
        acc.z = acc.z * inv + b.z;
        acc.w = acc.w * inv + b.w;
        st4(out + (size_t)n * 64 + c, acc);
    }
}

// ---------------- orchestration (pure kernel launches) ----------------
extern "C" void kernel_launch(void* const* d_in, const int* in_sizes, int n_in,
                              void* d_out, int out_size) {
    (void)in_sizes; (void)n_in; (void)out_size;
    const float* x  = (const float*)d_in[0];
    const int* ei   = (const int*)d_in[1];
    const int* et   = (const int*)d_in[2];
    const float* W0 = (const float*)d_in[3];
    const float* as0 = (const float*)d_in[4];
    const float* ad0 = (const float*)d_in[5];
    const float* ar0 = (const float*)d_in[6];
    const float* bi0 = (const float*)d_in[7];
    const float* W1 = (const float*)d_in[8];
    const float* as1 = (const float*)d_in[9];
    const float* ad1 = (const float*)d_in[10];
    const float* ar1 = (const float*)d_in[11];
    const float* bi1 = (const float*)d_in[12];
    const float* W2 = (const float*)d_in[13];
    const float* as2 = (const float*)d_in[14];
    const float* ad2 = (const float*)d_in[15];
    const float* ar2 = (const float*)d_in[16];
    const float* bi2 = (const float*)d_in[17];
    const float* g0 = (const float*)d_in[18];
    const float* be0 = (const float*)d_in[19];
    const float* g1 = (const float*)d_in[20];
    const float* be1 = (const float*)d_in[21];
    float* out = (float*)d_out;

    const int TB = 256;
    const int NT = (NN + 127) / 128;
    const int NB = (NN + 255) / 256;
    dim3 gTC01(NT, 17, 1);     // NTOTP=2176 (2048 real + dots tile)
    dim3 gTC2(NT, 5, 1);       // NTOTP=640  (512 real + dots tile)
    int ge = (NE + TB - 1) / TB;
    int gwn = (NN * 32 + TB - 1) / TB;

    // ======== layer 0: in=128 -> [8 rel] x 256, H=4 ========
    conv_w_t<128, 256, 2176><<<(128 * 512 + TB - 1) / TB, TB>>>(W0);
    conv_x_kernel<<<(NN * 128 / 4 + TB - 1) / TB, TB>>>(x, NN * 128 / 4);
    prep_ws2<4, 64, 2176, 2048><<<(128 * 32 + TB - 1) / TB, TB>>>(W0, as0, ad0, 128);
    mma_gemm<2048, 2176, 128><<<gTC01, TB>>>();        // 4th launch -> gets profiled
    // ---- build dst-CSR (needed before first aggregation) ----
    zero_deg_kernel<<<NB, TB>>>();
    hist_kernel<<<ge, TB>>>(ei);
    scan1_kernel<<<NB, TB>>>();
    scan2_kernel<<<1, TB>>>(NB);
    scan3_kernel<<<NB, TB>>>();
    scatter_kernel<<<ge, TB>>>(ei, et);
    agg_ln_csr<<<gwn, TB>>>(ar0, bi0, g0, be0);

    // ======== layer 1: in=256 -> [8 rel] x 256, H=4 ========
    conv_w_t<256, 256, 2176><<<(256 * 512 + TB - 1) / TB, TB>>>(W1);
    prep_ws2<4, 64, 2176, 2048><<<(256 * 32 + TB - 1) / TB, TB>>>(W1, as1, ad1, 256);
    mma_gemm<2048, 2176, 256><<<gTC01, TB>>>();
    agg_ln_csr<<<gwn, TB>>>(ar1, bi1, g1, be1);

    // ======== layer 2: in=256 -> [8 rel] x 64, H=1, no concat ========
    conv_w_t<256, 64, 640><<<(256 * 128 + TB - 1) / TB, TB>>>(W2);
    prep_ws2<1, 64, 640, 512><<<(256 * 32 + TB - 1) / TB, TB>>>(W2, as2, ad2, 256);
    mma_gemm<512, 640, 256><<<gTC2, TB>>>();
    agg_out_csr<<<gwn, TB>>>(ar2, bi2, out);
}

// round 15
// speedup vs baseline: 2.2110x; 1.0700x over previous
#include <cuda_runtime.h>
#include <cuda_bf16.h>
#include <cuda_fp16.h>
#include <cstdint>

#define NN 50000
#define NE 800000
#define NR 8

// ---------------- scratch (device globals; no allocs allowed) ----------------
__device__ __align__(16) __half g_xw[(size_t)NN * 2048];      // per-rel transforms (fp16)
__device__ __align__(16) float g_sd[NN * 64];                 // attention dots
__device__ __align__(16) float g_h[(size_t)NN * 256];
__device__ __align__(16) __nv_bfloat16 g_xh[(size_t)NN * 256];  // A operand hi
__device__ __align__(16) __nv_bfloat16 g_xl[(size_t)NN * 256];  // A operand lo
__device__ __align__(16) __nv_bfloat16 g_wh[256 * 2176];        // B hi, [K][NTOTP] transposed-concat + ws pad
__device__ __align__(16) __nv_bfloat16 g_wl[256 * 2176];        // B lo
// CSR by destination (built once per launch)
__device__ int g_deg[NN];
__device__ int g_off[NN + 1];
__device__ int g_pos[NN];
__device__ int g_bsum[256];
__device__ int g_esr[NE];     // (src<<3)|rel, grouped by dst

__device__ __forceinline__ float4 ld4(const float* p) { return *reinterpret_cast<const float4*>(p); }
__device__ __forceinline__ void st4(float* p, float4 v) { *reinterpret_cast<float4*>(p) = v; }

__device__ __forceinline__ uint32_t smem_u32(const void* p) {
    uint32_t a;
    asm("{ .reg .u64 t; cvta.to.shared.u64 t, %1; cvt.u32.u64 %0, t; }" : "=r"(a) : "l"(p));
    return a;
}

// load 4 halves -> float4
__device__ __forceinline__ float4 ldh4(const __half* p) {
    uint2 u = *reinterpret_cast<const uint2*>(p);
    __half2 h0 = *reinterpret_cast<__half2*>(&u.x);
    __half2 h1 = *reinterpret_cast<__half2*>(&u.y);
    float2 f0 = __half22float2(h0);
    float2 f1 = __half22float2(h1);
    return make_float4(f0.x, f0.y, f1.x, f1.y);
}

// fp32 pair -> bf16 hi pair + bf16 lo (residual) pair, packed as u32
__device__ __forceinline__ void split2(float x, float y, unsigned& hi, unsigned& lo) {
    __nv_bfloat16 hx = __float2bfloat16(x), hy = __float2bfloat16(y);
    float rx = x - __bfloat162float(hx), ry = y - __bfloat162float(hy);
    __nv_bfloat162 h; h.x = hx; h.y = hy;
    __nv_bfloat162 l = __floats2bfloat162_rn(rx, ry);
    hi = *reinterpret_cast<unsigned*>(&h);
    lo = *reinterpret_cast<unsigned*>(&l);
}

__device__ __forceinline__ void ldsm_x4(uint32_t addr, uint32_t& r0, uint32_t& r1, uint32_t& r2, uint32_t& r3) {
    asm volatile("ldmatrix.sync.aligned.m8n8.x4.shared.b16 {%0,%1,%2,%3}, [%4];"
                 : "=r"(r0), "=r"(r1), "=r"(r2), "=r"(r3) : "r"(addr));
}
__device__ __forceinline__ void ldsm_x4t(uint32_t addr, uint32_t& r0, uint32_t& r1, uint32_t& r2, uint32_t& r3) {
    asm volatile("ldmatrix.sync.aligned.m8n8.x4.trans.shared.b16 {%0,%1,%2,%3}, [%4];"
                 : "=r"(r0), "=r"(r1), "=r"(r2), "=r"(r3) : "r"(addr));
}
__device__ __forceinline__ void mma_bf16(float* d, const uint32_t* a, uint32_t b0, uint32_t b1) {
    asm volatile("mma.sync.aligned.m16n8k16.row.col.f32.bf16.bf16.f32 "
                 "{%0,%1,%2,%3}, {%4,%5,%6,%7}, {%8,%9}, {%0,%1,%2,%3};"
                 : "+f"(d[0]), "+f"(d[1]), "+f"(d[2]), "+f"(d[3])
                 : "r"(a[0]), "r"(a[1]), "r"(a[2]), "r"(a[3]), "r"(b0), "r"(b1));
}
__device__ __forceinline__ void cpa16(uint32_t d, const void* s, int zfill) {
    asm volatile("cp.async.cg.shared.global [%0], [%1], 16, %2;" :: "r"(d), "l"(s), "r"(zfill));
}

// ---------------- fp32 -> bf16 hi/lo converters ----------------
__global__ void conv_x_kernel(const float* __restrict__ X, int total4) {
    int i = blockIdx.x * blockDim.x + threadIdx.x;
    if (i >= total4) return;
    float4 v = ld4(X + (size_t)i * 4);
    unsigned h0, l0, h1, l1;
    split2(v.x, v.y, h0, l0);
    split2(v.z, v.w, h1, l1);
    *reinterpret_cast<uint2*>(g_xh + (size_t)i * 4) = make_uint2(h0, h1);
    *reinterpret_cast<uint2*>(g_xl + (size_t)i * 4) = make_uint2(l0, l1);
}
// W [R][K][M] -> transposed-concat [K][NTOTP] bf16 hi/lo (cols [0, 8*M))
template<int K, int M, int NTOTP>
__global__ void conv_w_t(const float* __restrict__ W) {
    int i = blockIdx.x * blockDim.x + threadIdx.x;
    constexpr int ROW4 = 8 * M / 4;
    if (i >= K * ROW4) return;
    int k = i / ROW4;
    int rest = i % ROW4;
    int z = rest / (M / 4);
    int m4 = rest % (M / 4);
    float4 v = ld4(W + ((size_t)z * K + k) * M + m4 * 4);
    unsigned h0, l0, h1, l1;
    split2(v.x, v.y, h0, l0);
    split2(v.z, v.w, h1, l1);
    size_t o = (size_t)k * NTOTP + z * M + m4 * 4;
    *reinterpret_cast<uint2*>(g_wh + o) = make_uint2(h0, h1);
    *reinterpret_cast<uint2*>(g_wl + o) = make_uint2(l0, l1);
}
// Fold attention-vector weights into pad cols [PADBASE, PADBASE+64) of g_wh/g_wl.
template<int H, int C, int NTOTP, int PADBASE>
__global__ void prep_ws2(const float* __restrict__ W, const float* __restrict__ a_src,
                         const float* __restrict__ a_dst, int K) {
    int idx = blockIdx.x * blockDim.x + threadIdx.x;
    if (idx >= K * 32) return;
    int k = idx >> 5;
    int cp = idx & 31;
    constexpr int RH = NR * H;
    float acc[2];
    #pragma unroll
    for (int q = 0; q < 2; q++) {
        int col = cp * 2 + q;
        float a = 0.f;
        if (col < 2 * RH) {
            int isd = col >= RH;
            int rh = isd ? col - RH : col;
            int r = rh / H, h = rh % H;
            const float* av = isd ? a_dst : a_src;
            const float* wrow = W + ((size_t)r * K + k) * (H * C) + h * C;
            #pragma unroll 8
            for (int c = 0; c < C; c++) a += wrow[c] * av[h * C + c];
        }
        acc[q] = a;
    }
    unsigned hi, lo;
    split2(acc[0], acc[1], hi, lo);
    size_t o = (size_t)k * NTOTP + PADBASE + cp * 2;
    *reinterpret_cast<unsigned*>(g_wh + o) = hi;
    *reinterpret_cast<unsigned*>(g_wl + o) = lo;
}

// ======== HMMA split-bf16 GEMM, 2-stage cp.async pipeline, dynamic SMEM ========
// cols [0, NTOTR): fp16 -> g_xw (stride NTOTR); cols [NTOTR, NTOTR+64): fp32 -> g_sd.
template<int NTOTR, int NTOTP, int KTOT>
__global__ void __launch_bounds__(256) mma_gemm() {
    constexpr int BN = 128, WN = 64, NF2 = 4;
    constexpr int AST = 40;
    constexpr int BST = BN + 8;
    constexpr int A_ELE = 128 * AST;       // per hi or lo buffer (bf16 elems)
    constexpr int B_ELE = 32 * BST;
    constexpr int STAGE = 2 * A_ELE + 2 * B_ELE;
    constexpr int NIT = KTOT / 32;

    extern __shared__ __nv_bfloat16 smem[];

    const int tid = threadIdx.x;
    const int wid = tid >> 5, lane = tid & 31;
    const int wm = wid & 3, wn = wid >> 2;
    const int rowBase = blockIdx.x * 128;
    const int nbase = blockIdx.y * BN;

    float acc[2][8][4];
    #pragma unroll
    for (int i = 0; i < 2; i++)
        #pragma unroll
        for (int j = 0; j < 8; j++)
            #pragma unroll
            for (int q = 0; q < 4; q++) acc[i][j][q] = 0.f;

    auto load_stage = [&](int s, int k0) {
        __nv_bfloat16* Ah = smem + (size_t)s * STAGE;
        __nv_bfloat16* Al = Ah + A_ELE;
        __nv_bfloat16* Bh = Al + A_ELE;
        __nv_bfloat16* Bl = Bh + B_ELE;
        #pragma unroll
        for (int i = 0; i < 2; i++) {
            int li = tid + i * 256;
            int row = li >> 2, c8 = (li & 3) * 8;
            int gr = rowBase + row;
            int zf = (gr < NN) ? 16 : 0;
            size_t goff = (size_t)gr * KTOT + k0 + c8;
            cpa16(smem_u32(Ah + row * AST + c8), g_xh + goff, zf);
            cpa16(smem_u32(Al + row * AST + c8), g_xl + goff, zf);
        }
        #pragma unroll
        for (int i = 0; i < 2; i++) {
            int li = tid + i * 256;
            int row = li >> 4, c8 = (li & 15) * 8;
            size_t goff = (size_t)(k0 + row) * NTOTP + nbase + c8;
            cpa16(smem_u32(Bh + row * BST + c8), g_wh + goff, 16);
            cpa16(smem_u32(Bl + row * BST + c8), g_wl + goff, 16);
        }
        asm volatile("cp.async.commit_group;");
    };

    load_stage(0, 0);

    for (int it = 0; it < NIT; it++) {
        if (it + 1 < NIT) {
            load_stage((it + 1) & 1, (it + 1) * 32);
            asm volatile("cp.async.wait_group 1;");
        } else {
            asm volatile("cp.async.wait_group 0;");
        }
        __syncthreads();

        const __nv_bfloat16* Ah = smem + (size_t)(it & 1) * STAGE;
        const __nv_bfloat16* Al = Ah + A_ELE;
        const __nv_bfloat16* Bh = Al + A_ELE;
        const __nv_bfloat16* Bl = Bh + B_ELE;

        #pragma unroll
        for (int ks = 0; ks < 2; ks++) {
            uint32_t ah[2][4], al[2][4];
            #pragma unroll
            for (int mf = 0; mf < 2; mf++) {
                int arow = wm * 32 + mf * 16 + (lane & 15);
                int acol = ks * 16 + ((lane >> 4) << 3);
                ldsm_x4(smem_u32(Ah + arow * AST + acol), ah[mf][0], ah[mf][1], ah[mf][2], ah[mf][3]);
                ldsm_x4(smem_u32(Al + arow * AST + acol), al[mf][0], al[mf][1], al[mf][2], al[mf][3]);
            }
            #pragma unroll
            for (int nf2 = 0; nf2 < NF2; nf2++) {
                int brow = ks * 16 + (lane & 15);
                int bcol = wn * WN + nf2 * 16 + ((lane >> 4) << 3);
                uint32_t bh[4], bl[4];
                ldsm_x4t(smem_u32(Bh + brow * BST + bcol), bh[0], bh[1], bh[2], bh[3]);
                ldsm_x4t(smem_u32(Bl + brow * BST + bcol), bl[0], bl[1], bl[2], bl[3]);
                #pragma unroll
                for (int half = 0; half < 2; half++) {
                    uint32_t bH0 = bh[half * 2], bH1 = bh[half * 2 + 1];
                    uint32_t bL0 = bl[half * 2], bL1 = bl[half * 2 + 1];
                    #pragma unroll
                    for (int mf = 0; mf < 2; mf++) {
                        float* d = acc[mf][nf2 * 2 + half];
                        mma_bf16(d, ah[mf], bH0, bH1);
                        mma_bf16(d, ah[mf], bL0, bL1);
                        mma_bf16(d, al[mf], bH0, bH1);
                    }
                }
            }
        }
        __syncthreads();
    }
    if (nbase < NTOTR) {
        const int colG = nbase + wn * WN + (lane & 3) * 2;
        #pragma unroll
        for (int mf = 0; mf < 2; mf++) {
            int r0 = rowBase + wm * 32 + mf * 16 + (lane >> 2);
            #pragma unroll
            for (int nf = 0; nf < 8; nf++) {
                float* d = acc[mf][nf];
                int c = colG + nf * 8;
                if (r0 < NN)
                    *reinterpret_cast<__half2*>(g_xw + (size_t)r0 * NTOTR + c) = __floats2half2_rn(d[0], d[1]);
                if (r0 + 8 < NN)
                    *reinterpret_cast<__half2*>(g_xw + (size_t)(r0 + 8) * NTOTR + c) = __floats2half2_rn(d[2], d[3]);
            }
        }
    } else if (wn == 0) {
        const int scol = (lane & 3) * 2;
        #pragma unroll
        for (int mf = 0; mf < 2; mf++) {
            int r0 = rowBase + wm * 32 + mf * 16 + (lane >> 2);
            #pragma unroll
            for (int nf = 0; nf < 8; nf++) {
                float* d = acc[mf][nf];
                int c = scol + nf * 8;
                if (r0 < NN)
                    *reinterpret_cast<float2*>(g_sd + (size_t)r0 * 64 + c) = make_float2(d[0], d[1]);
                if (r0 + 8 < NN)
                    *reinterpret_cast<float2*>(g_sd + (size_t)(r0 + 8) * 64 + c) = make_float2(d[2], d[3]);
            }
        }
    }
}

// ---------------- CSR build (once per launch) ----------------
__global__ void zero_deg_kernel() {
    int i = blockIdx.x * blockDim.x + threadIdx.x;
    if (i < NN) g_deg[i] = 0;
}
__global__ void hist_kernel(const int* __restrict__ ei) {
    int e = blockIdx.x * blockDim.x + threadIdx.x;
    if (e < NE) atomicAdd(&g_deg[ei[NE + e]], 1);
}
__device__ __forceinline__ int blk_excl_scan(int v, int tid, int* wsum) {
    int lane = tid & 31, w = tid >> 5;
    int x = v;
    #pragma unroll
    for (int o = 1; o < 32; o <<= 1) { int t = __shfl_up_sync(~0u, x, o); if (lane >= o) x += t; }
    if (lane == 31) wsum[w] = x;
    __syncthreads();
    if (w == 0) {
        int s = (lane < 8) ? wsum[lane] : 0;
        #pragma unroll
        for (int o = 1; o < 8; o <<= 1) { int t = __shfl_up_sync(~0u, s, o); if (lane >= o) s += t; }
        if (lane < 8) wsum[lane] = s;
    }
    __syncthreads();
    int incl = x + (w > 0 ? wsum[w - 1] : 0);
    return incl - v;
}
__global__ void scan1_kernel() {
    __shared__ int wsum[8];
    int i = blockIdx.x * 256 + threadIdx.x;
    int v = (i < NN) ? g_deg[i] : 0;
    int excl = blk_excl_scan(v, threadIdx.x, wsum);
    if (i < NN) g_off[i] = excl;
    if (threadIdx.x == 255) g_bsum[blockIdx.x] = excl + v;
}
__global__ void scan2_kernel(int nb) {
    __shared__ int wsum[8];
    int t = threadIdx.x;
    int v = (t < nb) ? g_bsum[t] : 0;
    int excl = blk_excl_scan(v, t, wsum);
    if (t < nb) g_bsum[t] = excl;
}
__global__ void scan3_kernel() {
    int i = blockIdx.x * 256 + threadIdx.x;
    if (i < NN) {
        int f = g_off[i] + g_bsum[blockIdx.x];
        g_off[i] = f;
        g_pos[i] = f;
    }
    if (i == 0) g_off[NN] = NE;
}
__global__ void scatter_kernel(const int* __restrict__ ei, const int* __restrict__ et) {
    int e = blockIdx.x * blockDim.x + threadIdx.x;
    if (e >= NE) return;
    int dst = ei[NE + e];
    int p = atomicAdd(&g_pos[dst], 1);
    g_esr[p] = (ei[e] << 3) | et[e];
}

// ---------------- fused softmax+aggregation+bias+LN+ELU+bf16 export (warp per dst; H=4, M=256) ----------------
__global__ void agg_ln_csr(const float* __restrict__ arel, const float* __restrict__ bias,
                           const float* __restrict__ gam, const float* __restrict__ bet) {
    int n = (blockIdx.x * blockDim.x + threadIdx.x) >> 5;
    int lane = threadIdx.x & 31;
    if (n >= NN) return;
    int start = g_off[n], end = g_off[n + 1];
    int c0 = lane * 4, c1 = 128 + lane * 4;
    float4 a0 = make_float4(0.f, 0.f, 0.f, 0.f);
    float4 a1 = make_float4(0.f, 0.f, 0.f, 0.f);
    float4 den = make_float4(0.f, 0.f, 0.f, 0.f);
    for (int base = start; base < end; base += 32) {
        int p = base + lane;
        float4 ex = make_float4(0.f, 0.f, 0.f, 0.f);
        int sr = 0;
        if (p < end) {
            sr = g_esr[p];
            int src = sr >> 3, r = sr & 7;
            float4 s = ld4(g_sd + src * 64 + r * 4);
            float4 d = ld4(g_sd + n * 64 + 32 + r * 4);
            float4 a = ld4(arel + r * 4);
            float4 v;
            v.x = s.x + d.x + a.x; v.y = s.y + d.y + a.y;
            v.z = s.z + d.z + a.z; v.w = s.w + d.w + a.w;
            v.x = v.x > 0.f ? v.x : 0.2f * v.x;
            v.y = v.y > 0.f ? v.y : 0.2f * v.y;
            v.z = v.z > 0.f ? v.z : 0.2f * v.z;
            v.w = v.w > 0.f ? v.w : 0.2f * v.w;
            ex = make_float4(expf(v.x), expf(v.y), expf(v.z), expf(v.w));
        }
        den.x += ex.x; den.y += ex.y; den.z += ex.z; den.w += ex.w;
        int cnt = min(32, end - base);
        for (int j = 0; j < cnt; j++) {
            int srj = __shfl_sync(~0u, sr, j);
            float e0 = __shfl_sync(~0u, ex.x, j);
            float e1 = __shfl_sync(~0u, ex.y, j);
            float e2 = __shfl_sync(~0u, ex.z, j);
            float e3 = __shfl_sync(~0u, ex.w, j);
            float sA = (lane < 16) ? e0 : e1;
            float sB = (lane < 16) ? e2 : e3;
            const __half* xp = g_xw + (size_t)(srj >> 3) * 2048 + (srj & 7) * 256;
            float4 v0 = ldh4(xp + c0), v1 = ldh4(xp + c1);
            a0.x += v0.x * sA; a0.y += v0.y * sA; a0.z += v0.z * sA; a0.w += v0.w * sA;
            a1.x += v1.x * sB; a1.y += v1.y * sB; a1.z += v1.z * sB; a1.w += v1.w * sB;
        }
    }
    #pragma unroll
    for (int o = 16; o; o >>= 1) {
        den.x += __shfl_xor_sync(~0u, den.x, o);
        den.y += __shfl_xor_sync(~0u, den.y, o);
        den.z += __shfl_xor_sync(~0u, den.z, o);
        den.w += __shfl_xor_sync(~0u, den.w, o);
    }
    float dA = (lane < 16) ? den.x : den.y;
    float dB = (lane < 16) ? den.z : den.w;
    float iA = dA > 0.f ? 1.f / dA : 0.f;
    float iB = dB > 0.f ? 1.f / dB : 0.f;
    a0.x *= iA; a0.y *= iA; a0.z *= iA; a0.w *= iA;
    a1.x *= iB; a1.y *= iB; a1.z *= iB; a1.w *= iB;
    float4 b0 = ld4(bias + c0), b1 = ld4(bias + c1);
    a0.x += b0.x; a0.y += b0.y; a0.z += b0.z; a0.w += b0.w;
    a1.x += b1.x; a1.y += b1.y; a1.z += b1.z; a1.w += b1.w;
    float sum = a0.x + a0.y + a0.z + a0.w + a1.x + a1.y + a1.z + a1.w;
    float sq = a0.x * a0.x + a0.y * a0.y + a0.z * a0.z + a0.w * a0.w
             + a1.x * a1.x + a1.y * a1.y + a1.z * a1.z + a1.w * a1.w;
    #pragma unroll
    for (int o = 16; o; o >>= 1) {
        sum += __shfl_xor_sync(0xffffffffu, sum, o);
        sq  += __shfl_xor_sync(0xffffffffu, sq, o);
    }
    float mean = sum * (1.f / 256.f);
    float var = sq * (1.f / 256.f) - mean * mean;
    float rstd = rsqrtf(var + 1e-5f);
    float4 g0 = ld4(gam + c0), g1 = ld4(gam + c1);
    float4 e0v = ld4(bet + c0), e1v = ld4(bet + c1);
    float4 y0, y1;
    y0.x = (a0.x - mean) * rstd * g0.x + e0v.x;
    y0.y = (a0.y - mean) * rstd * g0.y + e0v.y;
    y0.z = (a0.z - mean) * rstd * g0.z + e0v.z;
    y0.w = (a0.w - mean) * rstd * g0.w + e0v.w;
    y1.x = (a1.x - mean) * rstd * g1.x + e1v.x;
    y1.y = (a1.y - mean) * rstd * g1.y + e1v.y;
    y1.z = (a1.z - mean) * rstd * g1.z + e1v.z;
    y1.w = (a1.w - mean) * rstd * g1.w + e1v.w;
    y0.x = y0.x > 0.f ? y0.x : expm1f(y0.x);
    y0.y = y0.y > 0.f ? y0.y : expm1f(y0.y);
    y0.z = y0.z > 0.f ? y0.z : expm1f(y0.z);
    y0.w = y0.w > 0.f ? y0.w : expm1f(y0.w);
    y1.x = y1.x > 0.f ? y1.x : expm1f(y1.x);
    y1.y = y1.y > 0.f ? y1.y : expm1f(y1.y);
    y1.z = y1.z > 0.f ? y1.z : expm1f(y1.z);
    y1.w = y1.w > 0.f ? y1.w : expm1f(y1.w);
    float* hp = g_h + (size_t)n * 256;
    st4(hp + c0, y0);
    st4(hp + c1, y1);
    unsigned h0, l0, h1, l1;
    split2(y0.x, y0.y, h0, l0);
    split2(y0.z, y0.w, h1, l1);
    *reinterpret_cast<uint2*>(g_xh + (size_t)n * 256 + c0) = make_uint2(h0, h1);
    *reinterpret_cast<uint2*>(g_xl + (size_t)n * 256 + c0) = make_uint2(l0, l1);
    split2(y1.x, y1.y, h0, l0);
    split2(y1.z, y1.w, h1, l1);
    *reinterpret_cast<uint2*>(g_xh + (size_t)n * 256 + c1) = make_uint2(h0, h1);
    *reinterpret_cast<uint2*>(g_xl + (size_t)n * 256 + c1) = make_uint2(l0, l1);
}

// ---------------- fused softmax+aggregation layer 2 (warp per dst; H=1, M=64) + bias -> out ----------------
__global__ void agg_out_csr(const float* __restrict__ arel, const float* __restrict__ bi,
                            float* __restrict__ out) {
    int n = (blockIdx.x * blockDim.x + threadIdx.x) >> 5;
    int lane = threadIdx.x & 31;
    if (n >= NN) return;
    int start = g_off[n], end = g_off[n + 1];
    int half = lane >> 4;
    int c = (lane & 15) * 4;
    float4 acc = make_float4(0.f, 0.f, 0.f, 0.f);
    float den = 0.f;
    for (int base = start; base < end; base += 32) {
        int p = base + lane;
        float ex = 0.f;
        int sr = 0;
        if (p < end) {
            sr = g_esr[p];
            int src = sr >> 3, r = sr & 7;
            float v = g_sd[src * 64 + r] + g_sd[n * 64 + 8 + r] + arel[r];
            v = v > 0.f ? v : 0.2f * v;
            ex = expf(v);
        }
        den += ex;
        int cnt = min(32, end - base);
        for (int j = 0; j < cnt; j++) {
            int srj = __shfl_sync(~0u, sr, j);
            float exj = __shfl_sync(~0u, ex, j);
            if ((j & 1) == half) {
                const __half* xp = g_xw + (size_t)(srj >> 3) * 512 + (srj & 7) * 64;
                float4 v = ldh4(xp + c);
                acc.x += v.x * exj; acc.y += v.y * exj; acc.z += v.z * exj; acc.w += v.w * exj;
            }
        }
    }
    #pragma unroll
    for (int o = 16; o; o >>= 1) den += __shfl_xor_sync(~0u, den, o);
    acc.x += __shfl_xor_sync(~0u, acc.x, 16);
    acc.y += __shfl_xor_sync(~0u, acc.y, 16);
    acc.z += __shfl_xor_sync(~0u, acc.z, 16);
    acc.w += __shfl_xor_sync(~0u, acc.w, 16);
    if (half == 0) {
        float inv = den > 0.f ? 1.f / den : 0.f;
        float4 b = ld4(bi + c);
        acc.x = acc.x * inv + b.x;
        acc.y = acc.y * inv + b.y;
        acc.z = acc.z * inv + b.z;
        acc.w = acc.w * inv + b.w;
        st4(out + (size_t)n * 64 + c, acc);
    }
}

// ---------------- orchestration ----------------
extern "C" void kernel_launch(void* const* d_in, const int* in_sizes, int n_in,
                              void* d_out, int out_size) {
    (void)in_sizes; (void)n_in; (void)out_size;
    const float* x  = (const float*)d_in[0];
    const int* ei   = (const int*)d_in[1];
    const int* et   = (const int*)d_in[2];
    const float* W0 = (const float*)d_in[3];
    const float* as0 = (const float*)d_in[4];
    const float* ad0 = (const float*)d_in[5];
    const float* ar0 = (const float*)d_in[6];
    const float* bi0 = (const float*)d_in[7];
    const float* W1 = (const float*)d_in[8];
    const float* as1 = (const float*)d_in[9];
    const float* ad1 = (const float*)d_in[10];
    const float* ar1 = (const float*)d_in[11];
    const float* bi1 = (const float*)d_in[12];
    const float* W2 = (const float*)d_in[13];
    const float* as2 = (const float*)d_in[14];
    const float* ad2 = (const float*)d_in[15];
    const float* ar2 = (const float*)d_in[16];
    const float* bi2 = (const float*)d_in[17];
    const float* g0 = (const float*)d_in[18];
    const float* be0 = (const float*)d_in[19];
    const float* g1 = (const float*)d_in[20];
    const float* be1 = (const float*)d_in[21];
    float* out = (float*)d_out;

    const int TB = 256;
    const int NT = (NN + 127) / 128;
    const int NB = (NN + 255) / 256;
    dim3 gTC01(NT, 17, 1);     // NTOTP=2176 (2048 real + dots tile)
    dim3 gTC2(NT, 5, 1);       // NTOTP=640  (512 real + dots tile)
    int ge = (NE + TB - 1) / TB;
    int gwn = (NN * 32 + TB - 1) / TB;

    // dynamic smem: 2 stages x (A hi/lo 128x40 + B hi/lo 32x136) bf16
    const int SMSZ = 2 * (2 * 128 * 40 + 2 * 32 * 136) * 2;    // 75776 B
    cudaFuncSetAttribute((const void*)mma_gemm<2048, 2176, 128>, cudaFuncAttributeMaxDynamicSharedMemorySize, SMSZ);
    cudaFuncSetAttribute((const void*)mma_gemm<2048, 2176, 256>, cudaFuncAttributeMaxDynamicSharedMemorySize, SMSZ);
    cudaFuncSetAttribute((const void*)mma_gemm<512, 640, 256>,  cudaFuncAttributeMaxDynamicSharedMemorySize, SMSZ);

    // ======== layer 0: in=128 -> [8 rel] x 256, H=4 ========
    conv_w_t<128, 256, 2176><<<(128 * 512 + TB - 1) / TB, TB>>>(W0);
    conv_x_kernel<<<(NN * 128 / 4 + TB - 1) / TB, TB>>>(x, NN * 128 / 4);
    prep_ws2<4, 64, 2176, 2048><<<(128 * 32 + TB - 1) / TB, TB>>>(W0, as0, ad0, 128);
    mma_gemm<2048, 2176, 128><<<gTC01, TB, SMSZ>>>();   // 4th launch -> gets profiled
    // ---- build dst-CSR (needed before first aggregation) ----
    zero_deg_kernel<<<NB, TB>>>();
    hist_kernel<<<ge, TB>>>(ei);
    scan1_kernel<<<NB, TB>>>();
    scan2_kernel<<<1, TB>>>(NB);
    scan3_kernel<<<NB, TB>>>();
    scatter_kernel<<<ge, TB>>>(ei, et);
    agg_ln_csr<<<gwn, TB>>>(ar0, bi0, g0, be0);

    // ======== layer 1: in=256 -> [8 rel] x 256, H=4 ========
    conv_w_t<256, 256, 2176><<<(256 * 512 + TB - 1) / TB, TB>>>(W1);
    prep_ws2<4, 64, 2176, 2048><<<(256 * 32 + TB - 1) / TB, TB>>>(W1, as1, ad1, 256);
    mma_gemm<2048, 2176, 256><<<gTC01, TB, SMSZ>>>();
    agg_ln_csr<<<gwn, TB>>>(ar1, bi1, g1, be1);

    // ======== layer 2: in=256 -> [8 rel] x 64, H=1, no concat ========
    conv_w_t<256, 64, 640><<<(256 * 128 + TB - 1) / TB, TB>>>(W2);
    prep_ws2<1, 64, 640, 512><<<(256 * 32 + TB - 1) / TB, TB>>>(W2, as2, ad2, 256);
    mma_gemm<512, 640, 256><<<gTC2, TB, SMSZ>>>();
    agg_out_csr<<<gwn, TB>>>(ar2, bi2, out);
}

// round 16
// speedup vs baseline: 2.2244x; 1.0061x over previous
#include <cuda_runtime.h>
#include <cuda_bf16.h>
#include <cuda_fp16.h>
#include <cstdint>

#define NN 50000
#define NE 800000
#define NR 8

// ---------------- scratch (device globals; no allocs allowed) ----------------
__device__ __align__(16) __half g_xw[(size_t)NN * 2048];      // per-rel transforms (fp16)
__device__ __align__(16) float g_sd[NN * 64];                 // attention dots
__device__ __align__(16) float g_h[(size_t)NN * 256];
__device__ __align__(16) __nv_bfloat16 g_xh[(size_t)NN * 256];  // A operand hi
__device__ __align__(16) __nv_bfloat16 g_xl[(size_t)NN * 256];  // A operand lo
__device__ __align__(16) __nv_bfloat16 g_wh[256 * 2176];        // B hi, [K][NTOTP] transposed-concat + ws pad
__device__ __align__(16) __nv_bfloat16 g_wl[256 * 2176];        // B lo
// CSR by destination (built once per launch)
__device__ int g_deg[NN];
__device__ int g_off[NN + 1];
__device__ int g_pos[NN];
__device__ int g_bsum[256];
__device__ int g_esr[NE];     // (src<<3)|rel, grouped by dst

__device__ __forceinline__ float4 ld4(const float* p) { return *reinterpret_cast<const float4*>(p); }
__device__ __forceinline__ void st4(float* p, float4 v) { *reinterpret_cast<float4*>(p) = v; }

__device__ __forceinline__ uint32_t smem_u32(const void* p) {
    uint32_t a;
    asm("{ .reg .u64 t; cvta.to.shared.u64 t, %1; cvt.u32.u64 %0, t; }" : "=r"(a) : "l"(p));
    return a;
}

// load 4 halves -> float4
__device__ __forceinline__ float4 ldh4(const __half* p) {
    uint2 u = *reinterpret_cast<const uint2*>(p);
    __half2 h0 = *reinterpret_cast<__half2*>(&u.x);
    __half2 h1 = *reinterpret_cast<__half2*>(&u.y);
    float2 f0 = __half22float2(h0);
    float2 f1 = __half22float2(h1);
    return make_float4(f0.x, f0.y, f1.x, f1.y);
}

// fp32 pair -> bf16 hi pair + bf16 lo (residual) pair, packed as u32
__device__ __forceinline__ void split2(float x, float y, unsigned& hi, unsigned& lo) {
    __nv_bfloat16 hx = __float2bfloat16(x), hy = __float2bfloat16(y);
    float rx = x - __bfloat162float(hx), ry = y - __bfloat162float(hy);
    __nv_bfloat162 h; h.x = hx; h.y = hy;
    __nv_bfloat162 l = __floats2bfloat162_rn(rx, ry);
    hi = *reinterpret_cast<unsigned*>(&h);
    lo = *reinterpret_cast<unsigned*>(&l);
}

__device__ __forceinline__ void ldsm_x4(uint32_t addr, uint32_t& r0, uint32_t& r1, uint32_t& r2, uint32_t& r3) {
    asm volatile("ldmatrix.sync.aligned.m8n8.x4.shared.b16 {%0,%1,%2,%3}, [%4];"
                 : "=r"(r0), "=r"(r1), "=r"(r2), "=r"(r3) : "r"(addr));
}
__device__ __forceinline__ void ldsm_x4t(uint32_t addr, uint32_t& r0, uint32_t& r1, uint32_t& r2, uint32_t& r3) {
    asm volatile("ldmatrix.sync.aligned.m8n8.x4.trans.shared.b16 {%0,%1,%2,%3}, [%4];"
                 : "=r"(r0), "=r"(r1), "=r"(r2), "=r"(r3) : "r"(addr));
}
__device__ __forceinline__ void mma_bf16(float* d, const uint32_t* a, uint32_t b0, uint32_t b1) {
    asm volatile("mma.sync.aligned.m16n8k16.row.col.f32.bf16.bf16.f32 "
                 "{%0,%1,%2,%3}, {%4,%5,%6,%7}, {%8,%9}, {%0,%1,%2,%3};"
                 : "+f"(d[0]), "+f"(d[1]), "+f"(d[2]), "+f"(d[3])
                 : "r"(a[0]), "r"(a[1]), "r"(a[2]), "r"(a[3]), "r"(b0), "r"(b1));
}
__device__ __forceinline__ void cpa16(uint32_t d, const void* s, int zfill) {
    asm volatile("cp.async.cg.shared.global [%0], [%1], 16, %2;" :: "r"(d), "l"(s), "r"(zfill));
}

// ---------------- fp32 -> bf16 hi/lo converters ----------------
__global__ void conv_x_kernel(const float* __restrict__ X, int total4) {
    int i = blockIdx.x * blockDim.x + threadIdx.x;
    if (i >= total4) return;
    float4 v = ld4(X + (size_t)i * 4);
    unsigned h0, l0, h1, l1;
    split2(v.x, v.y, h0, l0);
    split2(v.z, v.w, h1, l1);
    *reinterpret_cast<uint2*>(g_xh + (size_t)i * 4) = make_uint2(h0, h1);
    *reinterpret_cast<uint2*>(g_xl + (size_t)i * 4) = make_uint2(l0, l1);
}
// W [R][K][M] -> transposed-concat [K][NTOTP] bf16 hi/lo (cols [0, 8*M))
template<int K, int M, int NTOTP>
__global__ void conv_w_t(const float* __restrict__ W) {
    int i = blockIdx.x * blockDim.x + threadIdx.x;
    constexpr int ROW4 = 8 * M / 4;
    if (i >= K * ROW4) return;
    int k = i / ROW4;
    int rest = i % ROW4;
    int z = rest / (M / 4);
    int m4 = rest % (M / 4);
    float4 v = ld4(W + ((size_t)z * K + k) * M + m4 * 4);
    unsigned h0, l0, h1, l1;
    split2(v.x, v.y, h0, l0);
    split2(v.z, v.w, h1, l1);
    size_t o = (size_t)k * NTOTP + z * M + m4 * 4;
    *reinterpret_cast<uint2*>(g_wh + o) = make_uint2(h0, h1);
    *reinterpret_cast<uint2*>(g_wl + o) = make_uint2(l0, l1);
}
// Fold attention-vector weights into pad cols [PADBASE, PADBASE+64) of g_wh/g_wl.
template<int H, int C, int NTOTP, int PADBASE>
__global__ void prep_ws2(const float* __restrict__ W, const float* __restrict__ a_src,
                         const float* __restrict__ a_dst, int K) {
    int idx = blockIdx.x * blockDim.x + threadIdx.x;
    if (idx >= K * 32) return;
    int k = idx >> 5;
    int cp = idx & 31;
    constexpr int RH = NR * H;
    float acc[2];
    #pragma unroll
    for (int q = 0; q < 2; q++) {
        int col = cp * 2 + q;
        float a = 0.f;
        if (col < 2 * RH) {
            int isd = col >= RH;
            int rh = isd ? col - RH : col;
            int r = rh / H, h = rh % H;
            const float* av = isd ? a_dst : a_src;
            const float* wrow = W + ((size_t)r * K + k) * (H * C) + h * C;
            #pragma unroll 8
            for (int c = 0; c < C; c++) a += wrow[c] * av[h * C + c];
        }
        acc[q] = a;
    }
    unsigned hi, lo;
    split2(acc[0], acc[1], hi, lo);
    size_t o = (size_t)k * NTOTP + PADBASE + cp * 2;
    *reinterpret_cast<unsigned*>(g_wh + o) = hi;
    *reinterpret_cast<unsigned*>(g_wl + o) = lo;
}

// ======== HMMA split-bf16 GEMM, 2-stage cp.async pipeline, term-major MMA issue ========
// cols [0, NTOTR): fp16 -> g_xw (stride NTOTR); cols [NTOTR, NTOTR+64): fp32 -> g_sd.
template<int NTOTR, int NTOTP, int KTOT>
__global__ void __launch_bounds__(256) mma_gemm() {
    constexpr int BN = 128, WN = 64, NF2 = 4;
    constexpr int AST = 40;
    constexpr int BST = BN + 8;
    constexpr int A_ELE = 128 * AST;       // per hi or lo buffer (bf16 elems)
    constexpr int B_ELE = 32 * BST;
    constexpr int STAGE = 2 * A_ELE + 2 * B_ELE;
    constexpr int NIT = KTOT / 32;

    extern __shared__ __nv_bfloat16 smem[];

    const int tid = threadIdx.x;
    const int wid = tid >> 5, lane = tid & 31;
    const int wm = wid & 3, wn = wid >> 2;
    const int rowBase = blockIdx.x * 128;
    const int nbase = blockIdx.y * BN;

    float acc[2][8][4];
    #pragma unroll
    for (int i = 0; i < 2; i++)
        #pragma unroll
        for (int j = 0; j < 8; j++)
            #pragma unroll
            for (int q = 0; q < 4; q++) acc[i][j][q] = 0.f;

    auto load_stage = [&](int s, int k0) {
        __nv_bfloat16* Ah = smem + (size_t)s * STAGE;
        __nv_bfloat16* Al = Ah + A_ELE;
        __nv_bfloat16* Bh = Al + A_ELE;
        __nv_bfloat16* Bl = Bh + B_ELE;
        #pragma unroll
        for (int i = 0; i < 2; i++) {
            int li = tid + i * 256;
            int row = li >> 2, c8 = (li & 3) * 8;
            int gr = rowBase + row;
            int zf = (gr < NN) ? 16 : 0;
            size_t goff = (size_t)gr * KTOT + k0 + c8;
            cpa16(smem_u32(Ah + row * AST + c8), g_xh + goff, zf);
            cpa16(smem_u32(Al + row * AST + c8), g_xl + goff, zf);
        }
        #pragma unroll
        for (int i = 0; i < 2; i++) {
            int li = tid + i * 256;
            int row = li >> 4, c8 = (li & 15) * 8;
            size_t goff = (size_t)(k0 + row) * NTOTP + nbase + c8;
            cpa16(smem_u32(Bh + row * BST + c8), g_wh + goff, 16);
            cpa16(smem_u32(Bl + row * BST + c8), g_wl + goff, 16);
        }
        asm volatile("cp.async.commit_group;");
    };

    load_stage(0, 0);

    for (int it = 0; it < NIT; it++) {
        if (it + 1 < NIT) {
            load_stage((it + 1) & 1, (it + 1) * 32);
            asm volatile("cp.async.wait_group 1;");
        } else {
            asm volatile("cp.async.wait_group 0;");
        }
        __syncthreads();

        const __nv_bfloat16* Ah = smem + (size_t)(it & 1) * STAGE;
        const __nv_bfloat16* Al = Ah + A_ELE;
        const __nv_bfloat16* Bh = Al + A_ELE;
        const __nv_bfloat16* Bl = Bh + B_ELE;

        #pragma unroll
        for (int ks = 0; ks < 2; ks++) {
            uint32_t ah[2][4], al[2][4];
            #pragma unroll
            for (int mf = 0; mf < 2; mf++) {
                int arow = wm * 32 + mf * 16 + (lane & 15);
                int acol = ks * 16 + ((lane >> 4) << 3);
                ldsm_x4(smem_u32(Ah + arow * AST + acol), ah[mf][0], ah[mf][1], ah[mf][2], ah[mf][3]);
                ldsm_x4(smem_u32(Al + arow * AST + acol), al[mf][0], al[mf][1], al[mf][2], al[mf][3]);
            }
            #pragma unroll
            for (int nf2 = 0; nf2 < NF2; nf2++) {
                int brow = ks * 16 + (lane & 15);
                int bcol = wn * WN + nf2 * 16 + ((lane >> 4) << 3);
                uint32_t bh[4], bl[4];
                ldsm_x4t(smem_u32(Bh + brow * BST + bcol), bh[0], bh[1], bh[2], bh[3]);
                ldsm_x4t(smem_u32(Bl + brow * BST + bcol), bl[0], bl[1], bl[2], bl[3]);
                // term-major issue: all HH, then all HL, then all LH — 4 independent
                // accumulator chains between dependent reuses (same per-acc term order).
                #pragma unroll
                for (int half = 0; half < 2; half++)
                    #pragma unroll
                    for (int mf = 0; mf < 2; mf++)
                        mma_bf16(acc[mf][nf2 * 2 + half], ah[mf], bh[half * 2], bh[half * 2 + 1]);
                #pragma unroll
                for (int half = 0; half < 2; half++)
                    #pragma unroll
                    for (int mf = 0; mf < 2; mf++)
                        mma_bf16(acc[mf][nf2 * 2 + half], ah[mf], bl[half * 2], bl[half * 2 + 1]);
                #pragma unroll
                for (int half = 0; half < 2; half++)
                    #pragma unroll
                    for (int mf = 0; mf < 2; mf++)
                        mma_bf16(acc[mf][nf2 * 2 + half], al[mf], bh[half * 2], bh[half * 2 + 1]);
            }
        }
        __syncthreads();
    }
    if (nbase < NTOTR) {
        const int colG = nbase + wn * WN + (lane & 3) * 2;
        #pragma unroll
        for (int mf = 0; mf < 2; mf++) {
            int r0 = rowBase + wm * 32 + mf * 16 + (lane >> 2);
            #pragma unroll
            for (int nf = 0; nf < 8; nf++) {
                float* d = acc[mf][nf];
                int c = colG + nf * 8;
                if (r0 < NN)
                    *reinterpret_cast<__half2*>(g_xw + (size_t)r0 * NTOTR + c) = __floats2half2_rn(d[0], d[1]);
                if (r0 + 8 < NN)
                    *reinterpret_cast<__half2*>(g_xw + (size_t)(r0 + 8) * NTOTR + c) = __floats2half2_rn(d[2], d[3]);
            }
        }
    } else if (wn == 0) {
        const int scol = (lane & 3) * 2;
        #pragma unroll
        for (int mf = 0; mf < 2; mf++) {
            int r0 = rowBase + wm * 32 + mf * 16 + (lane >> 2);
            #pragma unroll
            for (int nf = 0; nf < 8; nf++) {
                float* d = acc[mf][nf];
                int c = scol + nf * 8;
                if (r0 < NN)
                    *reinterpret_cast<float2*>(g_sd + (size_t)r0 * 64 + c) = make_float2(d[0], d[1]);
                if (r0 + 8 < NN)
                    *reinterpret_cast<float2*>(g_sd + (size_t)(r0 + 8) * 64 + c) = make_float2(d[2], d[3]);
            }
        }
    }
}

// ---------------- CSR build (once per launch) ----------------
__global__ void zero_deg_kernel() {
    int i = blockIdx.x * blockDim.x + threadIdx.x;
    if (i < NN) g_deg[i] = 0;
}
__global__ void hist_kernel(const int* __restrict__ ei) {
    int e = blockIdx.x * blockDim.x + threadIdx.x;
    if (e < NE) atomicAdd(&g_deg[ei[NE + e]], 1);
}
__device__ __forceinline__ int blk_excl_scan(int v, int tid, int* wsum) {
    int lane = tid & 31, w = tid >> 5;
    int x = v;
    #pragma unroll
    for (int o = 1; o < 32; o <<= 1) { int t = __shfl_up_sync(~0u, x, o); if (lane >= o) x += t; }
    if (lane == 31) wsum[w] = x;
    __syncthreads();
    if (w == 0) {
        int s = (lane < 8) ? wsum[lane] : 0;
        #pragma unroll
        for (int o = 1; o < 8; o <<= 1) { int t = __shfl_up_sync(~0u, s, o); if (lane >= o) s += t; }
        if (lane < 8) wsum[lane] = s;
    }
    __syncthreads();
    int incl = x + (w > 0 ? wsum[w - 1] : 0);
    return incl - v;
}
__global__ void scan1_kernel() {
    __shared__ int wsum[8];
    int i = blockIdx.x * 256 + threadIdx.x;
    int v = (i < NN) ? g_deg[i] : 0;
    int excl = blk_excl_scan(v, threadIdx.x, wsum);
    if (i < NN) g_off[i] = excl;
    if (threadIdx.x == 255) g_bsum[blockIdx.x] = excl + v;
}
__global__ void scan2_kernel(int nb) {
    __shared__ int wsum[8];
    int t = threadIdx.x;
    int v = (t < nb) ? g_bsum[t] : 0;
    int excl = blk_excl_scan(v, t, wsum);
    if (t < nb) g_bsum[t] = excl;
}
__global__ void scan3_kernel() {
    int i = blockIdx.x * 256 + threadIdx.x;
    if (i < NN) {
        int f = g_off[i] + g_bsum[blockIdx.x];
        g_off[i] = f;
        g_pos[i] = f;
    }
    if (i == 0) g_off[NN] = NE;
}
__global__ void scatter_kernel(const int* __restrict__ ei, const int* __restrict__ et) {
    int e = blockIdx.x * blockDim.x + threadIdx.x;
    if (e >= NE) return;
    int dst = ei[NE + e];
    int p = atomicAdd(&g_pos[dst], 1);
    g_esr[p] = (ei[e] << 3) | et[e];
}

// ---------------- fused softmax+aggregation+bias+LN+ELU+bf16 export (warp per dst; H=4, M=256) ----------------
__global__ void agg_ln_csr(const float* __restrict__ arel, const float* __restrict__ bias,
                           const float* __restrict__ gam, const float* __restrict__ bet) {
    int n = (blockIdx.x * blockDim.x + threadIdx.x) >> 5;
    int lane = threadIdx.x & 31;
    if (n >= NN) return;
    int start = g_off[n], end = g_off[n + 1];
    int c0 = lane * 4, c1 = 128 + lane * 4;
    float4 a0 = make_float4(0.f, 0.f, 0.f, 0.f);
    float4 a1 = make_float4(0.f, 0.f, 0.f, 0.f);
    float4 den = make_float4(0.f, 0.f, 0.f, 0.f);
    for (int base = start; base < end; base += 32) {
        int p = base + lane;
        float4 ex = make_float4(0.f, 0.f, 0.f, 0.f);
        int sr = 0;
        if (p < end) {
            sr = g_esr[p];
            int src = sr >> 3, r = sr & 7;
            float4 s = ld4(g_sd + src * 64 + r * 4);
            float4 d = ld4(g_sd + n * 64 + 32 + r * 4);
            float4 a = ld4(arel + r * 4);
            float4 v;
            v.x = s.x + d.x + a.x; v.y = s.y + d.y + a.y;
            v.z = s.z + d.z + a.z; v.w = s.w + d.w + a.w;
            v.x = v.x > 0.f ? v.x : 0.2f * v.x;
            v.y = v.y > 0.f ? v.y : 0.2f * v.y;
            v.z = v.z > 0.f ? v.z : 0.2f * v.z;
            v.w = v.w > 0.f ? v.w : 0.2f * v.w;
            ex = make_float4(expf(v.x), expf(v.y), expf(v.z), expf(v.w));
        }
        den.x += ex.x; den.y += ex.y; den.z += ex.z; den.w += ex.w;
        int cnt = min(32, end - base);
        for (int j = 0; j < cnt; j++) {
            int srj = __shfl_sync(~0u, sr, j);
            float e0 = __shfl_sync(~0u, ex.x, j);
            float e1 = __shfl_sync(~0u, ex.y, j);
            float e2 = __shfl_sync(~0u, ex.z, j);
            float e3 = __shfl_sync(~0u, ex.w, j);
            float sA = (lane < 16) ? e0 : e1;
            float sB = (lane < 16) ? e2 : e3;
            const __half* xp = g_xw + (size_t)(srj >> 3) * 2048 + (srj & 7) * 256;
            float4 v0 = ldh4(xp + c0), v1 = ldh4(xp + c1);
            a0.x += v0.x * sA; a0.y += v0.y * sA; a0.z += v0.z * sA; a0.w += v0.w * sA;
            a1.x += v1.x * sB; a1.y += v1.y * sB; a1.z += v1.z * sB; a1.w += v1.w * sB;
        }
    }
    #pragma unroll
    for (int o = 16; o; o >>= 1) {
        den.x += __shfl_xor_sync(~0u, den.x, o);
        den.y += __shfl_xor_sync(~0u, den.y, o);
        den.z += __shfl_xor_sync(~0u, den.z, o);
        den.w += __shfl_xor_sync(~0u, den.w, o);
    }
    float dA = (lane < 16) ? den.x : den.y;
    float dB = (lane < 16) ? den.z : den.w;
    float iA = dA > 0.f ? 1.f / dA : 0.f;
    float iB = dB > 0.f ? 1.f / dB : 0.f;
    a0.x *= iA; a0.y *= iA; a0.z *= iA; a0.w *= iA;
    a1.x *= iB; a1.y *= iB; a1.z *= iB; a1.w *= iB;
    float4 b0 = ld4(bias + c0), b1 = ld4(bias + c1);
    a0.x += b0.x; a0.y += b0.y; a0.z += b0.z; a0.w += b0.w;
    a1.x += b1.x; a1.y += b1.y; a1.z += b1.z; a1.w += b1.w;
    float sum = a0.x + a0.y + a0.z + a0.w + a1.x + a1.y + a1.z + a1.w;
    float sq = a0.x * a0.x + a0.y * a0.y + a0.z * a0.z + a0.w * a0.w
             + a1.x * a1.x + a1.y * a1.y + a1.z * a1.z + a1.w * a1.w;
    #pragma unroll
    for (int o = 16; o; o >>= 1) {
        sum += __shfl_xor_sync(0xffffffffu, sum, o);
        sq  += __shfl_xor_sync(0xffffffffu, sq, o);
    }
    float mean = sum * (1.f / 256.f);
    float var = sq * (1.f / 256.f) - mean * mean;
    float rstd = rsqrtf(var + 1e-5f);
    float4 g0 = ld4(gam + c0), g1 = ld4(gam + c1);
    float4 e0v = ld4(bet + c0), e1v = ld4(bet + c1);
    float4 y0, y1;
    y0.x = (a0.x - mean) * rstd * g0.x + e0v.x;
    y0.y = (a0.y - mean) * rstd * g0.y + e0v.y;
    y0.z = (a0.z - mean) * rstd * g0.z + e0v.z;
    y0.w = (a0.w - mean) * rstd * g0.w + e0v.w;
    y1.x = (a1.x - mean) * rstd * g1.x + e1v.x;
    y1.y = (a1.y - mean) * rstd * g1.y + e1v.y;
    y1.z = (a1.z - mean) * rstd * g1.z + e1v.z;
    y1.w = (a1.w - mean) * rstd * g1.w + e1v.w;
    y0.x = y0.x > 0.f ? y0.x : expm1f(y0.x);
    y0.y = y0.y > 0.f ? y0.y : expm1f(y0.y);
    y0.z = y0.z > 0.f ? y0.z : expm1f(y0.z);
    y0.w = y0.w > 0.f ? y0.w : expm1f(y0.w);
    y1.x = y1.x > 0.f ? y1.x : expm1f(y1.x);
    y1.y = y1.y > 0.f ? y1.y : expm1f(y1.y);
    y1.z = y1.z > 0.f ? y1.z : expm1f(y1.z);
    y1.w = y1.w > 0.f ? y1.w : expm1f(y1.w);
    float* hp = g_h + (size_t)n * 256;
    st4(hp + c0, y0);
    st4(hp + c1, y1);
    unsigned h0, l0, h1, l1;
    split2(y0.x, y0.y, h0, l0);
    split2(y0.z, y0.w, h1, l1);
    *reinterpret_cast<uint2*>(g_xh + (size_t)n * 256 + c0) = make_uint2(h0, h1);
    *reinterpret_cast<uint2*>(g_xl + (size_t)n * 256 + c0) = make_uint2(l0, l1);
    split2(y1.x, y1.y, h0, l0);
    split2(y1.z, y1.w, h1, l1);
    *reinterpret_cast<uint2*>(g_xh + (size_t)n * 256 + c1) = make_uint2(h0, h1);
    *reinterpret_cast<uint2*>(g_xl + (size_t)n * 256 + c1) = make_uint2(l0, l1);
}

// ---------------- fused softmax+aggregation layer 2 (warp per dst; H=1, M=64) + bias -> out ----------------
__global__ void agg_out_csr(const float* __restrict__ arel, const float* __restrict__ bi,
                            float* __restrict__ out) {
    int n = (blockIdx.x * blockDim.x + threadIdx.x) >> 5;
    int lane = threadIdx.x & 31;
    if (n >= NN) return;
    int start = g_off[n], end = g_off[n + 1];
    int half = lane >> 4;
    int c = (lane & 15) * 4;
    float4 acc = make_float4(0.f, 0.f, 0.f, 0.f);
    float den = 0.f;
    for (int base = start; base < end; base += 32) {
        int p = base + lane;
        float ex = 0.f;
        int sr = 0;
        if (p < end) {
            sr = g_esr[p];
            int src = sr >> 3, r = sr & 7;
            float v = g_sd[src * 64 + r] + g_sd[n * 64 + 8 + r] + arel[r];
            v = v > 0.f ? v : 0.2f * v;
            ex = expf(v);
        }
        den += ex;
        int cnt = min(32, end - base);
        for (int j = 0; j < cnt; j++) {
            int srj = __shfl_sync(~0u, sr, j);
            float exj = __shfl_sync(~0u, ex, j);
            if ((j & 1) == half) {
                const __half* xp = g_xw + (size_t)(srj >> 3) * 512 + (srj & 7) * 64;
                float4 v = ldh4(xp + c);
                acc.x += v.x * exj; acc.y += v.y * exj; acc.z += v.z * exj; acc.w += v.w * exj;
            }
        }
    }
    #pragma unroll
    for (int o = 16; o; o >>= 1) den += __shfl_xor_sync(~0u, den, o);
    acc.x += __shfl_xor_sync(~0u, acc.x, 16);
    acc.y += __shfl_xor_sync(~0u, acc.y, 16);
    acc.z += __shfl_xor_sync(~0u, acc.z, 16);
    acc.w += __shfl_xor_sync(~0u, acc.w, 16);
    if (half == 0) {
        float inv = den > 0.f ? 1.f / den : 0.f;
        float4 b = ld4(bi + c);
        acc.x = acc.x * inv + b.x;
        acc.y = acc.y * inv + b.y;
        acc.z = acc.z * inv + b.z;
        acc.w = acc.w * inv + b.w;
        st4(out + (size_t)n * 64 + c, acc);
    }
}

// ---------------- orchestration ----------------
extern "C" void kernel_launch(void* const* d_in, const int* in_sizes, int n_in,
                              void* d_out, int out_size) {
    (void)in_sizes; (void)n_in; (void)out_size;
    const float* x  = (const float*)d_in[0];
    const int* ei   = (const int*)d_in[1];
    const int* et   = (const int*)d_in[2];
    const float* W0 = (const float*)d_in[3];
    const float* as0 = (const float*)d_in[4];
    const float* ad0 = (const float*)d_in[5];
    const float* ar0 = (const float*)d_in[6];
    const float* bi0 = (const float*)d_in[7];
    const float* W1 = (const float*)d_in[8];
    const float* as1 = (const float*)d_in[9];
    const float* ad1 = (const float*)d_in[10];
    const float* ar1 = (const float*)d_in[11];
    const float* bi1 = (const float*)d_in[12];
    const float* W2 = (const float*)d_in[13];
    const float* as2 = (const float*)d_in[14];
    const float* ad2 = (const float*)d_in[15];
    const float* ar2 = (const float*)d_in[16];
    const float* bi2 = (const float*)d_in[17];
    const float* g0 = (const float*)d_in[18];
    const float* be0 = (const float*)d_in[19];
    const float* g1 = (const float*)d_in[20];
    const float* be1 = (const float*)d_in[21];
    float* out = (float*)d_out;

    const int TB = 256;
    const int NT = (NN + 127) / 128;
    const int NB = (NN + 255) / 256;
    dim3 gTC01(NT, 17, 1);     // NTOTP=2176 (2048 real + dots tile)
    dim3 gTC2(NT, 5, 1);       // NTOTP=640  (512 real + dots tile)
    int ge = (NE + TB - 1) / TB;
    int gwn = (NN * 32 + TB - 1) / TB;

    // dynamic smem: 2 stages x (A hi/lo 128x40 + B hi/lo 32x136) bf16
    const int SMSZ = 2 * (2 * 128 * 40 + 2 * 32 * 136) * 2;    // 75776 B
    cudaFuncSetAttribute((const void*)mma_gemm<2048, 2176, 128>, cudaFuncAttributeMaxDynamicSharedMemorySize, SMSZ);
    cudaFuncSetAttribute((const void*)mma_gemm<2048, 2176, 256>, cudaFuncAttributeMaxDynamicSharedMemorySize, SMSZ);
    cudaFuncSetAttribute((const void*)mma_gemm<512, 640, 256>,  cudaFuncAttributeMaxDynamicSharedMemorySize, SMSZ);

    // ======== layer 0: in=128 -> [8 rel] x 256, H=4 ========
    conv_w_t<128, 256, 2176><<<(128 * 512 + TB - 1) / TB, TB>>>(W0);
    conv_x_kernel<<<(NN * 128 / 4 + TB - 1) / TB, TB>>>(x, NN * 128 / 4);
    prep_ws2<4, 64, 2176, 2048><<<(128 * 32 + TB - 1) / TB, TB>>>(W0, as0, ad0, 128);
    mma_gemm<2048, 2176, 128><<<gTC01, TB, SMSZ>>>();   // 4th launch -> gets profiled
    // ---- build dst-CSR (needed before first aggregation) ----
    zero_deg_kernel<<<NB, TB>>>();
    hist_kernel<<<ge, TB>>>(ei);
    scan1_kernel<<<NB, TB>>>();
    scan2_kernel<<<1, TB>>>(NB);
    scan3_kernel<<<NB, TB>>>();
    scatter_kernel<<<ge, TB>>>(ei, et);
    agg_ln_csr<<<gwn, TB>>>(ar0, bi0, g0, be0);

    // ======== layer 1: in=256 -> [8 rel] x 256, H=4 ========
    conv_w_t<256, 256, 2176><<<(256 * 512 + TB - 1) / TB, TB>>>(W1);
    prep_ws2<4, 64, 2176, 2048><<<(256 * 32 + TB - 1) / TB, TB>>>(W1, as1, ad1, 256);
    mma_gemm<2048, 2176, 256><<<gTC01, TB, SMSZ>>>();
    agg_ln_csr<<<gwn, TB>>>(ar1, bi1, g1, be1);

    // ======== layer 2: in=256 -> [8 rel] x 64, H=1, no concat ========
    conv_w_t<256, 64, 640><<<(256 * 128 + TB - 1) / TB, TB>>>(W2);
    prep_ws2<1, 64, 640, 512><<<(256 * 32 + TB - 1) / TB, TB>>>(W2, as2, ad2, 256);
    mma_gemm<512, 640, 256><<<gTC2, TB, SMSZ>>>();
    agg_out_csr<<<gwn, TB>>>(ar2, bi2, out);
}